// round 1
// baseline (speedup 1.0000x reference)
#include <cuda_runtime.h>
#include <cstddef>

#define D       128
#define H       8
#define HD      16
#define NMAX    50000
#define LAYERS  3

// ---------------------------------------------------------------------------
// Scratch: one big __device__ global (no allocations allowed).
// Layout (floats):
//   x    : NMAX*D
//   q    : NMAX*D      (also reused as y2 buffer)
//   k    : NMAX*D
//   v    : NMAX*D
//   wV   : NMAX*D      (attn numerator; normalized in place -> attn)
//   y    : NMAX*D      (attention output)
//   mid  : NMAX*2*D    (FFN hidden)
//   Z    : NMAX*H
//   acc  : D
// ---------------------------------------------------------------------------
#define OFF_X    ((size_t)0)
#define OFF_Q    (OFF_X  + (size_t)NMAX * D)
#define OFF_K    (OFF_Q  + (size_t)NMAX * D)
#define OFF_V    (OFF_K  + (size_t)NMAX * D)
#define OFF_WV   (OFF_V  + (size_t)NMAX * D)
#define OFF_Y    (OFF_WV + (size_t)NMAX * D)
#define OFF_MID  (OFF_Y  + (size_t)NMAX * D)
#define OFF_Z    (OFF_MID + (size_t)NMAX * 2 * D)
#define OFF_ACC  (OFF_Z  + (size_t)NMAX * H)
#define SCRATCH_FLOATS (OFF_ACC + D)

__device__ float g_scratch[SCRATCH_FLOATS];

// ---------------------------------------------------------------------------
// Zero-fill
// ---------------------------------------------------------------------------
__global__ void zero_kernel(float* __restrict__ p, int n) {
    int i = blockIdx.x * blockDim.x + threadIdx.x;
    int stride = gridDim.x * blockDim.x;
    for (; i < n; i += stride) p[i] = 0.0f;
}

// ---------------------------------------------------------------------------
// Embedding gather: x[n, :] = emb[idx[n], :]
// ---------------------------------------------------------------------------
__global__ void emb_gather(const int* __restrict__ idx, const float* __restrict__ emb,
                           float* __restrict__ x, int N) {
    int i = blockIdx.x * blockDim.x + threadIdx.x;
    if (i >= N * D) return;
    int n = i >> 7;          // / 128
    int d = i & 127;
    x[i] = emb[(size_t)idx[n] * D + d];
}

// ---------------------------------------------------------------------------
// Tiled fp32 GEMM: C[N, M] = A[N, K] @ W[K, M] + bias, optional relu.
// Block tile 64 x 128, K consumed in chunks of 128. 256 threads,
// per-thread 4x8 register micro-tile. 96KB dynamic smem.
// ---------------------------------------------------------------------------
__global__ void gemm_tiled(const float* __restrict__ A, const float* __restrict__ W,
                           const float* __restrict__ bias, float* __restrict__ C,
                           int N, int K, int M, int relu) {
    extern __shared__ float sm[];
    float* As = sm;                 // [64][128]
    float* Ws = sm + 64 * 128;      // [128][128]

    const int tid = threadIdx.x;
    const int tx = tid & 15;        // 0..15  -> cols
    const int ty = tid >> 4;        // 0..15  -> rows
    const int bm = blockIdx.x * 64;
    const int bn = blockIdx.y * 128;
    const int r0 = ty * 4;
    const int c0 = tx * 8;

    float acc[4][8];
#pragma unroll
    for (int i = 0; i < 4; i++)
#pragma unroll
        for (int j = 0; j < 8; j++) acc[i][j] = 0.0f;

    for (int kc = 0; kc < K; kc += 128) {
        // Load A tile (64 x 128) as float4
#pragma unroll
        for (int it = 0; it < 8; it++) {
            int idx = tid + it * 256;          // 0..2047
            int r = idx >> 5;                  // row in tile
            int c4 = idx & 31;                 // float4 col
            int row = bm + r;
            float4 val = make_float4(0.f, 0.f, 0.f, 0.f);
            if (row < N)
                val = *(const float4*)(A + (size_t)row * K + kc + c4 * 4);
            ((float4*)As)[r * 32 + c4] = val;
        }
        // Load W tile (128 x 128) as float4
#pragma unroll
        for (int it = 0; it < 16; it++) {
            int idx = tid + it * 256;          // 0..4095
            int r = idx >> 5;
            int c4 = idx & 31;
            ((float4*)Ws)[r * 32 + c4] =
                *(const float4*)(W + (size_t)(kc + r) * M + bn + c4 * 4);
        }
        __syncthreads();

#pragma unroll 8
        for (int kk = 0; kk < 128; kk++) {
            float a0 = As[(r0 + 0) * 128 + kk];
            float a1 = As[(r0 + 1) * 128 + kk];
            float a2 = As[(r0 + 2) * 128 + kk];
            float a3 = As[(r0 + 3) * 128 + kk];
            float4 b0 = ((float4*)Ws)[kk * 32 + tx * 2 + 0];
            float4 b1 = ((float4*)Ws)[kk * 32 + tx * 2 + 1];
            float bv[8] = {b0.x, b0.y, b0.z, b0.w, b1.x, b1.y, b1.z, b1.w};
            float av[4] = {a0, a1, a2, a3};
#pragma unroll
            for (int i = 0; i < 4; i++)
#pragma unroll
                for (int j = 0; j < 8; j++)
                    acc[i][j] = fmaf(av[i], bv[j], acc[i][j]);
        }
        __syncthreads();
    }

    // Epilogue: bias (+relu), float4 stores
    float bsv[8];
#pragma unroll
    for (int j = 0; j < 8; j++) bsv[j] = bias[bn + c0 + j];

#pragma unroll
    for (int i = 0; i < 4; i++) {
        int row = bm + r0 + i;
        if (row >= N) continue;
        float o[8];
#pragma unroll
        for (int j = 0; j < 8; j++) {
            float t = acc[i][j] + bsv[j];
            o[j] = relu ? fmaxf(t, 0.0f) : t;
        }
        float* cp = C + (size_t)row * M + bn + c0;
        *(float4*)(cp + 0) = make_float4(o[0], o[1], o[2], o[3]);
        *(float4*)(cp + 4) = make_float4(o[4], o[5], o[6], o[7]);
    }
}

// ---------------------------------------------------------------------------
// Edge attention: warp per edge. 8 heads x 4 lanes; lane handles 4 of HD=16.
// score = exp(clip(dot(k[e0],q[e1])/4, -5, 5)); atomic scatter of v*score, score.
// ---------------------------------------------------------------------------
__global__ void edge_attn(const int* __restrict__ ei, int E,
                          const float* __restrict__ q, const float* __restrict__ k,
                          const float* __restrict__ v,
                          float* __restrict__ wV, float* __restrict__ Z) {
    int warp = blockIdx.x * (blockDim.x >> 5) + (threadIdx.x >> 5);
    if (warp >= E) return;
    int lane = threadIdx.x & 31;
    int e0 = ei[warp];
    int e1 = ei[E + warp];
    int head = lane >> 2;
    int sub = lane & 3;
    int off = head * HD + sub * 4;

    float4 kk = *(const float4*)(k + (size_t)e0 * D + off);
    float4 qq = *(const float4*)(q + (size_t)e1 * D + off);
    float s = kk.x * qq.x + kk.y * qq.y + kk.z * qq.z + kk.w * qq.w;
    s += __shfl_xor_sync(0xffffffffu, s, 1);
    s += __shfl_xor_sync(0xffffffffu, s, 2);
    s = expf(fminf(fmaxf(s * 0.25f, -5.0f), 5.0f));   // /sqrt(HD)=*0.25

    float4 vv = *(const float4*)(v + (size_t)e0 * D + off);
    float* wp = wV + (size_t)e1 * D + off;
    atomicAdd(wp + 0, vv.x * s);
    atomicAdd(wp + 1, vv.y * s);
    atomicAdd(wp + 2, vv.z * s);
    atomicAdd(wp + 3, vv.w * s);
    if (sub == 0) atomicAdd(Z + (size_t)e1 * H + head, s);
}

// ---------------------------------------------------------------------------
// attn = wV / (Z + 1e-6), in place on wV
// ---------------------------------------------------------------------------
__global__ void norm_attn(float* __restrict__ wV, const float* __restrict__ Z, int N) {
    int i = blockIdx.x * blockDim.x + threadIdx.x;
    if (i >= N * D) return;
    int n = i >> 7;
    int d = i & 127;
    wV[i] = wV[i] / (Z[n * H + (d >> 4)] + 1e-6f);
}

// ---------------------------------------------------------------------------
// out = LN(res + y) * g + b ; block per row, 128 threads. May alias res==out.
// ---------------------------------------------------------------------------
__global__ void add_ln(const float* __restrict__ res, const float* __restrict__ y,
                       float* __restrict__ out, const float* __restrict__ g,
                       const float* __restrict__ b) {
    int row = blockIdx.x;
    int tid = threadIdx.x;
    float val = res[(size_t)row * D + tid] + y[(size_t)row * D + tid];

    __shared__ float red[4];
    float s = val;
#pragma unroll
    for (int o = 16; o > 0; o >>= 1) s += __shfl_xor_sync(0xffffffffu, s, o);
    if ((tid & 31) == 0) red[tid >> 5] = s;
    __syncthreads();
    float mean = (red[0] + red[1] + red[2] + red[3]) * (1.0f / 128.0f);

    float dlt = val - mean;
    float vs = dlt * dlt;
#pragma unroll
    for (int o = 16; o > 0; o >>= 1) vs += __shfl_xor_sync(0xffffffffu, vs, o);
    __syncthreads();
    if ((tid & 31) == 0) red[tid >> 5] = vs;
    __syncthreads();
    float var = (red[0] + red[1] + red[2] + red[3]) * (1.0f / 128.0f);

    out[(size_t)row * D + tid] = dlt * rsqrtf(var + 1e-5f) * g[tid] + b[tid];
}

// ---------------------------------------------------------------------------
// Column-sum over rows (for mean pooling). grid=256 blocks x 128 threads.
// ---------------------------------------------------------------------------
__global__ void colsum(const float* __restrict__ x, float* __restrict__ acc, int N) {
    int d = threadIdx.x;
    float s = 0.0f;
    for (int r = blockIdx.x; r < N; r += gridDim.x)
        s += x[(size_t)r * D + d];
    atomicAdd(&acc[d], s);
}

// ---------------------------------------------------------------------------
// Readout MLP: mean -> 64 -> 32 -> 10. Single block, 128 threads.
// ---------------------------------------------------------------------------
__global__ void readout(const float* __restrict__ acc,
                        const float* __restrict__ mW0, const float* __restrict__ mb0,
                        const float* __restrict__ mW1, const float* __restrict__ mb1,
                        const float* __restrict__ mW2, const float* __restrict__ mb2,
                        float* __restrict__ out, int N) {
    __shared__ float m[D];
    __shared__ float h0[64];
    __shared__ float h1[32];
    int tid = threadIdx.x;
    m[tid] = acc[tid] * (1.0f / (float)N);
    __syncthreads();
    if (tid < 64) {
        float s = mb0[tid];
        for (int kk = 0; kk < D; kk++) s = fmaf(m[kk], mW0[kk * 64 + tid], s);
        h0[tid] = fmaxf(s, 0.0f);
    }
    __syncthreads();
    if (tid < 32) {
        float s = mb1[tid];
        for (int kk = 0; kk < 64; kk++) s = fmaf(h0[kk], mW1[kk * 32 + tid], s);
        h1[tid] = fmaxf(s, 0.0f);
    }
    __syncthreads();
    if (tid < 10) {
        float s = mb2[tid];
        for (int kk = 0; kk < 32; kk++) s = fmaf(h1[kk], mW2[kk * 10 + tid], s);
        out[tid] = s;
    }
}

// ---------------------------------------------------------------------------
// Launch
// ---------------------------------------------------------------------------
extern "C" void kernel_launch(void* const* d_in, const int* in_sizes, int n_in,
                              void* d_out, int out_size) {
    const int*   x_idx = (const int*)d_in[0];
    const int*   ei    = (const int*)d_in[1];
    const float* emb   = (const float*)d_in[2];
    const float* Wq  = (const float*)d_in[3];
    const float* bq  = (const float*)d_in[4];
    const float* Wk  = (const float*)d_in[5];
    const float* bk  = (const float*)d_in[6];
    const float* Wv  = (const float*)d_in[7];
    const float* bv  = (const float*)d_in[8];
    const float* Wo  = (const float*)d_in[9];
    const float* bo  = (const float*)d_in[10];
    const float* g1  = (const float*)d_in[11];
    const float* be1 = (const float*)d_in[12];
    const float* Wf1 = (const float*)d_in[13];
    const float* bf1 = (const float*)d_in[14];
    const float* Wf2 = (const float*)d_in[15];
    const float* bf2 = (const float*)d_in[16];
    const float* g2  = (const float*)d_in[17];
    const float* be2 = (const float*)d_in[18];
    const float* mW0 = (const float*)d_in[19];
    const float* mb0 = (const float*)d_in[20];
    const float* mW1 = (const float*)d_in[21];
    const float* mb1 = (const float*)d_in[22];
    const float* mW2 = (const float*)d_in[23];
    const float* mb2 = (const float*)d_in[24];
    float* out = (float*)d_out;

    const int N = in_sizes[0];       // B*N*1 = 50000
    const int E = in_sizes[1] / 2;   // 800000

    float* base;
    cudaGetSymbolAddress((void**)&base, g_scratch);
    float* x   = base + OFF_X;
    float* q   = base + OFF_Q;
    float* k   = base + OFF_K;
    float* v   = base + OFF_V;
    float* wV  = base + OFF_WV;
    float* y   = base + OFF_Y;
    float* mid = base + OFF_MID;
    float* Z   = base + OFF_Z;
    float* acc = base + OFF_ACC;

    const int SMEM = (64 * 128 + 128 * 128) * 4;   // 96 KB
    cudaFuncSetAttribute(gemm_tiled, cudaFuncAttributeMaxDynamicSharedMemorySize, SMEM);

    const int nb64 = (N + 63) / 64;
    dim3 g1d(nb64, 1), g2d(nb64, 2);

    emb_gather<<<(N * D + 255) / 256, 256>>>(x_idx, emb, x, N);

    for (int l = 0; l < LAYERS; l++) {
        const float* Wql = Wq + (size_t)l * D * D;
        const float* Wkl = Wk + (size_t)l * D * D;
        const float* Wvl = Wv + (size_t)l * D * D;
        const float* Wol = Wo + (size_t)l * D * D;
        const float* Wf1l = Wf1 + (size_t)l * D * 2 * D;
        const float* Wf2l = Wf2 + (size_t)l * 2 * D * D;

        gemm_tiled<<<g1d, 256, SMEM>>>(x, Wql, bq + l * D, q, N, D, D, 0);
        gemm_tiled<<<g1d, 256, SMEM>>>(x, Wkl, bk + l * D, k, N, D, D, 0);
        gemm_tiled<<<g1d, 256, SMEM>>>(x, Wvl, bv + l * D, v, N, D, D, 0);

        zero_kernel<<<1024, 256>>>(wV, N * D);
        zero_kernel<<<256, 256>>>(Z, N * H);
        edge_attn<<<(E + 7) / 8, 256>>>(ei, E, q, k, v, wV, Z);
        norm_attn<<<(N * D + 255) / 256, 256>>>(wV, Z, N);

        gemm_tiled<<<g1d, 256, SMEM>>>(wV, Wol, bo + l * D, y, N, D, D, 0);
        add_ln<<<N, 128>>>(x, y, x, g1 + l * D, be1 + l * D);

        gemm_tiled<<<g2d, 256, SMEM>>>(y, Wf1l, bf1 + l * 2 * D, mid, N, D, 2 * D, 1);
        gemm_tiled<<<g1d, 256, SMEM>>>(mid, Wf2l, bf2 + l * D, q, N, 2 * D, D, 0);
        add_ln<<<N, 128>>>(x, q, x, g2 + l * D, be2 + l * D);
    }

    zero_kernel<<<1, 128>>>(acc, D);
    colsum<<<256, 128>>>(x, acc, N);
    readout<<<1, 128>>>(acc, mW0, mb0, mW1, mb1, mW2, mb2, out, N);
}

// round 2
// speedup vs baseline: 1.4449x; 1.4449x over previous
#include <cuda_runtime.h>
#include <cstddef>

#define D       128
#define H       8
#define HD      16
#define NMAX    50000
#define LAYERS  3

// ---------------------------------------------------------------------------
// Scratch layout (floats)
// ---------------------------------------------------------------------------
#define OFF_X    ((size_t)0)
#define OFF_Q    (OFF_X  + (size_t)NMAX * D)
#define OFF_K    (OFF_Q  + (size_t)NMAX * D)
#define OFF_V    (OFF_K  + (size_t)NMAX * D)
#define OFF_WV   (OFF_V  + (size_t)NMAX * D)
#define OFF_Y    (OFF_WV + (size_t)NMAX * D)
#define OFF_MID  (OFF_Y  + (size_t)NMAX * D)
#define OFF_Z    (OFF_MID + (size_t)NMAX * 2 * D)
#define OFF_ACC  (OFF_Z  + (size_t)NMAX * H)
#define SCRATCH_FLOATS (OFF_ACC + D)

__device__ float g_scratch[SCRATCH_FLOATS];

// ---------------------------------------------------------------------------
__global__ void zero_kernel(float* __restrict__ p, int n) {
    int i = blockIdx.x * blockDim.x + threadIdx.x;
    int stride = gridDim.x * blockDim.x;
    for (; i < n; i += stride) p[i] = 0.0f;
}

__global__ void emb_gather(const int* __restrict__ idx, const float* __restrict__ emb,
                           float* __restrict__ x, int N) {
    int i = blockIdx.x * blockDim.x + threadIdx.x;
    if (i >= N * D) return;
    int n = i >> 7;
    int d = i & 127;
    x[i] = emb[(size_t)idx[n] * D + d];
}

// ---------------------------------------------------------------------------
// tf32x3 tensor-core GEMM: C[rows, Nout] = A[rows, K] @ W[K, Nout] + bias.
// Block tile 128x128, BLOCK_K=32, 256 threads (8 warps, 4x2 -> 32x64/warp).
// mma.sync.m16n8k8 tf32 with hi/lo split => ~fp32 accuracy.
// ---------------------------------------------------------------------------
__device__ __forceinline__ unsigned f2tf(float f) {
    unsigned r;
    asm("cvt.rna.tf32.f32 %0, %1;" : "=r"(r) : "f"(f));
    return r;
}

__device__ __forceinline__ void mma8(float c[4], const unsigned a[4], const unsigned b[2]) {
    asm volatile(
        "mma.sync.aligned.m16n8k8.row.col.f32.tf32.tf32.f32 "
        "{%0,%1,%2,%3}, {%4,%5,%6,%7}, {%8,%9}, {%0,%1,%2,%3};"
        : "+f"(c[0]), "+f"(c[1]), "+f"(c[2]), "+f"(c[3])
        : "r"(a[0]), "r"(a[1]), "r"(a[2]), "r"(a[3]), "r"(b[0]), "r"(b[1]));
}

__global__ void gemm_tc(const float* __restrict__ A, const float* __restrict__ W,
                        const float* __restrict__ bias, float* __restrict__ C,
                        int rows, int K, int Nout, int relu) {
    __shared__ float As[128][36];    // pad 4: conflict-free frag loads
    __shared__ float Bs[32][136];    // pad 8: conflict-free frag loads, 16B-aligned rows

    const int tid = threadIdx.x;
    const int lane = tid & 31;
    const int wid = tid >> 5;
    const int warp_m = wid & 3;      // 4 warps along M (32 rows each)
    const int warp_n = wid >> 2;     // 2 warps along N (64 cols each)
    const int bm = blockIdx.x * 128;
    const int bn = blockIdx.y * 128;

    const int lr = lane >> 2;        // 0..7
    const int lc = lane & 3;         // 0..3

    float acc[2][8][4];
#pragma unroll
    for (int mi = 0; mi < 2; mi++)
#pragma unroll
        for (int ni = 0; ni < 8; ni++)
#pragma unroll
            for (int t = 0; t < 4; t++) acc[mi][ni][t] = 0.0f;

    for (int kc = 0; kc < K; kc += 32) {
        // A tile: 128x32 = 1024 float4, 4 per thread
#pragma unroll
        for (int it = 0; it < 4; it++) {
            int idx = tid + it * 256;
            int r = idx >> 3;
            int c4 = idx & 7;
            int row = bm + r;
            float4 val = make_float4(0.f, 0.f, 0.f, 0.f);
            if (row < rows)
                val = *(const float4*)(A + (size_t)row * K + kc + c4 * 4);
            *(float4*)&As[r][c4 * 4] = val;
        }
        // B tile: 32x128 = 1024 float4, 4 per thread
#pragma unroll
        for (int it = 0; it < 4; it++) {
            int idx = tid + it * 256;
            int r = idx >> 5;
            int c4 = idx & 31;
            *(float4*)&Bs[r][c4 * 4] =
                *(const float4*)(W + (size_t)(kc + r) * Nout + bn + c4 * 4);
        }
        __syncthreads();

#pragma unroll
        for (int ks = 0; ks < 32; ks += 8) {
            // A fragments (hi/lo)
            unsigned ah[2][4], al[2][4];
#pragma unroll
            for (int mi = 0; mi < 2; mi++) {
                int rb = warp_m * 32 + mi * 16 + lr;
                float a0 = As[rb][ks + lc];
                float a1 = As[rb + 8][ks + lc];
                float a2 = As[rb][ks + lc + 4];
                float a3 = As[rb + 8][ks + lc + 4];
                ah[mi][0] = f2tf(a0); al[mi][0] = f2tf(a0 - __uint_as_float(ah[mi][0]));
                ah[mi][1] = f2tf(a1); al[mi][1] = f2tf(a1 - __uint_as_float(ah[mi][1]));
                ah[mi][2] = f2tf(a2); al[mi][2] = f2tf(a2 - __uint_as_float(ah[mi][2]));
                ah[mi][3] = f2tf(a3); al[mi][3] = f2tf(a3 - __uint_as_float(ah[mi][3]));
            }
            // B fragments (hi/lo)
            unsigned bh[8][2], bl[8][2];
#pragma unroll
            for (int ni = 0; ni < 8; ni++) {
                int cb = warp_n * 64 + ni * 8 + lr;
                float b0 = Bs[ks + lc][cb];
                float b1 = Bs[ks + lc + 4][cb];
                bh[ni][0] = f2tf(b0); bl[ni][0] = f2tf(b0 - __uint_as_float(bh[ni][0]));
                bh[ni][1] = f2tf(b1); bl[ni][1] = f2tf(b1 - __uint_as_float(bh[ni][1]));
            }
#pragma unroll
            for (int mi = 0; mi < 2; mi++)
#pragma unroll
                for (int ni = 0; ni < 8; ni++) {
                    mma8(acc[mi][ni], al[mi], bh[ni]);   // small terms first
                    mma8(acc[mi][ni], ah[mi], bl[ni]);
                    mma8(acc[mi][ni], ah[mi], bh[ni]);
                }
        }
        __syncthreads();
    }

    // Epilogue
#pragma unroll
    for (int mi = 0; mi < 2; mi++) {
        int row0 = bm + warp_m * 32 + mi * 16 + lr;
        int row1 = row0 + 8;
#pragma unroll
        for (int ni = 0; ni < 8; ni++) {
            int col = bn + warp_n * 64 + ni * 8 + 2 * lc;
            float bs0 = bias[col], bs1 = bias[col + 1];
            float o0 = acc[mi][ni][0] + bs0;
            float o1 = acc[mi][ni][1] + bs1;
            float o2 = acc[mi][ni][2] + bs0;
            float o3 = acc[mi][ni][3] + bs1;
            if (relu) {
                o0 = fmaxf(o0, 0.f); o1 = fmaxf(o1, 0.f);
                o2 = fmaxf(o2, 0.f); o3 = fmaxf(o3, 0.f);
            }
            if (row0 < rows)
                *(float2*)(C + (size_t)row0 * Nout + col) = make_float2(o0, o1);
            if (row1 < rows)
                *(float2*)(C + (size_t)row1 * Nout + col) = make_float2(o2, o3);
        }
    }
}

// ---------------------------------------------------------------------------
// Edge attention: warp per edge (8 heads x 4 lanes).
// ---------------------------------------------------------------------------
__global__ void edge_attn(const int* __restrict__ ei, int E,
                          const float* __restrict__ q, const float* __restrict__ k,
                          const float* __restrict__ v,
                          float* __restrict__ wV, float* __restrict__ Z) {
    int warp = blockIdx.x * (blockDim.x >> 5) + (threadIdx.x >> 5);
    if (warp >= E) return;
    int lane = threadIdx.x & 31;
    int e0 = ei[warp];
    int e1 = ei[E + warp];
    int head = lane >> 2;
    int sub = lane & 3;
    int off = head * HD + sub * 4;

    float4 kk = *(const float4*)(k + (size_t)e0 * D + off);
    float4 qq = *(const float4*)(q + (size_t)e1 * D + off);
    float s = kk.x * qq.x + kk.y * qq.y + kk.z * qq.z + kk.w * qq.w;
    s += __shfl_xor_sync(0xffffffffu, s, 1);
    s += __shfl_xor_sync(0xffffffffu, s, 2);
    s = expf(fminf(fmaxf(s * 0.25f, -5.0f), 5.0f));

    float4 vv = *(const float4*)(v + (size_t)e0 * D + off);
    float* wp = wV + (size_t)e1 * D + off;
    atomicAdd(wp + 0, vv.x * s);
    atomicAdd(wp + 1, vv.y * s);
    atomicAdd(wp + 2, vv.z * s);
    atomicAdd(wp + 3, vv.w * s);
    if (sub == 0) atomicAdd(Z + (size_t)e1 * H + head, s);
}

__global__ void norm_attn(float* __restrict__ wV, const float* __restrict__ Z, int N) {
    int i = blockIdx.x * blockDim.x + threadIdx.x;
    if (i >= N * D) return;
    int n = i >> 7;
    int d = i & 127;
    wV[i] = wV[i] / (Z[n * H + (d >> 4)] + 1e-6f);
}

// ---------------------------------------------------------------------------
__global__ void add_ln(const float* __restrict__ res, const float* __restrict__ y,
                       float* __restrict__ out, const float* __restrict__ g,
                       const float* __restrict__ b) {
    int row = blockIdx.x;
    int tid = threadIdx.x;
    float val = res[(size_t)row * D + tid] + y[(size_t)row * D + tid];

    __shared__ float red[4];
    float s = val;
#pragma unroll
    for (int o = 16; o > 0; o >>= 1) s += __shfl_xor_sync(0xffffffffu, s, o);
    if ((tid & 31) == 0) red[tid >> 5] = s;
    __syncthreads();
    float mean = (red[0] + red[1] + red[2] + red[3]) * (1.0f / 128.0f);

    float dlt = val - mean;
    float vs = dlt * dlt;
#pragma unroll
    for (int o = 16; o > 0; o >>= 1) vs += __shfl_xor_sync(0xffffffffu, vs, o);
    __syncthreads();
    if ((tid & 31) == 0) red[tid >> 5] = vs;
    __syncthreads();
    float var = (red[0] + red[1] + red[2] + red[3]) * (1.0f / 128.0f);

    out[(size_t)row * D + tid] = dlt * rsqrtf(var + 1e-5f) * g[tid] + b[tid];
}

__global__ void colsum(const float* __restrict__ x, float* __restrict__ acc, int N) {
    int d = threadIdx.x;
    float s = 0.0f;
    for (int r = blockIdx.x; r < N; r += gridDim.x)
        s += x[(size_t)r * D + d];
    atomicAdd(&acc[d], s);
}

__global__ void readout(const float* __restrict__ acc,
                        const float* __restrict__ mW0, const float* __restrict__ mb0,
                        const float* __restrict__ mW1, const float* __restrict__ mb1,
                        const float* __restrict__ mW2, const float* __restrict__ mb2,
                        float* __restrict__ out, int N) {
    __shared__ float m[D];
    __shared__ float h0[64];
    __shared__ float h1[32];
    int tid = threadIdx.x;
    m[tid] = acc[tid] * (1.0f / (float)N);
    __syncthreads();
    if (tid < 64) {
        float s = mb0[tid];
        for (int kk = 0; kk < D; kk++) s = fmaf(m[kk], mW0[kk * 64 + tid], s);
        h0[tid] = fmaxf(s, 0.0f);
    }
    __syncthreads();
    if (tid < 32) {
        float s = mb1[tid];
        for (int kk = 0; kk < 64; kk++) s = fmaf(h0[kk], mW1[kk * 32 + tid], s);
        h1[tid] = fmaxf(s, 0.0f);
    }
    __syncthreads();
    if (tid < 10) {
        float s = mb2[tid];
        for (int kk = 0; kk < 32; kk++) s = fmaf(h1[kk], mW2[kk * 10 + tid], s);
        out[tid] = s;
    }
}

// ---------------------------------------------------------------------------
extern "C" void kernel_launch(void* const* d_in, const int* in_sizes, int n_in,
                              void* d_out, int out_size) {
    const int*   x_idx = (const int*)d_in[0];
    const int*   ei    = (const int*)d_in[1];
    const float* emb   = (const float*)d_in[2];
    const float* Wq  = (const float*)d_in[3];
    const float* bq  = (const float*)d_in[4];
    const float* Wk  = (const float*)d_in[5];
    const float* bk  = (const float*)d_in[6];
    const float* Wv  = (const float*)d_in[7];
    const float* bv  = (const float*)d_in[8];
    const float* Wo  = (const float*)d_in[9];
    const float* bo  = (const float*)d_in[10];
    const float* g1  = (const float*)d_in[11];
    const float* be1 = (const float*)d_in[12];
    const float* Wf1 = (const float*)d_in[13];
    const float* bf1 = (const float*)d_in[14];
    const float* Wf2 = (const float*)d_in[15];
    const float* bf2 = (const float*)d_in[16];
    const float* g2  = (const float*)d_in[17];
    const float* be2 = (const float*)d_in[18];
    const float* mW0 = (const float*)d_in[19];
    const float* mb0 = (const float*)d_in[20];
    const float* mW1 = (const float*)d_in[21];
    const float* mb1 = (const float*)d_in[22];
    const float* mW2 = (const float*)d_in[23];
    const float* mb2 = (const float*)d_in[24];
    float* out = (float*)d_out;

    const int N = in_sizes[0];       // 50000
    const int E = in_sizes[1] / 2;   // 800000

    float* base;
    cudaGetSymbolAddress((void**)&base, g_scratch);
    float* x   = base + OFF_X;
    float* q   = base + OFF_Q;
    float* k   = base + OFF_K;
    float* v   = base + OFF_V;
    float* wV  = base + OFF_WV;
    float* y   = base + OFF_Y;
    float* mid = base + OFF_MID;
    float* Z   = base + OFF_Z;
    float* acc = base + OFF_ACC;

    const int nb128 = (N + 127) / 128;
    dim3 g1d(nb128, 1), g2d(nb128, 2);

    emb_gather<<<(N * D + 255) / 256, 256>>>(x_idx, emb, x, N);

    for (int l = 0; l < LAYERS; l++) {
        const float* Wql = Wq + (size_t)l * D * D;
        const float* Wkl = Wk + (size_t)l * D * D;
        const float* Wvl = Wv + (size_t)l * D * D;
        const float* Wol = Wo + (size_t)l * D * D;
        const float* Wf1l = Wf1 + (size_t)l * D * 2 * D;
        const float* Wf2l = Wf2 + (size_t)l * 2 * D * D;

        gemm_tc<<<g1d, 256>>>(x, Wql, bq + l * D, q, N, D, D, 0);
        gemm_tc<<<g1d, 256>>>(x, Wkl, bk + l * D, k, N, D, D, 0);
        gemm_tc<<<g1d, 256>>>(x, Wvl, bv + l * D, v, N, D, D, 0);

        zero_kernel<<<1024, 256>>>(wV, N * D);
        zero_kernel<<<256, 256>>>(Z, N * H);
        edge_attn<<<(E + 7) / 8, 256>>>(ei, E, q, k, v, wV, Z);
        norm_attn<<<(N * D + 255) / 256, 256>>>(wV, Z, N);

        gemm_tc<<<g1d, 256>>>(wV, Wol, bo + l * D, y, N, D, D, 0);
        add_ln<<<N, 128>>>(x, y, x, g1 + l * D, be1 + l * D);

        gemm_tc<<<g2d, 256>>>(y, Wf1l, bf1 + l * 2 * D, mid, N, D, 2 * D, 1);
        gemm_tc<<<g1d, 256>>>(mid, Wf2l, bf2 + l * D, q, N, 2 * D, D, 0);
        add_ln<<<N, 128>>>(x, q, x, g2 + l * D, be2 + l * D);
    }

    zero_kernel<<<1, 128>>>(acc, D);
    colsum<<<256, 128>>>(x, acc, N);
    readout<<<1, 128>>>(acc, mW0, mb0, mW1, mb1, mW2, mb2, out, N);
}

// round 3
// speedup vs baseline: 2.1375x; 1.4793x over previous
#include <cuda_runtime.h>
#include <cstddef>

#define D       128
#define H       8
#define HD      16
#define NMAX    50000
#define EMAX    800000
#define LAYERS  3

// ---------------------------------------------------------------------------
// Float scratch
// ---------------------------------------------------------------------------
#define OFF_X    ((size_t)0)
#define OFF_Q    (OFF_X  + (size_t)NMAX * D)
#define OFF_K    (OFF_Q  + (size_t)NMAX * D)
#define OFF_V    (OFF_K  + (size_t)NMAX * D)
#define OFF_WV   (OFF_V  + (size_t)NMAX * D)
#define OFF_Y    (OFF_WV + (size_t)NMAX * D)
#define OFF_MID  (OFF_Y  + (size_t)NMAX * D)
#define OFF_ACC  (OFF_MID + (size_t)NMAX * 2 * D)
#define SCRATCH_FLOATS (OFF_ACC + D)

__device__ float g_scratch[SCRATCH_FLOATS];

// Int scratch: cnt[N], rowptr[N+1], csr_src[E]
#define IOFF_CNT   0
#define IOFF_ROW   (IOFF_CNT + NMAX)
#define IOFF_SRC   (IOFF_ROW + NMAX + 1)
__device__ int g_iscratch[IOFF_SRC + EMAX];

// ---------------------------------------------------------------------------
__global__ void zero_int(int* __restrict__ p, int n) {
    int i = blockIdx.x * blockDim.x + threadIdx.x;
    int stride = gridDim.x * blockDim.x;
    for (; i < n; i += stride) p[i] = 0;
}

__global__ void zero_kernel(float* __restrict__ p, int n) {
    int i = blockIdx.x * blockDim.x + threadIdx.x;
    int stride = gridDim.x * blockDim.x;
    for (; i < n; i += stride) p[i] = 0.0f;
}

__global__ void emb_gather(const int* __restrict__ idx, const float* __restrict__ emb,
                           float* __restrict__ x, int N) {
    int i = blockIdx.x * blockDim.x + threadIdx.x;
    if (i >= N * D) return;
    int n = i >> 7;
    int d = i & 127;
    x[i] = emb[(size_t)idx[n] * D + d];
}

// ---------------------------------------------------------------------------
// CSR build: histogram of destinations, scan, scatter sources.
// ---------------------------------------------------------------------------
__global__ void hist_dst(const int* __restrict__ ei, int E, int* __restrict__ cnt) {
    int j = blockIdx.x * blockDim.x + threadIdx.x;
    if (j < E) atomicAdd(&cnt[ei[E + j]], 1);
}

// Single block, 1024 threads: exclusive scan of cnt[N] -> rowptr[N+1]
__global__ void scan_rowptr(const int* __restrict__ cnt, int* __restrict__ rowptr, int N) {
    __shared__ int ssum[1024];
    int tid = threadIdx.x;
    int chunk = (N + 1023) / 1024;
    int start = tid * chunk;
    int end = min(start + chunk, N);
    int s = 0;
    for (int i = start; i < end; i++) s += cnt[i];
    ssum[tid] = s;
    __syncthreads();
    int mysum = s;
    for (int o = 1; o < 1024; o <<= 1) {
        int t = (tid >= o) ? ssum[tid - o] : 0;
        __syncthreads();
        ssum[tid] += t;
        __syncthreads();
    }
    int off = ssum[tid] - mysum;   // exclusive prefix
    for (int i = start; i < end; i++) { rowptr[i] = off; off += cnt[i]; }
    if (end == N) rowptr[N] = off;
}

__global__ void csr_scatter(const int* __restrict__ ei, int E,
                            const int* __restrict__ rowptr, int* __restrict__ cur,
                            int* __restrict__ csr_src) {
    int j = blockIdx.x * blockDim.x + threadIdx.x;
    if (j >= E) return;
    int d = ei[E + j];
    int pos = atomicAdd(&cur[d], 1);
    csr_src[rowptr[d] + pos] = ei[j];
}

// ---------------------------------------------------------------------------
// tf32x3 tensor-core GEMM, hi/lo precomputed at tile load into smem.
// Block tile 128x128, BLOCK_K=32, 256 threads (8 warps, 4x2 -> 32x64/warp).
// ---------------------------------------------------------------------------
__device__ __forceinline__ unsigned f2tf(float f) {
    unsigned r;
    asm("cvt.rna.tf32.f32 %0, %1;" : "=r"(r) : "f"(f));
    return r;
}

__device__ __forceinline__ void mma8(float c[4], const unsigned a[4], const unsigned b[2]) {
    asm volatile(
        "mma.sync.aligned.m16n8k8.row.col.f32.tf32.tf32.f32 "
        "{%0,%1,%2,%3}, {%4,%5,%6,%7}, {%8,%9}, {%0,%1,%2,%3};"
        : "+f"(c[0]), "+f"(c[1]), "+f"(c[2]), "+f"(c[3])
        : "r"(a[0]), "r"(a[1]), "r"(a[2]), "r"(a[3]), "r"(b[0]), "r"(b[1]));
}

#define AS_STRIDE 36
#define BS_STRIDE 136
#define SM_AH 0
#define SM_AL (128 * AS_STRIDE)
#define SM_BH (2 * 128 * AS_STRIDE)
#define SM_BL (2 * 128 * AS_STRIDE + 32 * BS_STRIDE)
#define GEMM_SMEM ((2 * 128 * AS_STRIDE + 2 * 32 * BS_STRIDE) * 4)

__global__ void gemm_tc(const float* __restrict__ A, const float* __restrict__ W,
                        const float* __restrict__ bias, float* __restrict__ C,
                        int rows, int K, int Nout, int relu) {
    extern __shared__ unsigned sm[];
    unsigned* Ah = sm + SM_AH;
    unsigned* Al = sm + SM_AL;
    unsigned* Bh = sm + SM_BH;
    unsigned* Bl = sm + SM_BL;

    const int tid = threadIdx.x;
    const int lane = tid & 31;
    const int wid = tid >> 5;
    const int warp_m = wid & 3;
    const int warp_n = wid >> 2;
    const int bm = blockIdx.x * 128;
    const int bn = blockIdx.y * 128;
    const int lr = lane >> 2;   // 0..7
    const int lc = lane & 3;    // 0..3

    float acc[2][8][4];
#pragma unroll
    for (int mi = 0; mi < 2; mi++)
#pragma unroll
        for (int ni = 0; ni < 8; ni++)
#pragma unroll
            for (int t = 0; t < 4; t++) acc[mi][ni][t] = 0.0f;

    for (int kc = 0; kc < K; kc += 32) {
        // A tile 128x32: 4 float4 per thread, convert to hi/lo
#pragma unroll
        for (int it = 0; it < 4; it++) {
            int idx = tid + it * 256;
            int r = idx >> 3;
            int c4 = idx & 7;
            int row = bm + r;
            float4 val = make_float4(0.f, 0.f, 0.f, 0.f);
            if (row < rows)
                val = *(const float4*)(A + (size_t)row * K + kc + c4 * 4);
            unsigned* ph = Ah + r * AS_STRIDE + c4 * 4;
            unsigned* pl = Al + r * AS_STRIDE + c4 * 4;
            float fv[4] = {val.x, val.y, val.z, val.w};
#pragma unroll
            for (int t = 0; t < 4; t++) {
                unsigned h = f2tf(fv[t]);
                ph[t] = h;
                pl[t] = f2tf(fv[t] - __uint_as_float(h));
            }
        }
        // B tile 32x128
#pragma unroll
        for (int it = 0; it < 4; it++) {
            int idx = tid + it * 256;
            int r = idx >> 5;
            int c4 = idx & 31;
            float4 val = *(const float4*)(W + (size_t)(kc + r) * Nout + bn + c4 * 4);
            unsigned* ph = Bh + r * BS_STRIDE + c4 * 4;
            unsigned* pl = Bl + r * BS_STRIDE + c4 * 4;
            float fv[4] = {val.x, val.y, val.z, val.w};
#pragma unroll
            for (int t = 0; t < 4; t++) {
                unsigned h = f2tf(fv[t]);
                ph[t] = h;
                pl[t] = f2tf(fv[t] - __uint_as_float(h));
            }
        }
        __syncthreads();

#pragma unroll
        for (int ks = 0; ks < 32; ks += 8) {
            unsigned ah[2][4], al[2][4];
#pragma unroll
            for (int mi = 0; mi < 2; mi++) {
                int rb = warp_m * 32 + mi * 16 + lr;
                ah[mi][0] = Ah[rb * AS_STRIDE + ks + lc];
                ah[mi][1] = Ah[(rb + 8) * AS_STRIDE + ks + lc];
                ah[mi][2] = Ah[rb * AS_STRIDE + ks + lc + 4];
                ah[mi][3] = Ah[(rb + 8) * AS_STRIDE + ks + lc + 4];
                al[mi][0] = Al[rb * AS_STRIDE + ks + lc];
                al[mi][1] = Al[(rb + 8) * AS_STRIDE + ks + lc];
                al[mi][2] = Al[rb * AS_STRIDE + ks + lc + 4];
                al[mi][3] = Al[(rb + 8) * AS_STRIDE + ks + lc + 4];
            }
            unsigned bh[8][2], bl[8][2];
#pragma unroll
            for (int ni = 0; ni < 8; ni++) {
                int cb = warp_n * 64 + ni * 8 + lr;
                bh[ni][0] = Bh[(ks + lc) * BS_STRIDE + cb];
                bh[ni][1] = Bh[(ks + lc + 4) * BS_STRIDE + cb];
                bl[ni][0] = Bl[(ks + lc) * BS_STRIDE + cb];
                bl[ni][1] = Bl[(ks + lc + 4) * BS_STRIDE + cb];
            }
#pragma unroll
            for (int mi = 0; mi < 2; mi++)
#pragma unroll
                for (int ni = 0; ni < 8; ni++) {
                    mma8(acc[mi][ni], al[mi], bh[ni]);
                    mma8(acc[mi][ni], ah[mi], bl[ni]);
                    mma8(acc[mi][ni], ah[mi], bh[ni]);
                }
        }
        __syncthreads();
    }

#pragma unroll
    for (int mi = 0; mi < 2; mi++) {
        int row0 = bm + warp_m * 32 + mi * 16 + lr;
        int row1 = row0 + 8;
#pragma unroll
        for (int ni = 0; ni < 8; ni++) {
            int col = bn + warp_n * 64 + ni * 8 + 2 * lc;
            float bs0 = bias[col], bs1 = bias[col + 1];
            float o0 = acc[mi][ni][0] + bs0;
            float o1 = acc[mi][ni][1] + bs1;
            float o2 = acc[mi][ni][2] + bs0;
            float o3 = acc[mi][ni][3] + bs1;
            if (relu) {
                o0 = fmaxf(o0, 0.f); o1 = fmaxf(o1, 0.f);
                o2 = fmaxf(o2, 0.f); o3 = fmaxf(o3, 0.f);
            }
            if (row0 < rows)
                *(float2*)(C + (size_t)row0 * Nout + col) = make_float2(o0, o1);
            if (row1 < rows)
                *(float2*)(C + (size_t)row1 * Nout + col) = make_float2(o2, o3);
        }
    }
}

// ---------------------------------------------------------------------------
// CSR attention: warp per destination node. Lane owns 4 dims (head = lane>>2).
// No atomics; normalization fused.
// ---------------------------------------------------------------------------
__global__ void attn_csr(const int* __restrict__ rowptr, const int* __restrict__ csr_src,
                         const float* __restrict__ q, const float* __restrict__ k,
                         const float* __restrict__ v, float* __restrict__ attn, int N) {
    int warp = blockIdx.x * (blockDim.x >> 5) + (threadIdx.x >> 5);
    if (warp >= N) return;
    int lane = threadIdx.x & 31;
    int off = lane * 4;      // head = lane>>2, dims [head*16 + (lane&3)*4 .. +3]

    float4 qq = *(const float4*)(q + (size_t)warp * D + off);
    float4 acc = make_float4(0.f, 0.f, 0.f, 0.f);
    float Zh = 0.0f;

    int jb = rowptr[warp];
    int je = rowptr[warp + 1];
    for (int j = jb; j < je; j++) {
        int s0 = csr_src[j];
        float4 kk = *(const float4*)(k + (size_t)s0 * D + off);
        float s = kk.x * qq.x + kk.y * qq.y + kk.z * qq.z + kk.w * qq.w;
        s += __shfl_xor_sync(0xffffffffu, s, 1);
        s += __shfl_xor_sync(0xffffffffu, s, 2);
        s = expf(fminf(fmaxf(s * 0.25f, -5.0f), 5.0f));
        float4 vv = *(const float4*)(v + (size_t)s0 * D + off);
        acc.x = fmaf(vv.x, s, acc.x);
        acc.y = fmaf(vv.y, s, acc.y);
        acc.z = fmaf(vv.z, s, acc.z);
        acc.w = fmaf(vv.w, s, acc.w);
        Zh += s;
    }
    float inv = 1.0f / (Zh + 1e-6f);
    acc.x *= inv; acc.y *= inv; acc.z *= inv; acc.w *= inv;
    *(float4*)(attn + (size_t)warp * D + off) = acc;
}

// ---------------------------------------------------------------------------
__global__ void add_ln(const float* __restrict__ res, const float* __restrict__ y,
                       float* __restrict__ out, const float* __restrict__ g,
                       const float* __restrict__ b) {
    int row = blockIdx.x;
    int tid = threadIdx.x;
    float val = res[(size_t)row * D + tid] + y[(size_t)row * D + tid];

    __shared__ float red[4];
    float s = val;
#pragma unroll
    for (int o = 16; o > 0; o >>= 1) s += __shfl_xor_sync(0xffffffffu, s, o);
    if ((tid & 31) == 0) red[tid >> 5] = s;
    __syncthreads();
    float mean = (red[0] + red[1] + red[2] + red[3]) * (1.0f / 128.0f);

    float dlt = val - mean;
    float vs = dlt * dlt;
#pragma unroll
    for (int o = 16; o > 0; o >>= 1) vs += __shfl_xor_sync(0xffffffffu, vs, o);
    __syncthreads();
    if ((tid & 31) == 0) red[tid >> 5] = vs;
    __syncthreads();
    float var = (red[0] + red[1] + red[2] + red[3]) * (1.0f / 128.0f);

    out[(size_t)row * D + tid] = dlt * rsqrtf(var + 1e-5f) * g[tid] + b[tid];
}

__global__ void colsum(const float* __restrict__ x, float* __restrict__ acc, int N) {
    int d = threadIdx.x;
    float s = 0.0f;
    for (int r = blockIdx.x; r < N; r += gridDim.x)
        s += x[(size_t)r * D + d];
    atomicAdd(&acc[d], s);
}

__global__ void readout(const float* __restrict__ acc,
                        const float* __restrict__ mW0, const float* __restrict__ mb0,
                        const float* __restrict__ mW1, const float* __restrict__ mb1,
                        const float* __restrict__ mW2, const float* __restrict__ mb2,
                        float* __restrict__ out, int N) {
    __shared__ float m[D];
    __shared__ float h0[64];
    __shared__ float h1[32];
    int tid = threadIdx.x;
    m[tid] = acc[tid] * (1.0f / (float)N);
    __syncthreads();
    if (tid < 64) {
        float s = mb0[tid];
        for (int kk = 0; kk < D; kk++) s = fmaf(m[kk], mW0[kk * 64 + tid], s);
        h0[tid] = fmaxf(s, 0.0f);
    }
    __syncthreads();
    if (tid < 32) {
        float s = mb1[tid];
        for (int kk = 0; kk < 64; kk++) s = fmaf(h0[kk], mW1[kk * 32 + tid], s);
        h1[tid] = fmaxf(s, 0.0f);
    }
    __syncthreads();
    if (tid < 10) {
        float s = mb2[tid];
        for (int kk = 0; kk < 32; kk++) s = fmaf(h1[kk], mW2[kk * 10 + tid], s);
        out[tid] = s;
    }
}

// ---------------------------------------------------------------------------
extern "C" void kernel_launch(void* const* d_in, const int* in_sizes, int n_in,
                              void* d_out, int out_size) {
    const int*   x_idx = (const int*)d_in[0];
    const int*   ei    = (const int*)d_in[1];
    const float* emb   = (const float*)d_in[2];
    const float* Wq  = (const float*)d_in[3];
    const float* bq  = (const float*)d_in[4];
    const float* Wk  = (const float*)d_in[5];
    const float* bk  = (const float*)d_in[6];
    const float* Wv  = (const float*)d_in[7];
    const float* bv  = (const float*)d_in[8];
    const float* Wo  = (const float*)d_in[9];
    const float* bo  = (const float*)d_in[10];
    const float* g1  = (const float*)d_in[11];
    const float* be1 = (const float*)d_in[12];
    const float* Wf1 = (const float*)d_in[13];
    const float* bf1 = (const float*)d_in[14];
    const float* Wf2 = (const float*)d_in[15];
    const float* bf2 = (const float*)d_in[16];
    const float* g2  = (const float*)d_in[17];
    const float* be2 = (const float*)d_in[18];
    const float* mW0 = (const float*)d_in[19];
    const float* mb0 = (const float*)d_in[20];
    const float* mW1 = (const float*)d_in[21];
    const float* mb1 = (const float*)d_in[22];
    const float* mW2 = (const float*)d_in[23];
    const float* mb2 = (const float*)d_in[24];
    float* out = (float*)d_out;

    const int N = in_sizes[0];       // 50000
    const int E = in_sizes[1] / 2;   // 800000

    float* base;
    cudaGetSymbolAddress((void**)&base, g_scratch);
    float* x   = base + OFF_X;
    float* q   = base + OFF_Q;
    float* k   = base + OFF_K;
    float* v   = base + OFF_V;
    float* wV  = base + OFF_WV;
    float* y   = base + OFF_Y;
    float* mid = base + OFF_MID;
    float* acc = base + OFF_ACC;

    int* ibase;
    cudaGetSymbolAddress((void**)&ibase, g_iscratch);
    int* cnt     = ibase + IOFF_CNT;
    int* rowptr  = ibase + IOFF_ROW;
    int* csr_src = ibase + IOFF_SRC;

    cudaFuncSetAttribute(gemm_tc, cudaFuncAttributeMaxDynamicSharedMemorySize, GEMM_SMEM);

    const int nb128 = (N + 127) / 128;
    dim3 g1d(nb128, 1), g2d(nb128, 2);

    // CSR build (edge structure is layer-invariant)
    zero_int<<<(N + 255) / 256, 256>>>(cnt, N);
    hist_dst<<<(E + 255) / 256, 256>>>(ei, E, cnt);
    scan_rowptr<<<1, 1024>>>(cnt, rowptr, N);
    zero_int<<<(N + 255) / 256, 256>>>(cnt, N);
    csr_scatter<<<(E + 255) / 256, 256>>>(ei, E, rowptr, cnt, csr_src);

    emb_gather<<<(N * D + 255) / 256, 256>>>(x_idx, emb, x, N);

    for (int l = 0; l < LAYERS; l++) {
        const float* Wql = Wq + (size_t)l * D * D;
        const float* Wkl = Wk + (size_t)l * D * D;
        const float* Wvl = Wv + (size_t)l * D * D;
        const float* Wol = Wo + (size_t)l * D * D;
        const float* Wf1l = Wf1 + (size_t)l * D * 2 * D;
        const float* Wf2l = Wf2 + (size_t)l * 2 * D * D;

        gemm_tc<<<g1d, 256, GEMM_SMEM>>>(x, Wql, bq + l * D, q, N, D, D, 0);
        gemm_tc<<<g1d, 256, GEMM_SMEM>>>(x, Wkl, bk + l * D, k, N, D, D, 0);
        gemm_tc<<<g1d, 256, GEMM_SMEM>>>(x, Wvl, bv + l * D, v, N, D, D, 0);

        attn_csr<<<(N + 7) / 8, 256>>>(rowptr, csr_src, q, k, v, wV, N);

        gemm_tc<<<g1d, 256, GEMM_SMEM>>>(wV, Wol, bo + l * D, y, N, D, D, 0);
        add_ln<<<N, 128>>>(x, y, x, g1 + l * D, be1 + l * D);

        gemm_tc<<<g2d, 256, GEMM_SMEM>>>(y, Wf1l, bf1 + l * 2 * D, mid, N, D, 2 * D, 1);
        gemm_tc<<<g1d, 256, GEMM_SMEM>>>(mid, Wf2l, bf2 + l * D, q, N, 2 * D, D, 0);
        add_ln<<<N, 128>>>(x, q, x, g2 + l * D, be2 + l * D);
    }

    zero_kernel<<<1, 128>>>(acc, D);
    colsum<<<256, 128>>>(x, acc, N);
    readout<<<1, 128>>>(acc, mW0, mb0, mW1, mb1, mW2, mb2, out, N);
}

// round 4
// speedup vs baseline: 2.8625x; 1.3392x over previous
#include <cuda_runtime.h>
#include <cuda_bf16.h>
#include <cstddef>

#define D       128
#define H       8
#define HD      16
#define NMAX    50000
#define EMAX    800000
#define LAYERS  3

// ---------------------------------------------------------------------------
// Float scratch
// ---------------------------------------------------------------------------
#define OFF_X    ((size_t)0)
#define OFF_Q    (OFF_X  + (size_t)NMAX * D)
#define OFF_K    (OFF_Q  + (size_t)NMAX * D)
#define OFF_V    (OFF_K  + (size_t)NMAX * D)
#define OFF_WV   (OFF_V  + (size_t)NMAX * D)
#define OFF_Y    (OFF_WV + (size_t)NMAX * D)
#define OFF_MID  (OFF_Y  + (size_t)NMAX * D)
#define OFF_ACC  (OFF_MID + (size_t)NMAX * 2 * D)
#define SCRATCH_FLOATS (OFF_ACC + D)

__device__ float g_scratch[SCRATCH_FLOATS];

// Int scratch: cnt[N], rowptr[N+1], csr_src[E]
#define IOFF_CNT   0
#define IOFF_ROW   (IOFF_CNT + NMAX)
#define IOFF_SRC   (IOFF_ROW + NMAX + 1)
__device__ int g_iscratch[IOFF_SRC + EMAX];

// Packed bf16 hi/lo weights. Per matrix: [K/2 * Nout] hi then lo (uints).
// Layout: Wq(3L) Wk(3L) Wv(3L) Wo(3L) Wf1(3L) Wf2(3L)
#define PQ      (64 * 128)        // 8192 packed positions per DxD matrix
#define PF      (64 * 256)        // 16384 for 128x256 (and 256x128)
#define WQ_OFF  0
#define WK_OFF  (WQ_OFF + LAYERS * 2 * PQ)
#define WV_OFF  (WK_OFF + LAYERS * 2 * PQ)
#define WO_OFF  (WV_OFF + LAYERS * 2 * PQ)
#define WF1_OFF (WO_OFF + LAYERS * 2 * PQ)
#define WF2_OFF (WF1_OFF + LAYERS * 2 * PF)
#define WPACK_TOTAL (WF2_OFF + LAYERS * 2 * PF)
__device__ unsigned g_wpack[WPACK_TOTAL];

// ---------------------------------------------------------------------------
__global__ void zero_int(int* __restrict__ p, int n) {
    int i = blockIdx.x * blockDim.x + threadIdx.x;
    int stride = gridDim.x * blockDim.x;
    for (; i < n; i += stride) p[i] = 0;
}

__global__ void zero_kernel(float* __restrict__ p, int n) {
    int i = blockIdx.x * blockDim.x + threadIdx.x;
    int stride = gridDim.x * blockDim.x;
    for (; i < n; i += stride) p[i] = 0.0f;
}

__global__ void emb_gather(const int* __restrict__ idx, const float* __restrict__ emb,
                           float* __restrict__ x, int N) {
    int i = blockIdx.x * blockDim.x + threadIdx.x;
    if (i >= N * D) return;
    int n = i >> 7;
    int d = i & 127;
    x[i] = emb[(size_t)idx[n] * D + d];
}

// ---------------------------------------------------------------------------
// Weight conversion: float [L, K, Nout] -> packed bf16 hi/lo pairs along K.
// dst per layer block = 2*P (hi at +0, lo at +P), P = K/2*Nout.
// ---------------------------------------------------------------------------
__device__ __forceinline__ unsigned pack2_bf16(float lo, float hi) {
    __nv_bfloat162 h2 = __floats2bfloat162_rn(lo, hi);   // .x = lo (low 16 bits)
    return *(unsigned*)&h2;
}

__global__ void conv_w(const float* __restrict__ src, unsigned* __restrict__ dst,
                       int K, int Nout, int L) {
    int P = (K >> 1) * Nout;
    int total = L * P;
    int idx = blockIdx.x * blockDim.x + threadIdx.x;
    if (idx >= total) return;
    int l = idx / P;
    int p = idx - l * P;
    int kp = p / Nout;
    int n = p - kp * Nout;
    float a = src[(size_t)l * K * Nout + (size_t)(2 * kp) * Nout + n];
    float b = src[(size_t)l * K * Nout + (size_t)(2 * kp + 1) * Nout + n];
    __nv_bfloat16 ah = __float2bfloat16(a);
    __nv_bfloat16 bh = __float2bfloat16(b);
    float al = a - __bfloat162float(ah);
    float bl = b - __bfloat162float(bh);
    dst[(size_t)l * 2 * P + p]     = pack2_bf16(__bfloat162float(ah), __bfloat162float(bh));
    dst[(size_t)l * 2 * P + P + p] = pack2_bf16(al, bl);
}

// ---------------------------------------------------------------------------
// CSR build
// ---------------------------------------------------------------------------
__global__ void hist_dst(const int* __restrict__ ei, int E, int* __restrict__ cnt) {
    int j = blockIdx.x * blockDim.x + threadIdx.x;
    if (j < E) atomicAdd(&cnt[ei[E + j]], 1);
}

__global__ void scan_rowptr(const int* __restrict__ cnt, int* __restrict__ rowptr, int N) {
    __shared__ int ssum[1024];
    int tid = threadIdx.x;
    int chunk = (N + 1023) / 1024;
    int start = tid * chunk;
    int end = min(start + chunk, N);
    int s = 0;
    for (int i = start; i < end; i++) s += cnt[i];
    ssum[tid] = s;
    __syncthreads();
    int mysum = s;
    for (int o = 1; o < 1024; o <<= 1) {
        int t = (tid >= o) ? ssum[tid - o] : 0;
        __syncthreads();
        ssum[tid] += t;
        __syncthreads();
    }
    int off = ssum[tid] - mysum;
    for (int i = start; i < end; i++) { rowptr[i] = off; off += cnt[i]; }
    if (end == N) rowptr[N] = off;
}

__global__ void csr_scatter(const int* __restrict__ ei, int E,
                            const int* __restrict__ rowptr, int* __restrict__ cur,
                            int* __restrict__ csr_src) {
    int j = blockIdx.x * blockDim.x + threadIdx.x;
    if (j >= E) return;
    int d = ei[E + j];
    int pos = atomicAdd(&cur[d], 1);
    csr_src[rowptr[d] + pos] = ei[j];
}

// ---------------------------------------------------------------------------
// bf16x3 tensor-core GEMM core. Block tile 128x128, BLOCK_K=32,
// 256 threads (8 warps: 4 along M x 2 along N; warp tile 32x64).
// mma.sync.m16n8k16 bf16, hi/lo split (3 mma) => ~1e-5 accuracy.
// Weights pre-packed (hi at Wp, lo at Wp + K/2*Nout), pairs along K.
// ---------------------------------------------------------------------------
#define ASTR 20
#define BSTR 136
#define SM_AH 0
#define SM_AL 2560
#define SM_BH 5120
#define SM_BL 7296
#define SMEM_UINTS 9472

__device__ __forceinline__ void mma16(float c[4], const unsigned a[4], const unsigned b[2]) {
    asm volatile(
        "mma.sync.aligned.m16n8k16.row.col.f32.bf16.bf16.f32 "
        "{%0,%1,%2,%3}, {%4,%5,%6,%7}, {%8,%9}, {%0,%1,%2,%3};"
        : "+f"(c[0]), "+f"(c[1]), "+f"(c[2]), "+f"(c[3])
        : "r"(a[0]), "r"(a[1]), "r"(a[2]), "r"(a[3]), "r"(b[0]), "r"(b[1]));
}

__device__ __forceinline__ void gemm_core(
    const float* __restrict__ A, const unsigned* __restrict__ Wp,
    int rows, int K, int Nout, int bm, int bn,
    unsigned* sm, float acc[2][8][4])
{
    unsigned* Ah = sm + SM_AH;
    unsigned* Al = sm + SM_AL;
    unsigned* Bh = sm + SM_BH;
    unsigned* Bl = sm + SM_BL;
    const unsigned* Wlo = Wp + (size_t)(K >> 1) * Nout;

    const int tid = threadIdx.x;
    const int lane = tid & 31;
    const int wid = tid >> 5;
    const int warp_m = wid & 3;
    const int warp_n = wid >> 2;
    const int lr = lane >> 2;
    const int lc = lane & 3;

#pragma unroll
    for (int mi = 0; mi < 2; mi++)
#pragma unroll
        for (int ni = 0; ni < 8; ni++)
#pragma unroll
            for (int t = 0; t < 4; t++) acc[mi][ni][t] = 0.0f;

    for (int kc = 0; kc < K; kc += 32) {
        // A tile 128x32 floats -> packed hi/lo (pairs along k)
#pragma unroll
        for (int it = 0; it < 4; it++) {
            int idx = tid + it * 256;
            int r = idx >> 3;
            int c4 = idx & 7;
            int row = bm + r;
            float4 val = make_float4(0.f, 0.f, 0.f, 0.f);
            if (row < rows)
                val = *(const float4*)(A + (size_t)row * K + kc + c4 * 4);
            float f[4] = {val.x, val.y, val.z, val.w};
            unsigned hp[2], lp[2];
#pragma unroll
            for (int t = 0; t < 2; t++) {
                float a = f[2 * t], b = f[2 * t + 1];
                __nv_bfloat16 ahh = __float2bfloat16(a);
                __nv_bfloat16 bhh = __float2bfloat16(b);
                hp[t] = pack2_bf16(__bfloat162float(ahh), __bfloat162float(bhh));
                lp[t] = pack2_bf16(a - __bfloat162float(ahh), b - __bfloat162float(bhh));
            }
            *(uint2*)(Ah + r * ASTR + c4 * 2) = make_uint2(hp[0], hp[1]);
            *(uint2*)(Al + r * ASTR + c4 * 2) = make_uint2(lp[0], lp[1]);
        }
        // B tile: copy packed weights (16 kp x 128 n), uint4
        int kp0 = kc >> 1;
#pragma unroll
        for (int it = 0; it < 2; it++) {
            int idx = tid + it * 256;
            int kpl = idx >> 5;
            int n4 = idx & 31;
            size_t gsrc = (size_t)(kp0 + kpl) * Nout + bn + n4 * 4;
            *(uint4*)(Bh + kpl * BSTR + n4 * 4) = *(const uint4*)(Wp + gsrc);
            *(uint4*)(Bl + kpl * BSTR + n4 * 4) = *(const uint4*)(Wlo + gsrc);
        }
        __syncthreads();

#pragma unroll
        for (int s = 0; s < 2; s++) {
            unsigned ah[2][4], al[2][4];
#pragma unroll
            for (int mi = 0; mi < 2; mi++) {
                int rb = warp_m * 32 + mi * 16 + lr;
                int o0 = rb * ASTR + 8 * s + lc;
                int o1 = (rb + 8) * ASTR + 8 * s + lc;
                ah[mi][0] = Ah[o0];     ah[mi][1] = Ah[o1];
                ah[mi][2] = Ah[o0 + 4]; ah[mi][3] = Ah[o1 + 4];
                al[mi][0] = Al[o0];     al[mi][1] = Al[o1];
                al[mi][2] = Al[o0 + 4]; al[mi][3] = Al[o1 + 4];
            }
            unsigned bh[8][2], bl[8][2];
#pragma unroll
            for (int ni = 0; ni < 8; ni++) {
                int cb = warp_n * 64 + ni * 8 + lr;
                bh[ni][0] = Bh[(8 * s + lc) * BSTR + cb];
                bh[ni][1] = Bh[(8 * s + lc + 4) * BSTR + cb];
                bl[ni][0] = Bl[(8 * s + lc) * BSTR + cb];
                bl[ni][1] = Bl[(8 * s + lc + 4) * BSTR + cb];
            }
#pragma unroll
            for (int mi = 0; mi < 2; mi++)
#pragma unroll
                for (int ni = 0; ni < 8; ni++) {
                    mma16(acc[mi][ni], al[mi], bh[ni]);
                    mma16(acc[mi][ni], ah[mi], bl[ni]);
                    mma16(acc[mi][ni], ah[mi], bh[ni]);
                }
        }
        __syncthreads();
    }
}

// Generic GEMM (+bias, optional relu)
__global__ void gemm_bf16(const float* __restrict__ A, const unsigned* __restrict__ Wp,
                          const float* __restrict__ bias, float* __restrict__ C,
                          int rows, int K, int Nout, int relu) {
    __shared__ unsigned sm[SMEM_UINTS];
    const int bm = blockIdx.x * 128;
    const int bn = blockIdx.y * 128;
    float acc[2][8][4];
    gemm_core(A, Wp, rows, K, Nout, bm, bn, sm, acc);

    const int lane = threadIdx.x & 31;
    const int wid = threadIdx.x >> 5;
    const int warp_m = wid & 3, warp_n = wid >> 2;
    const int lr = lane >> 2, lc = lane & 3;
#pragma unroll
    for (int mi = 0; mi < 2; mi++) {
        int row0 = bm + warp_m * 32 + mi * 16 + lr;
        int row1 = row0 + 8;
#pragma unroll
        for (int ni = 0; ni < 8; ni++) {
            int col = bn + warp_n * 64 + ni * 8 + 2 * lc;
            float bs0 = bias[col], bs1 = bias[col + 1];
            float o0 = acc[mi][ni][0] + bs0;
            float o1 = acc[mi][ni][1] + bs1;
            float o2 = acc[mi][ni][2] + bs0;
            float o3 = acc[mi][ni][3] + bs1;
            if (relu) {
                o0 = fmaxf(o0, 0.f); o1 = fmaxf(o1, 0.f);
                o2 = fmaxf(o2, 0.f); o3 = fmaxf(o3, 0.f);
            }
            if (row0 < rows) *(float2*)(C + (size_t)row0 * Nout + col) = make_float2(o0, o1);
            if (row1 < rows) *(float2*)(C + (size_t)row1 * Nout + col) = make_float2(o2, o3);
        }
    }
}

// QKV fused: grid.z selects weight/bias/output
__global__ void gemm_qkv(const float* __restrict__ A,
                         const unsigned* __restrict__ Wpq, const unsigned* __restrict__ Wpk,
                         const unsigned* __restrict__ Wpv,
                         const float* __restrict__ bq, const float* __restrict__ bk,
                         const float* __restrict__ bv,
                         float* __restrict__ Cq, float* __restrict__ Ck, float* __restrict__ Cv,
                         int rows) {
    __shared__ unsigned sm[SMEM_UINTS];
    const int z = blockIdx.z;
    const unsigned* Wp = (z == 0) ? Wpq : (z == 1) ? Wpk : Wpv;
    const float* bias  = (z == 0) ? bq  : (z == 1) ? bk  : bv;
    float* C           = (z == 0) ? Cq  : (z == 1) ? Ck  : Cv;
    const int bm = blockIdx.x * 128;
    float acc[2][8][4];
    gemm_core(A, Wp, rows, D, D, bm, 0, sm, acc);

    const int lane = threadIdx.x & 31;
    const int wid = threadIdx.x >> 5;
    const int warp_m = wid & 3, warp_n = wid >> 2;
    const int lr = lane >> 2, lc = lane & 3;
#pragma unroll
    for (int mi = 0; mi < 2; mi++) {
        int row0 = bm + warp_m * 32 + mi * 16 + lr;
        int row1 = row0 + 8;
#pragma unroll
        for (int ni = 0; ni < 8; ni++) {
            int col = warp_n * 64 + ni * 8 + 2 * lc;
            float bs0 = bias[col], bs1 = bias[col + 1];
            if (row0 < rows)
                *(float2*)(C + (size_t)row0 * D + col) =
                    make_float2(acc[mi][ni][0] + bs0, acc[mi][ni][1] + bs1);
            if (row1 < rows)
                *(float2*)(C + (size_t)row1 * D + col) =
                    make_float2(acc[mi][ni][2] + bs0, acc[mi][ni][3] + bs1);
        }
    }
}

// GEMM with fused residual + LayerNorm epilogue (Nout = D = 128, full row/block):
//   o   = A@W + bias            (optionally written to Y)
//   xio = LN(xio + o)*g + b     (in place on xio)
__global__ void gemm_ln(const float* __restrict__ A, const unsigned* __restrict__ Wp,
                        const float* __restrict__ bias, float* __restrict__ Y,
                        float* __restrict__ xio, const float* __restrict__ g,
                        const float* __restrict__ b, int rows, int K, int write_y) {
    __shared__ unsigned sm[SMEM_UINTS];
    const int bm = blockIdx.x * 128;
    float acc[2][8][4];
    gemm_core(A, Wp, rows, K, D, bm, 0, sm, acc);

    const int lane = threadIdx.x & 31;
    const int wid = threadIdx.x >> 5;
    const int warp_m = wid & 3, warp_n = wid >> 2;
    const int lr = lane >> 2, lc = lane & 3;

    float* sred = (float*)sm;   // [128 rows][2 warp_n][{sum, sumsq}] = 512 floats

    // Compute val = o + x_res, overwrite acc with val, accumulate row stats.
#pragma unroll
    for (int mi = 0; mi < 2; mi++) {
#pragma unroll
        for (int rp = 0; rp < 2; rp++) {
            int r_loc = warp_m * 32 + mi * 16 + lr + 8 * rp;
            int row = bm + r_loc;
            float sum = 0.f, sq = 0.f;
#pragma unroll
            for (int ni = 0; ni < 8; ni++) {
                int col = warp_n * 64 + ni * 8 + 2 * lc;
                float o0 = acc[mi][ni][2 * rp + 0] + bias[col];
                float o1 = acc[mi][ni][2 * rp + 1] + bias[col + 1];
                float x0 = 0.f, x1 = 0.f;
                if (row < rows) {
                    float2 xr = *(const float2*)(xio + (size_t)row * D + col);
                    x0 = xr.x; x1 = xr.y;
                    if (write_y)
                        *(float2*)(Y + (size_t)row * D + col) = make_float2(o0, o1);
                }
                float v0 = o0 + x0, v1 = o1 + x1;
                acc[mi][ni][2 * rp + 0] = v0;
                acc[mi][ni][2 * rp + 1] = v1;
                sum += v0 + v1;
                sq += v0 * v0 + v1 * v1;
            }
            // reduce over lc (lane bits 0,1)
            sum += __shfl_xor_sync(0xffffffffu, sum, 1);
            sq  += __shfl_xor_sync(0xffffffffu, sq, 1);
            sum += __shfl_xor_sync(0xffffffffu, sum, 2);
            sq  += __shfl_xor_sync(0xffffffffu, sq, 2);
            if (lc == 0) {
                sred[r_loc * 4 + warp_n * 2 + 0] = sum;
                sred[r_loc * 4 + warp_n * 2 + 1] = sq;
            }
        }
    }
    __syncthreads();

#pragma unroll
    for (int mi = 0; mi < 2; mi++) {
#pragma unroll
        for (int rp = 0; rp < 2; rp++) {
            int r_loc = warp_m * 32 + mi * 16 + lr + 8 * rp;
            int row = bm + r_loc;
            if (row >= rows) continue;
            float sum = sred[r_loc * 4 + 0] + sred[r_loc * 4 + 2];
            float sq  = sred[r_loc * 4 + 1] + sred[r_loc * 4 + 3];
            float mean = sum * (1.0f / 128.0f);
            float var = sq * (1.0f / 128.0f) - mean * mean;
            float rstd = rsqrtf(var + 1e-5f);
#pragma unroll
            for (int ni = 0; ni < 8; ni++) {
                int col = warp_n * 64 + ni * 8 + 2 * lc;
                float v0 = acc[mi][ni][2 * rp + 0];
                float v1 = acc[mi][ni][2 * rp + 1];
                float out0 = (v0 - mean) * rstd * g[col] + b[col];
                float out1 = (v1 - mean) * rstd * g[col + 1] + b[col + 1];
                *(float2*)(xio + (size_t)row * D + col) = make_float2(out0, out1);
            }
        }
    }
}

// ---------------------------------------------------------------------------
// CSR attention: warp per destination node.
// ---------------------------------------------------------------------------
__global__ void attn_csr(const int* __restrict__ rowptr, const int* __restrict__ csr_src,
                         const float* __restrict__ q, const float* __restrict__ k,
                         const float* __restrict__ v, float* __restrict__ attn, int N) {
    int warp = blockIdx.x * (blockDim.x >> 5) + (threadIdx.x >> 5);
    if (warp >= N) return;
    int lane = threadIdx.x & 31;
    int off = lane * 4;

    float4 qq = *(const float4*)(q + (size_t)warp * D + off);
    float4 acc = make_float4(0.f, 0.f, 0.f, 0.f);
    float Zh = 0.0f;

    int jb = rowptr[warp];
    int je = rowptr[warp + 1];
    for (int j = jb; j < je; j++) {
        int s0 = csr_src[j];
        float4 kk = *(const float4*)(k + (size_t)s0 * D + off);
        float s = kk.x * qq.x + kk.y * qq.y + kk.z * qq.z + kk.w * qq.w;
        s += __shfl_xor_sync(0xffffffffu, s, 1);
        s += __shfl_xor_sync(0xffffffffu, s, 2);
        s = expf(fminf(fmaxf(s * 0.25f, -5.0f), 5.0f));
        float4 vv = *(const float4*)(v + (size_t)s0 * D + off);
        acc.x = fmaf(vv.x, s, acc.x);
        acc.y = fmaf(vv.y, s, acc.y);
        acc.z = fmaf(vv.z, s, acc.z);
        acc.w = fmaf(vv.w, s, acc.w);
        Zh += s;
    }
    float inv = 1.0f / (Zh + 1e-6f);
    acc.x *= inv; acc.y *= inv; acc.z *= inv; acc.w *= inv;
    *(float4*)(attn + (size_t)warp * D + off) = acc;
}

// ---------------------------------------------------------------------------
__global__ void colsum(const float* __restrict__ x, float* __restrict__ acc, int N) {
    int d = threadIdx.x;
    float s = 0.0f;
    for (int r = blockIdx.x; r < N; r += gridDim.x)
        s += x[(size_t)r * D + d];
    atomicAdd(&acc[d], s);
}

__global__ void readout(const float* __restrict__ acc,
                        const float* __restrict__ mW0, const float* __restrict__ mb0,
                        const float* __restrict__ mW1, const float* __restrict__ mb1,
                        const float* __restrict__ mW2, const float* __restrict__ mb2,
                        float* __restrict__ out, int N) {
    __shared__ float m[D];
    __shared__ float h0[64];
    __shared__ float h1[32];
    int tid = threadIdx.x;
    m[tid] = acc[tid] * (1.0f / (float)N);
    __syncthreads();
    if (tid < 64) {
        float s = mb0[tid];
        for (int kk = 0; kk < D; kk++) s = fmaf(m[kk], mW0[kk * 64 + tid], s);
        h0[tid] = fmaxf(s, 0.0f);
    }
    __syncthreads();
    if (tid < 32) {
        float s = mb1[tid];
        for (int kk = 0; kk < 64; kk++) s = fmaf(h0[kk], mW1[kk * 32 + tid], s);
        h1[tid] = fmaxf(s, 0.0f);
    }
    __syncthreads();
    if (tid < 10) {
        float s = mb2[tid];
        for (int kk = 0; kk < 32; kk++) s = fmaf(h1[kk], mW2[kk * 10 + tid], s);
        out[tid] = s;
    }
}

// ---------------------------------------------------------------------------
extern "C" void kernel_launch(void* const* d_in, const int* in_sizes, int n_in,
                              void* d_out, int out_size) {
    const int*   x_idx = (const int*)d_in[0];
    const int*   ei    = (const int*)d_in[1];
    const float* emb   = (const float*)d_in[2];
    const float* Wq  = (const float*)d_in[3];
    const float* bq  = (const float*)d_in[4];
    const float* Wk  = (const float*)d_in[5];
    const float* bk  = (const float*)d_in[6];
    const float* Wv  = (const float*)d_in[7];
    const float* bv  = (const float*)d_in[8];
    const float* Wo  = (const float*)d_in[9];
    const float* bo  = (const float*)d_in[10];
    const float* g1  = (const float*)d_in[11];
    const float* be1 = (const float*)d_in[12];
    const float* Wf1 = (const float*)d_in[13];
    const float* bf1 = (const float*)d_in[14];
    const float* Wf2 = (const float*)d_in[15];
    const float* bf2 = (const float*)d_in[16];
    const float* g2  = (const float*)d_in[17];
    const float* be2 = (const float*)d_in[18];
    const float* mW0 = (const float*)d_in[19];
    const float* mb0 = (const float*)d_in[20];
    const float* mW1 = (const float*)d_in[21];
    const float* mb1 = (const float*)d_in[22];
    const float* mW2 = (const float*)d_in[23];
    const float* mb2 = (const float*)d_in[24];
    float* out = (float*)d_out;

    const int N = in_sizes[0];       // 50000
    const int E = in_sizes[1] / 2;   // 800000

    float* base;
    cudaGetSymbolAddress((void**)&base, g_scratch);
    float* x   = base + OFF_X;
    float* q   = base + OFF_Q;
    float* k   = base + OFF_K;
    float* v   = base + OFF_V;
    float* wV  = base + OFF_WV;
    float* y   = base + OFF_Y;
    float* mid = base + OFF_MID;
    float* acc = base + OFF_ACC;

    int* ibase;
    cudaGetSymbolAddress((void**)&ibase, g_iscratch);
    int* cnt     = ibase + IOFF_CNT;
    int* rowptr  = ibase + IOFF_ROW;
    int* csr_src = ibase + IOFF_SRC;

    unsigned* wp;
    cudaGetSymbolAddress((void**)&wp, g_wpack);

    // Weight conversion (per launch; weights reused by 391 blocks each)
    conv_w<<<(LAYERS * PQ + 255) / 256, 256>>>(Wq, wp + WQ_OFF, 128, 128, LAYERS);
    conv_w<<<(LAYERS * PQ + 255) / 256, 256>>>(Wk, wp + WK_OFF, 128, 128, LAYERS);
    conv_w<<<(LAYERS * PQ + 255) / 256, 256>>>(Wv, wp + WV_OFF, 128, 128, LAYERS);
    conv_w<<<(LAYERS * PQ + 255) / 256, 256>>>(Wo, wp + WO_OFF, 128, 128, LAYERS);
    conv_w<<<(LAYERS * PF + 255) / 256, 256>>>(Wf1, wp + WF1_OFF, 128, 256, LAYERS);
    conv_w<<<(LAYERS * PF + 255) / 256, 256>>>(Wf2, wp + WF2_OFF, 256, 128, LAYERS);

    // CSR build
    zero_int<<<(N + 255) / 256, 256>>>(cnt, N);
    hist_dst<<<(E + 255) / 256, 256>>>(ei, E, cnt);
    scan_rowptr<<<1, 1024>>>(cnt, rowptr, N);
    zero_int<<<(N + 255) / 256, 256>>>(cnt, N);
    csr_scatter<<<(E + 255) / 256, 256>>>(ei, E, rowptr, cnt, csr_src);

    emb_gather<<<(N * D + 255) / 256, 256>>>(x_idx, emb, x, N);

    const int nb128 = (N + 127) / 128;

    for (int l = 0; l < LAYERS; l++) {
        const unsigned* wq_p = wp + WQ_OFF + (size_t)l * 2 * PQ;
        const unsigned* wk_p = wp + WK_OFF + (size_t)l * 2 * PQ;
        const unsigned* wv_p = wp + WV_OFF + (size_t)l * 2 * PQ;
        const unsigned* wo_p = wp + WO_OFF + (size_t)l * 2 * PQ;
        const unsigned* wf1_p = wp + WF1_OFF + (size_t)l * 2 * PF;
        const unsigned* wf2_p = wp + WF2_OFF + (size_t)l * 2 * PF;

        gemm_qkv<<<dim3(nb128, 1, 3), 256>>>(x, wq_p, wk_p, wv_p,
                                             bq + l * D, bk + l * D, bv + l * D,
                                             q, k, v, N);

        attn_csr<<<(N + 7) / 8, 256>>>(rowptr, csr_src, q, k, v, wV, N);

        // y = wV@Wo + bo (stored); x = LN(x + y)
        gemm_ln<<<nb128, 256>>>(wV, wo_p, bo + l * D, y, x,
                                g1 + l * D, be1 + l * D, N, D, 1);

        // mid = relu(y@Wf1 + bf1)
        gemm_bf16<<<dim3(nb128, 2), 256>>>(y, wf1_p, bf1 + l * 2 * D, mid, N, D, 2 * D, 1);

        // x = LN(x + mid@Wf2 + bf2)
        gemm_ln<<<nb128, 256>>>(mid, wf2_p, bf2 + l * D, nullptr, x,
                                g2 + l * D, be2 + l * D, N, 2 * D, 0);
    }

    zero_kernel<<<1, 128>>>(acc, D);
    colsum<<<256, 128>>>(x, acc, N);
    readout<<<1, 128>>>(acc, mW0, mb0, mW1, mb1, mW2, mb2, out, N);
}

// round 5
// speedup vs baseline: 2.8810x; 1.0065x over previous
#include <cuda_runtime.h>
#include <cuda_bf16.h>
#include <cstddef>

#define D       128
#define H       8
#define HD      16
#define NMAX    50000
#define NPAD    50176          // 392 * 128, padded row count for packed buffers
#define EMAX    800000
#define LAYERS  3

// ---------------------------------------------------------------------------
// Float scratch: x (residual/pool), q,k,v (attn), acc
// ---------------------------------------------------------------------------
#define OFF_X    ((size_t)0)
#define OFF_Q    (OFF_X  + (size_t)NMAX * D)
#define OFF_K    (OFF_Q  + (size_t)NMAX * D)
#define OFF_V    (OFF_K  + (size_t)NMAX * D)
#define OFF_ACC  (OFF_V  + (size_t)NMAX * D)
#define SCRATCH_FLOATS (OFF_ACC + D)
__device__ float g_scratch[SCRATCH_FLOATS];

// Packed bf16 hi/lo activations (plane 0 = hi, plane 1 = lo)
#define XPL   ((size_t)NPAD * 64)
#define MIDPL ((size_t)NPAD * 128)
__device__ unsigned g_xp[2 * XPL];
__device__ unsigned g_yp[2 * XPL];
__device__ unsigned g_wvp[2 * XPL];
__device__ unsigned g_midp[2 * MIDPL];

// Int scratch: cnt[N], rowptr[N+1], csr_src[E]
#define IOFF_CNT   0
#define IOFF_ROW   (IOFF_CNT + NMAX)
#define IOFF_SRC   (IOFF_ROW + NMAX + 1)
__device__ int g_iscratch[IOFF_SRC + EMAX];

// Packed bf16 hi/lo weights: per matrix [K/2 * Nout] hi then lo
#define PQ      (64 * 128)
#define PF      (64 * 256)
#define WQ_OFF  0
#define WK_OFF  (WQ_OFF + LAYERS * 2 * PQ)
#define WV_OFF  (WK_OFF + LAYERS * 2 * PQ)
#define WO_OFF  (WV_OFF + LAYERS * 2 * PQ)
#define WF1_OFF (WO_OFF + LAYERS * 2 * PQ)
#define WF2_OFF (WF1_OFF + LAYERS * 2 * PF)
#define WPACK_TOTAL (WF2_OFF + LAYERS * 2 * PF)
__device__ unsigned g_wpack[WPACK_TOTAL];

// ---------------------------------------------------------------------------
__device__ __forceinline__ unsigned pack2_bf16(float lo, float hi) {
    __nv_bfloat162 h2 = __floats2bfloat162_rn(lo, hi);
    return *(unsigned*)&h2;
}

__device__ __forceinline__ void pack_pair(float a, float b, unsigned& hi, unsigned& lo) {
    __nv_bfloat16 ah = __float2bfloat16(a), bh = __float2bfloat16(b);
    hi = pack2_bf16(__bfloat162float(ah), __bfloat162float(bh));
    lo = pack2_bf16(a - __bfloat162float(ah), b - __bfloat162float(bh));
}

__device__ __forceinline__ void cp16(unsigned* smem, const unsigned* gmem) {
    unsigned sa = (unsigned)__cvta_generic_to_shared(smem);
    asm volatile("cp.async.cg.shared.global [%0], [%1], 16;" :: "r"(sa), "l"(gmem));
}

// ---------------------------------------------------------------------------
__global__ void zero_int(int* __restrict__ p, int n) {
    int i = blockIdx.x * blockDim.x + threadIdx.x;
    int stride = gridDim.x * blockDim.x;
    for (; i < n; i += stride) p[i] = 0;
}

__global__ void zero_kernel(float* __restrict__ p, int n) {
    int i = blockIdx.x * blockDim.x + threadIdx.x;
    int stride = gridDim.x * blockDim.x;
    for (; i < n; i += stride) p[i] = 0.0f;
}

// Embedding gather: writes float x + packed xp
__global__ void emb_gather(const int* __restrict__ idx, const float* __restrict__ emb,
                           float* __restrict__ x, unsigned* __restrict__ xp, int N) {
    int i = blockIdx.x * blockDim.x + threadIdx.x;
    if (i >= N * 64) return;
    int n = i >> 6;
    int kp = i & 63;
    float2 e = *(const float2*)(emb + (size_t)idx[n] * D + 2 * kp);
    *(float2*)(x + (size_t)n * D + 2 * kp) = e;
    unsigned hi, lo;
    pack_pair(e.x, e.y, hi, lo);
    xp[(size_t)n * 64 + kp] = hi;
    xp[XPL + (size_t)n * 64 + kp] = lo;
}

// Weight conversion
__global__ void conv_w(const float* __restrict__ src, unsigned* __restrict__ dst,
                       int K, int Nout, int L) {
    int P = (K >> 1) * Nout;
    int total = L * P;
    int idx = blockIdx.x * blockDim.x + threadIdx.x;
    if (idx >= total) return;
    int l = idx / P;
    int p = idx - l * P;
    int kp = p / Nout;
    int n = p - kp * Nout;
    float a = src[(size_t)l * K * Nout + (size_t)(2 * kp) * Nout + n];
    float b = src[(size_t)l * K * Nout + (size_t)(2 * kp + 1) * Nout + n];
    unsigned hi, lo;
    pack_pair(a, b, hi, lo);
    dst[(size_t)l * 2 * P + p] = hi;
    dst[(size_t)l * 2 * P + P + p] = lo;
}

// ---------------------------------------------------------------------------
// CSR build
// ---------------------------------------------------------------------------
__global__ void hist_dst(const int* __restrict__ ei, int E, int* __restrict__ cnt) {
    int j = blockIdx.x * blockDim.x + threadIdx.x;
    if (j < E) atomicAdd(&cnt[ei[E + j]], 1);
}

__global__ void scan_rowptr(const int* __restrict__ cnt, int* __restrict__ rowptr, int N) {
    __shared__ int ssum[1024];
    int tid = threadIdx.x;
    int chunk = (N + 1023) / 1024;
    int start = tid * chunk;
    int end = min(start + chunk, N);
    int s = 0;
    for (int i = start; i < end; i++) s += cnt[i];
    ssum[tid] = s;
    __syncthreads();
    int mysum = s;
    for (int o = 1; o < 1024; o <<= 1) {
        int t = (tid >= o) ? ssum[tid - o] : 0;
        __syncthreads();
        ssum[tid] += t;
        __syncthreads();
    }
    int off = ssum[tid] - mysum;
    for (int i = start; i < end; i++) { rowptr[i] = off; off += cnt[i]; }
    if (end == N) rowptr[N] = off;
}

__global__ void csr_scatter(const int* __restrict__ ei, int E,
                            const int* __restrict__ rowptr, int* __restrict__ cur,
                            int* __restrict__ csr_src) {
    int j = blockIdx.x * blockDim.x + threadIdx.x;
    if (j >= E) return;
    int d = ei[E + j];
    int pos = atomicAdd(&cur[d], 1);
    csr_src[rowptr[d] + pos] = ei[j];
}

// ---------------------------------------------------------------------------
// bf16x3 tensor-core GEMM core, packed A + packed W, cp.async double buffer.
// Block tile 128x128, chunk K=32, 256 threads (8 warps, warp tile 32x64).
// ---------------------------------------------------------------------------
#define ASTR 20
#define BSTR 136
#define SM_AH 0
#define SM_AL 2560
#define SM_BH 5120
#define SM_BL 7296
#define STG_UINTS 9472
#define GEMM_DYN_SMEM (2 * STG_UINTS * 4)

__device__ __forceinline__ void mma16(float c[4], const unsigned a[4], const unsigned b[2]) {
    asm volatile(
        "mma.sync.aligned.m16n8k16.row.col.f32.bf16.bf16.f32 "
        "{%0,%1,%2,%3}, {%4,%5,%6,%7}, {%8,%9}, {%0,%1,%2,%3};"
        : "+f"(c[0]), "+f"(c[1]), "+f"(c[2]), "+f"(c[3])
        : "r"(a[0]), "r"(a[1]), "r"(a[2]), "r"(a[3]), "r"(b[0]), "r"(b[1]));
}

__device__ __forceinline__ void load_stage(
    const unsigned* __restrict__ Ap, size_t aplane, int ldA,
    const unsigned* __restrict__ Wp, size_t wplane, int Nout,
    int bm, int bn, int chunk, unsigned* s, int tid)
{
    int kp0 = chunk * 16;
#pragma unroll
    for (int it = 0; it < 2; it++) {
        int idx = tid + it * 256;
        int r = idx >> 2;
        int c4 = idx & 3;
        const unsigned* g = Ap + (size_t)(bm + r) * ldA + kp0 + c4 * 4;
        cp16(s + SM_AH + r * ASTR + c4 * 4, g);
        cp16(s + SM_AL + r * ASTR + c4 * 4, g + aplane);
    }
#pragma unroll
    for (int it = 0; it < 2; it++) {
        int idx = tid + it * 256;
        int kpl = idx >> 5;
        int n4 = idx & 31;
        const unsigned* g = Wp + (size_t)(kp0 + kpl) * Nout + bn + n4 * 4;
        cp16(s + SM_BH + kpl * BSTR + n4 * 4, g);
        cp16(s + SM_BL + kpl * BSTR + n4 * 4, g + wplane);
    }
    asm volatile("cp.async.commit_group;");
}

__device__ __forceinline__ void gemm_core_p(
    const unsigned* __restrict__ Ap, size_t aplane, int ldA,
    const unsigned* __restrict__ Wp, size_t wplane,
    int K, int Nout, int bm, int bn,
    unsigned* sm, float acc[2][8][4])
{
    const int tid = threadIdx.x;
    const int lane = tid & 31;
    const int wid = tid >> 5;
    const int warp_m = wid & 3;
    const int warp_n = wid >> 2;
    const int lr = lane >> 2;
    const int lc = lane & 3;

#pragma unroll
    for (int mi = 0; mi < 2; mi++)
#pragma unroll
        for (int ni = 0; ni < 8; ni++)
#pragma unroll
            for (int t = 0; t < 4; t++) acc[mi][ni][t] = 0.0f;

    const int C = K >> 5;
    load_stage(Ap, aplane, ldA, Wp, wplane, Nout, bm, bn, 0, sm, tid);

    for (int c = 0; c < C; c++) {
        if (c + 1 < C) {
            load_stage(Ap, aplane, ldA, Wp, wplane, Nout, bm, bn, c + 1,
                       sm + ((c + 1) & 1) * STG_UINTS, tid);
            asm volatile("cp.async.wait_group 1;");
        } else {
            asm volatile("cp.async.wait_group 0;");
        }
        __syncthreads();

        unsigned* s = sm + (c & 1) * STG_UINTS;
        unsigned* Ah = s + SM_AH;
        unsigned* Al = s + SM_AL;
        unsigned* Bh = s + SM_BH;
        unsigned* Bl = s + SM_BL;

#pragma unroll
        for (int st = 0; st < 2; st++) {
            unsigned ah[2][4], al[2][4];
#pragma unroll
            for (int mi = 0; mi < 2; mi++) {
                int rb = warp_m * 32 + mi * 16 + lr;
                int o0 = rb * ASTR + 8 * st + lc;
                int o1 = (rb + 8) * ASTR + 8 * st + lc;
                ah[mi][0] = Ah[o0];     ah[mi][1] = Ah[o1];
                ah[mi][2] = Ah[o0 + 4]; ah[mi][3] = Ah[o1 + 4];
                al[mi][0] = Al[o0];     al[mi][1] = Al[o1];
                al[mi][2] = Al[o0 + 4]; al[mi][3] = Al[o1 + 4];
            }
            unsigned bh[8][2], bl[8][2];
#pragma unroll
            for (int ni = 0; ni < 8; ni++) {
                int cb = warp_n * 64 + ni * 8 + lr;
                bh[ni][0] = Bh[(8 * st + lc) * BSTR + cb];
                bh[ni][1] = Bh[(8 * st + lc + 4) * BSTR + cb];
                bl[ni][0] = Bl[(8 * st + lc) * BSTR + cb];
                bl[ni][1] = Bl[(8 * st + lc + 4) * BSTR + cb];
            }
#pragma unroll
            for (int mi = 0; mi < 2; mi++)
#pragma unroll
                for (int ni = 0; ni < 8; ni++) {
                    mma16(acc[mi][ni], al[mi], bh[ni]);
                    mma16(acc[mi][ni], ah[mi], bl[ni]);
                    mma16(acc[mi][ni], ah[mi], bh[ni]);
                }
        }
        __syncthreads();
    }
}

// QKV fused: grid.z selects weight/bias/output; writes float q/k/v for attn.
__global__ void gemm_qkv(const unsigned* __restrict__ Ap,
                         const unsigned* __restrict__ Wpq, const unsigned* __restrict__ Wpk,
                         const unsigned* __restrict__ Wpv,
                         const float* __restrict__ bq, const float* __restrict__ bk,
                         const float* __restrict__ bv,
                         float* __restrict__ Cq, float* __restrict__ Ck, float* __restrict__ Cv,
                         int rows) {
    extern __shared__ unsigned sm[];
    const int z = blockIdx.z;
    const unsigned* Wp = (z == 0) ? Wpq : (z == 1) ? Wpk : Wpv;
    const float* bias  = (z == 0) ? bq  : (z == 1) ? bk  : bv;
    float* C           = (z == 0) ? Cq  : (z == 1) ? Ck  : Cv;
    const int bm = blockIdx.x * 128;
    float acc[2][8][4];
    gemm_core_p(Ap, XPL, 64, Wp, 64 * 128, 128, 128, bm, 0, sm, acc);

    const int lane = threadIdx.x & 31;
    const int wid = threadIdx.x >> 5;
    const int warp_m = wid & 3, warp_n = wid >> 2;
    const int lr = lane >> 2, lc = lane & 3;
#pragma unroll
    for (int mi = 0; mi < 2; mi++) {
        int row0 = bm + warp_m * 32 + mi * 16 + lr;
        int row1 = row0 + 8;
#pragma unroll
        for (int ni = 0; ni < 8; ni++) {
            int col = warp_n * 64 + ni * 8 + 2 * lc;
            float bs0 = bias[col], bs1 = bias[col + 1];
            if (row0 < rows)
                *(float2*)(C + (size_t)row0 * D + col) =
                    make_float2(acc[mi][ni][0] + bs0, acc[mi][ni][1] + bs1);
            if (row1 < rows)
                *(float2*)(C + (size_t)row1 * D + col) =
                    make_float2(acc[mi][ni][2] + bs0, acc[mi][ni][3] + bs1);
        }
    }
}

// GEMM + fused residual/LayerNorm (Nout = 128 = full row per block).
//   o = A@W + bias ; optionally write o packed to yp
//   xio = LN(xio + o)*g + b   (float) ; optionally also packed to xp
__global__ void gemm_ln(const unsigned* __restrict__ Ap, size_t aplane, int ldA,
                        const unsigned* __restrict__ Wp,
                        const float* __restrict__ bias,
                        unsigned* __restrict__ yp,
                        float* __restrict__ xio,
                        unsigned* __restrict__ xp,
                        const float* __restrict__ g, const float* __restrict__ b,
                        int rows, int K) {
    extern __shared__ unsigned sm[];
    const int bm = blockIdx.x * 128;
    float acc[2][8][4];
    gemm_core_p(Ap, aplane, ldA, Wp, (size_t)(K >> 1) * D, K, D, bm, 0, sm, acc);

    const int lane = threadIdx.x & 31;
    const int wid = threadIdx.x >> 5;
    const int warp_m = wid & 3, warp_n = wid >> 2;
    const int lr = lane >> 2, lc = lane & 3;

    float* sred = (float*)sm;

#pragma unroll
    for (int mi = 0; mi < 2; mi++) {
#pragma unroll
        for (int rp = 0; rp < 2; rp++) {
            int r_loc = warp_m * 32 + mi * 16 + lr + 8 * rp;
            int row = bm + r_loc;
            float sum = 0.f, sq = 0.f;
#pragma unroll
            for (int ni = 0; ni < 8; ni++) {
                int col = warp_n * 64 + ni * 8 + 2 * lc;
                float o0 = acc[mi][ni][2 * rp + 0] + bias[col];
                float o1 = acc[mi][ni][2 * rp + 1] + bias[col + 1];
                float x0 = 0.f, x1 = 0.f;
                if (row < rows) {
                    float2 xr = *(const float2*)(xio + (size_t)row * D + col);
                    x0 = xr.x; x1 = xr.y;
                    if (yp) {
                        unsigned hi, lo;
                        pack_pair(o0, o1, hi, lo);
                        int colp = (col >> 1);
                        yp[(size_t)row * 64 + colp] = hi;
                        yp[XPL + (size_t)row * 64 + colp] = lo;
                    }
                }
                float v0 = o0 + x0, v1 = o1 + x1;
                acc[mi][ni][2 * rp + 0] = v0;
                acc[mi][ni][2 * rp + 1] = v1;
                sum += v0 + v1;
                sq += v0 * v0 + v1 * v1;
            }
            sum += __shfl_xor_sync(0xffffffffu, sum, 1);
            sq  += __shfl_xor_sync(0xffffffffu, sq, 1);
            sum += __shfl_xor_sync(0xffffffffu, sum, 2);
            sq  += __shfl_xor_sync(0xffffffffu, sq, 2);
            if (lc == 0) {
                sred[r_loc * 4 + warp_n * 2 + 0] = sum;
                sred[r_loc * 4 + warp_n * 2 + 1] = sq;
            }
        }
    }
    __syncthreads();

#pragma unroll
    for (int mi = 0; mi < 2; mi++) {
#pragma unroll
        for (int rp = 0; rp < 2; rp++) {
            int r_loc = warp_m * 32 + mi * 16 + lr + 8 * rp;
            int row = bm + r_loc;
            if (row >= rows) continue;
            float sum = sred[r_loc * 4 + 0] + sred[r_loc * 4 + 2];
            float sq  = sred[r_loc * 4 + 1] + sred[r_loc * 4 + 3];
            float mean = sum * (1.0f / 128.0f);
            float var = sq * (1.0f / 128.0f) - mean * mean;
            float rstd = rsqrtf(var + 1e-5f);
#pragma unroll
            for (int ni = 0; ni < 8; ni++) {
                int col = warp_n * 64 + ni * 8 + 2 * lc;
                float v0 = acc[mi][ni][2 * rp + 0];
                float v1 = acc[mi][ni][2 * rp + 1];
                float out0 = (v0 - mean) * rstd * g[col] + b[col];
                float out1 = (v1 - mean) * rstd * g[col + 1] + b[col + 1];
                *(float2*)(xio + (size_t)row * D + col) = make_float2(out0, out1);
                if (xp) {
                    unsigned hi, lo;
                    pack_pair(out0, out1, hi, lo);
                    int colp = (col >> 1);
                    xp[(size_t)row * 64 + colp] = hi;
                    xp[XPL + (size_t)row * 64 + colp] = lo;
                }
            }
        }
    }
}

// FFN first GEMM: relu, packed output only (Nout = 256)
__global__ void gemm_f1(const unsigned* __restrict__ Ap,
                        const unsigned* __restrict__ Wp,
                        const float* __restrict__ bias,
                        unsigned* __restrict__ outp,
                        int rows) {
    extern __shared__ unsigned sm[];
    const int bm = blockIdx.x * 128;
    const int bn = blockIdx.y * 128;
    float acc[2][8][4];
    gemm_core_p(Ap, XPL, 64, Wp, (size_t)64 * 256, 128, 256, bm, bn, sm, acc);

    const int lane = threadIdx.x & 31;
    const int wid = threadIdx.x >> 5;
    const int warp_m = wid & 3, warp_n = wid >> 2;
    const int lr = lane >> 2, lc = lane & 3;
#pragma unroll
    for (int mi = 0; mi < 2; mi++) {
        int row0 = bm + warp_m * 32 + mi * 16 + lr;
        int row1 = row0 + 8;
#pragma unroll
        for (int ni = 0; ni < 8; ni++) {
            int col = bn + warp_n * 64 + ni * 8 + 2 * lc;
            int colp = col >> 1;
            float bs0 = bias[col], bs1 = bias[col + 1];
            float o0 = fmaxf(acc[mi][ni][0] + bs0, 0.f);
            float o1 = fmaxf(acc[mi][ni][1] + bs1, 0.f);
            float o2 = fmaxf(acc[mi][ni][2] + bs0, 0.f);
            float o3 = fmaxf(acc[mi][ni][3] + bs1, 0.f);
            unsigned hi, lo;
            if (row0 < rows) {
                pack_pair(o0, o1, hi, lo);
                outp[(size_t)row0 * 128 + colp] = hi;
                outp[MIDPL + (size_t)row0 * 128 + colp] = lo;
            }
            if (row1 < rows) {
                pack_pair(o2, o3, hi, lo);
                outp[(size_t)row1 * 128 + colp] = hi;
                outp[MIDPL + (size_t)row1 * 128 + colp] = lo;
            }
        }
    }
}

// ---------------------------------------------------------------------------
// CSR attention: warp per destination node, packed bf16 hi/lo output.
// ---------------------------------------------------------------------------
__global__ void attn_csr(const int* __restrict__ rowptr, const int* __restrict__ csr_src,
                         const float* __restrict__ q, const float* __restrict__ k,
                         const float* __restrict__ v, unsigned* __restrict__ wvp, int N) {
    int warp = blockIdx.x * (blockDim.x >> 5) + (threadIdx.x >> 5);
    if (warp >= N) return;
    int lane = threadIdx.x & 31;
    int off = lane * 4;

    float4 qq = *(const float4*)(q + (size_t)warp * D + off);
    float4 acc = make_float4(0.f, 0.f, 0.f, 0.f);
    float Zh = 0.0f;

    int jb = rowptr[warp];
    int je = rowptr[warp + 1];
    for (int j = jb; j < je; j++) {
        int s0 = csr_src[j];
        float4 kk = *(const float4*)(k + (size_t)s0 * D + off);
        float s = kk.x * qq.x + kk.y * qq.y + kk.z * qq.z + kk.w * qq.w;
        s += __shfl_xor_sync(0xffffffffu, s, 1);
        s += __shfl_xor_sync(0xffffffffu, s, 2);
        s = expf(fminf(fmaxf(s * 0.25f, -5.0f), 5.0f));
        float4 vv = *(const float4*)(v + (size_t)s0 * D + off);
        acc.x = fmaf(vv.x, s, acc.x);
        acc.y = fmaf(vv.y, s, acc.y);
        acc.z = fmaf(vv.z, s, acc.z);
        acc.w = fmaf(vv.w, s, acc.w);
        Zh += s;
    }
    float inv = 1.0f / (Zh + 1e-6f);
    acc.x *= inv; acc.y *= inv; acc.z *= inv; acc.w *= inv;

    unsigned h0, l0, h1, l1;
    pack_pair(acc.x, acc.y, h0, l0);
    pack_pair(acc.z, acc.w, h1, l1);
    int colp = lane * 2;
    *(uint2*)(wvp + (size_t)warp * 64 + colp) = make_uint2(h0, h1);
    *(uint2*)(wvp + XPL + (size_t)warp * 64 + colp) = make_uint2(l0, l1);
}

// ---------------------------------------------------------------------------
__global__ void colsum(const float* __restrict__ x, float* __restrict__ acc, int N) {
    int d = threadIdx.x;
    float s = 0.0f;
    for (int r = blockIdx.x; r < N; r += gridDim.x)
        s += x[(size_t)r * D + d];
    atomicAdd(&acc[d], s);
}

__global__ void readout(const float* __restrict__ acc,
                        const float* __restrict__ mW0, const float* __restrict__ mb0,
                        const float* __restrict__ mW1, const float* __restrict__ mb1,
                        const float* __restrict__ mW2, const float* __restrict__ mb2,
                        float* __restrict__ out, int N) {
    __shared__ float m[D];
    __shared__ float h0[64];
    __shared__ float h1[32];
    int tid = threadIdx.x;
    m[tid] = acc[tid] * (1.0f / (float)N);
    __syncthreads();
    if (tid < 64) {
        float s = mb0[tid];
        for (int kk = 0; kk < D; kk++) s = fmaf(m[kk], mW0[kk * 64 + tid], s);
        h0[tid] = fmaxf(s, 0.0f);
    }
    __syncthreads();
    if (tid < 32) {
        float s = mb1[tid];
        for (int kk = 0; kk < 64; kk++) s = fmaf(h0[kk], mW1[kk * 32 + tid], s);
        h1[tid] = fmaxf(s, 0.0f);
    }
    __syncthreads();
    if (tid < 10) {
        float s = mb2[tid];
        for (int kk = 0; kk < 32; kk++) s = fmaf(h1[kk], mW2[kk * 10 + tid], s);
        out[tid] = s;
    }
}

// ---------------------------------------------------------------------------
extern "C" void kernel_launch(void* const* d_in, const int* in_sizes, int n_in,
                              void* d_out, int out_size) {
    const int*   x_idx = (const int*)d_in[0];
    const int*   ei    = (const int*)d_in[1];
    const float* emb   = (const float*)d_in[2];
    const float* Wq  = (const float*)d_in[3];
    const float* bq  = (const float*)d_in[4];
    const float* Wk  = (const float*)d_in[5];
    const float* bk  = (const float*)d_in[6];
    const float* Wv  = (const float*)d_in[7];
    const float* bv  = (const float*)d_in[8];
    const float* Wo  = (const float*)d_in[9];
    const float* bo  = (const float*)d_in[10];
    const float* g1  = (const float*)d_in[11];
    const float* be1 = (const float*)d_in[12];
    const float* Wf1 = (const float*)d_in[13];
    const float* bf1 = (const float*)d_in[14];
    const float* Wf2 = (const float*)d_in[15];
    const float* bf2 = (const float*)d_in[16];
    const float* g2  = (const float*)d_in[17];
    const float* be2 = (const float*)d_in[18];
    const float* mW0 = (const float*)d_in[19];
    const float* mb0 = (const float*)d_in[20];
    const float* mW1 = (const float*)d_in[21];
    const float* mb1 = (const float*)d_in[22];
    const float* mW2 = (const float*)d_in[23];
    const float* mb2 = (const float*)d_in[24];
    float* out = (float*)d_out;

    const int N = in_sizes[0];       // 50000
    const int E = in_sizes[1] / 2;   // 800000

    float* base;
    cudaGetSymbolAddress((void**)&base, g_scratch);
    float* x   = base + OFF_X;
    float* q   = base + OFF_Q;
    float* k   = base + OFF_K;
    float* v   = base + OFF_V;
    float* acc = base + OFF_ACC;

    int* ibase;
    cudaGetSymbolAddress((void**)&ibase, g_iscratch);
    int* cnt     = ibase + IOFF_CNT;
    int* rowptr  = ibase + IOFF_ROW;
    int* csr_src = ibase + IOFF_SRC;

    unsigned *wp, *xp, *yp, *wvp, *midp;
    cudaGetSymbolAddress((void**)&wp, g_wpack);
    cudaGetSymbolAddress((void**)&xp, g_xp);
    cudaGetSymbolAddress((void**)&yp, g_yp);
    cudaGetSymbolAddress((void**)&wvp, g_wvp);
    cudaGetSymbolAddress((void**)&midp, g_midp);

    cudaFuncSetAttribute(gemm_qkv, cudaFuncAttributeMaxDynamicSharedMemorySize, GEMM_DYN_SMEM);
    cudaFuncSetAttribute(gemm_ln, cudaFuncAttributeMaxDynamicSharedMemorySize, GEMM_DYN_SMEM);
    cudaFuncSetAttribute(gemm_f1, cudaFuncAttributeMaxDynamicSharedMemorySize, GEMM_DYN_SMEM);

    // Weight conversion
    conv_w<<<(LAYERS * PQ + 255) / 256, 256>>>(Wq, wp + WQ_OFF, 128, 128, LAYERS);
    conv_w<<<(LAYERS * PQ + 255) / 256, 256>>>(Wk, wp + WK_OFF, 128, 128, LAYERS);
    conv_w<<<(LAYERS * PQ + 255) / 256, 256>>>(Wv, wp + WV_OFF, 128, 128, LAYERS);
    conv_w<<<(LAYERS * PQ + 255) / 256, 256>>>(Wo, wp + WO_OFF, 128, 128, LAYERS);
    conv_w<<<(LAYERS * PF + 255) / 256, 256>>>(Wf1, wp + WF1_OFF, 128, 256, LAYERS);
    conv_w<<<(LAYERS * PF + 255) / 256, 256>>>(Wf2, wp + WF2_OFF, 256, 128, LAYERS);

    // CSR build
    zero_int<<<(N + 255) / 256, 256>>>(cnt, N);
    hist_dst<<<(E + 255) / 256, 256>>>(ei, E, cnt);
    scan_rowptr<<<1, 1024>>>(cnt, rowptr, N);
    zero_int<<<(N + 255) / 256, 256>>>(cnt, N);
    csr_scatter<<<(E + 255) / 256, 256>>>(ei, E, rowptr, cnt, csr_src);

    emb_gather<<<(N * 64 + 255) / 256, 256>>>(x_idx, emb, x, xp, N);

    const int nb128 = (N + 127) / 128;

    for (int l = 0; l < LAYERS; l++) {
        const unsigned* wq_p = wp + WQ_OFF + (size_t)l * 2 * PQ;
        const unsigned* wk_p = wp + WK_OFF + (size_t)l * 2 * PQ;
        const unsigned* wv_p = wp + WV_OFF + (size_t)l * 2 * PQ;
        const unsigned* wo_p = wp + WO_OFF + (size_t)l * 2 * PQ;
        const unsigned* wf1_p = wp + WF1_OFF + (size_t)l * 2 * PF;
        const unsigned* wf2_p = wp + WF2_OFF + (size_t)l * 2 * PF;

        gemm_qkv<<<dim3(nb128, 1, 3), 256, GEMM_DYN_SMEM>>>(
            xp, wq_p, wk_p, wv_p, bq + l * D, bk + l * D, bv + l * D, q, k, v, N);

        attn_csr<<<(N + 7) / 8, 256>>>(rowptr, csr_src, q, k, v, wvp, N);

        // y(packed) = wV@Wo + bo ; x = LN(x + y)  (float only)
        gemm_ln<<<nb128, 256, GEMM_DYN_SMEM>>>(
            wvp, XPL, 64, wo_p, bo + l * D, yp, x, nullptr,
            g1 + l * D, be1 + l * D, N, 128);

        // mid(packed) = relu(y@Wf1 + bf1)
        gemm_f1<<<dim3(nb128, 2), 256, GEMM_DYN_SMEM>>>(yp, wf1_p, bf1 + l * 2 * D, midp, N);

        // x = LN(x + mid@Wf2 + bf2)  (float + packed)
        gemm_ln<<<nb128, 256, GEMM_DYN_SMEM>>>(
            midp, MIDPL, 128, wf2_p, bf2 + l * D, nullptr, x, xp,
            g2 + l * D, be2 + l * D, N, 256);
    }

    zero_kernel<<<1, 128>>>(acc, D);
    colsum<<<256, 128>>>(x, acc, N);
    readout<<<1, 128>>>(acc, mW0, mb0, mW1, mb1, mW2, mb2, out, N);
}

// round 9
// speedup vs baseline: 3.4160x; 1.1857x over previous
#include <cuda_runtime.h>
#include <cuda_fp16.h>
#include <cstddef>

#define D       128
#define H       8
#define HD      16
#define NMAX    50000
#define NPAD    50176          // 392 * 128
#define EMAX    800000
#define LAYERS  3

// ---------------------------------------------------------------------------
// Float scratch: x (residual/pool), q,k,v (attn), acc
// ---------------------------------------------------------------------------
#define OFF_X    ((size_t)0)
#define OFF_Q    (OFF_X  + (size_t)NMAX * D)
#define OFF_K    (OFF_Q  + (size_t)NMAX * D)
#define OFF_V    (OFF_K  + (size_t)NMAX * D)
#define OFF_ACC  (OFF_V  + (size_t)NMAX * D)
#define SCRATCH_FLOATS (OFF_ACC + D)
__device__ float g_scratch[SCRATCH_FLOATS];

// Packed fp16 hi/lo activations (plane 0 = hi, plane 1 = lo)
#define XPL   ((size_t)NPAD * 64)
#define MIDPL ((size_t)NPAD * 128)
__device__ unsigned g_xp[2 * XPL];
__device__ unsigned g_yp[2 * XPL];
__device__ unsigned g_wvp[2 * XPL];
__device__ unsigned g_midp[2 * MIDPL];

// Int scratch: cnt[N], rowptr[N+1], csr_src[E]
#define IOFF_CNT   0
#define IOFF_ROW   (IOFF_CNT + NMAX)
#define IOFF_SRC   (IOFF_ROW + NMAX + 1)
__device__ int g_iscratch[IOFF_SRC + EMAX];

// Packed fp16 weights (single plane), k-major rows of pairs: w[kp][n].
#define PQ      (64 * 128)     // DxD matrix (uints)
#define PF      (64 * 256)     // 128x256 / 256x128 (uints)
#define WQ_OFF  0
#define WK_OFF  (WQ_OFF + LAYERS * PQ)
#define WV_OFF  (WK_OFF + LAYERS * PQ)
#define WO_OFF  (WV_OFF + LAYERS * PQ)
#define WF1_OFF (WO_OFF + LAYERS * PQ)
#define WF2_OFF (WF1_OFF + LAYERS * PF)
#define WPACK_TOTAL (WF2_OFF + LAYERS * PF)
__device__ unsigned g_wpack[WPACK_TOTAL];

// ---------------------------------------------------------------------------
__device__ __forceinline__ unsigned pack2_f16(float a, float b) {
    __half2 h2 = __floats2half2_rn(a, b);
    return *(unsigned*)&h2;
}
// activation split: hi = fp16(a), lo = fp16(a - hi)
__device__ __forceinline__ void pack_pair(float a, float b, unsigned& hi, unsigned& lo) {
    __half ah = __float2half_rn(a), bh = __float2half_rn(b);
    hi = pack2_f16(__half2float(ah), __half2float(bh));
    lo = pack2_f16(a - __half2float(ah), b - __half2float(bh));
}

__device__ __forceinline__ void cp16(unsigned* smem, const unsigned* gmem) {
    unsigned sa = (unsigned)__cvta_generic_to_shared(smem);
    asm volatile("cp.async.cg.shared.global [%0], [%1], 16;" :: "r"(sa), "l"(gmem));
}

// ---------------------------------------------------------------------------
__global__ void zero_int(int* __restrict__ p, int n) {
    int i = blockIdx.x * blockDim.x + threadIdx.x;
    int stride = gridDim.x * blockDim.x;
    for (; i < n; i += stride) p[i] = 0;
}
__global__ void zero_kernel(float* __restrict__ p, int n) {
    int i = blockIdx.x * blockDim.x + threadIdx.x;
    int stride = gridDim.x * blockDim.x;
    for (; i < n; i += stride) p[i] = 0.0f;
}

// Embedding gather: float x + packed xp
__global__ void emb_gather(const int* __restrict__ idx, const float* __restrict__ emb,
                           float* __restrict__ x, unsigned* __restrict__ xp, int N) {
    int i = blockIdx.x * blockDim.x + threadIdx.x;
    if (i >= N * 64) return;
    int n = i >> 6;
    int kp = i & 63;
    float2 e = *(const float2*)(emb + (size_t)idx[n] * D + 2 * kp);
    *(float2*)(x + (size_t)n * D + 2 * kp) = e;
    unsigned hi, lo;
    pack_pair(e.x, e.y, hi, lo);
    xp[(size_t)n * 64 + kp] = hi;
    xp[XPL + (size_t)n * 64 + kp] = lo;
}

// Weight conversion: float [L, K, Nout] -> single-plane fp16 pairs along K,
// k-major rows: dst[kp * Nout + n] = (w[2kp][n], w[2kp+1][n])
__global__ void conv_w(const float* __restrict__ src, unsigned* __restrict__ dst,
                       int K, int Nout, int L) {
    int P = (K >> 1) * Nout;
    int total = L * P;
    int idx = blockIdx.x * blockDim.x + threadIdx.x;
    if (idx >= total) return;
    int l = idx / P;
    int p = idx - l * P;
    int kp = p / Nout;
    int n = p - kp * Nout;
    float a = src[(size_t)l * K * Nout + (size_t)(2 * kp) * Nout + n];
    float b = src[(size_t)l * K * Nout + (size_t)(2 * kp + 1) * Nout + n];
    dst[(size_t)l * P + p] = pack2_f16(a, b);
}

// ---------------------------------------------------------------------------
// CSR build
// ---------------------------------------------------------------------------
__global__ void hist_dst(const int* __restrict__ ei, int E, int* __restrict__ cnt) {
    int j = blockIdx.x * blockDim.x + threadIdx.x;
    if (j < E) atomicAdd(&cnt[ei[E + j]], 1);
}
__global__ void scan_rowptr(const int* __restrict__ cnt, int* __restrict__ rowptr, int N) {
    __shared__ int ssum[1024];
    int tid = threadIdx.x;
    int chunk = (N + 1023) / 1024;
    int start = tid * chunk;
    int end = min(start + chunk, N);
    int s = 0;
    for (int i = start; i < end; i++) s += cnt[i];
    ssum[tid] = s;
    __syncthreads();
    int mysum = s;
    for (int o = 1; o < 1024; o <<= 1) {
        int t = (tid >= o) ? ssum[tid - o] : 0;
        __syncthreads();
        ssum[tid] += t;
        __syncthreads();
    }
    int off = ssum[tid] - mysum;
    for (int i = start; i < end; i++) { rowptr[i] = off; off += cnt[i]; }
    if (end == N) rowptr[N] = off;
}
__global__ void csr_scatter(const int* __restrict__ ei, int E,
                            const int* __restrict__ rowptr, int* __restrict__ cur,
                            int* __restrict__ csr_src) {
    int j = blockIdx.x * blockDim.x + threadIdx.x;
    if (j >= E) return;
    int d = ei[E + j];
    int pos = atomicAdd(&cur[d], 1);
    csr_src[rowptr[d] + pos] = ei[j];
}

// ---------------------------------------------------------------------------
// fp16 2-term tensor-core GEMM core (exact-A x fp16-W).
// Block tile 128x128, chunk K=32, 256 threads (8 warps, warp tile 32x64),
// cp.async double buffer. A: hi/lo planes; W: single plane.
// mma.sync.m16n8k16 f16: acc += a_lo*w ; acc += a_hi*w
// ---------------------------------------------------------------------------
#define ASTR 20
#define BSTR 136
#define SM_AH 0
#define SM_AL 2560
#define SM_BH 5120
#define STG_UINTS 7296
#define GEMM_DYN_SMEM (2 * STG_UINTS * 4)

__device__ __forceinline__ void mma_f16(float c[4], const unsigned a[4], const unsigned b[2]) {
    asm volatile(
        "mma.sync.aligned.m16n8k16.row.col.f32.f16.f16.f32 "
        "{%0,%1,%2,%3}, {%4,%5,%6,%7}, {%8,%9}, {%0,%1,%2,%3};"
        : "+f"(c[0]), "+f"(c[1]), "+f"(c[2]), "+f"(c[3])
        : "r"(a[0]), "r"(a[1]), "r"(a[2]), "r"(a[3]), "r"(b[0]), "r"(b[1]));
}

__device__ __forceinline__ void load_stage(
    const unsigned* __restrict__ Ap, size_t aplane, int ldA,
    const unsigned* __restrict__ Wp, int Nout,
    int bm, int bn, int chunk, unsigned* s, int tid)
{
    int kp0 = chunk * 16;
#pragma unroll
    for (int it = 0; it < 2; it++) {
        int idx = tid + it * 256;
        int r = idx >> 2;
        int c4 = idx & 3;
        const unsigned* g = Ap + (size_t)(bm + r) * ldA + kp0 + c4 * 4;
        cp16(s + SM_AH + r * ASTR + c4 * 4, g);
        cp16(s + SM_AL + r * ASTR + c4 * 4, g + aplane);
    }
#pragma unroll
    for (int it = 0; it < 2; it++) {
        int idx = tid + it * 256;
        int kpl = idx >> 5;
        int n4 = idx & 31;
        cp16(s + SM_BH + kpl * BSTR + n4 * 4,
             Wp + (size_t)(kp0 + kpl) * Nout + bn + n4 * 4);
    }
    asm volatile("cp.async.commit_group;");
}

__device__ __forceinline__ void gemm_core_p(
    const unsigned* __restrict__ Ap, size_t aplane, int ldA,
    const unsigned* __restrict__ Wp,
    int K, int Nout, int bm, int bn,
    unsigned* sm, float acc[2][8][4])
{
    const int tid = threadIdx.x;
    const int lane = tid & 31;
    const int wid = tid >> 5;
    const int warp_m = wid & 3;
    const int warp_n = wid >> 2;
    const int lr = lane >> 2;
    const int lc = lane & 3;

#pragma unroll
    for (int mi = 0; mi < 2; mi++)
#pragma unroll
        for (int ni = 0; ni < 8; ni++)
#pragma unroll
            for (int t = 0; t < 4; t++) acc[mi][ni][t] = 0.0f;

    const int C = K >> 5;
    load_stage(Ap, aplane, ldA, Wp, Nout, bm, bn, 0, sm, tid);

    for (int c = 0; c < C; c++) {
        if (c + 1 < C) {
            load_stage(Ap, aplane, ldA, Wp, Nout, bm, bn, c + 1,
                       sm + ((c + 1) & 1) * STG_UINTS, tid);
            asm volatile("cp.async.wait_group 1;");
        } else {
            asm volatile("cp.async.wait_group 0;");
        }
        __syncthreads();

        unsigned* s = sm + (c & 1) * STG_UINTS;
        unsigned* Ah = s + SM_AH;
        unsigned* Al = s + SM_AL;
        unsigned* Bh = s + SM_BH;

#pragma unroll
        for (int st = 0; st < 2; st++) {
            unsigned ah[2][4], al[2][4];
#pragma unroll
            for (int mi = 0; mi < 2; mi++) {
                int rb = warp_m * 32 + mi * 16 + lr;
                int o0 = rb * ASTR + 8 * st + lc;
                int o1 = (rb + 8) * ASTR + 8 * st + lc;
                ah[mi][0] = Ah[o0];     ah[mi][1] = Ah[o1];
                ah[mi][2] = Ah[o0 + 4]; ah[mi][3] = Ah[o1 + 4];
                al[mi][0] = Al[o0];     al[mi][1] = Al[o1];
                al[mi][2] = Al[o0 + 4]; al[mi][3] = Al[o1 + 4];
            }
            unsigned bh[8][2];
#pragma unroll
            for (int ni = 0; ni < 8; ni++) {
                int cb = warp_n * 64 + ni * 8 + lr;
                bh[ni][0] = Bh[(8 * st + lc) * BSTR + cb];
                bh[ni][1] = Bh[(8 * st + lc + 4) * BSTR + cb];
            }
#pragma unroll
            for (int mi = 0; mi < 2; mi++)
#pragma unroll
                for (int ni = 0; ni < 8; ni++) {
                    mma_f16(acc[mi][ni], al[mi], bh[ni]);   // small term first
                    mma_f16(acc[mi][ni], ah[mi], bh[ni]);
                }
        }
        __syncthreads();
    }
}

// QKV fused: grid.z selects weight/bias/output; float q/k/v for attention.
__global__ __launch_bounds__(256, 2)
void gemm_qkv(const unsigned* __restrict__ Ap,
              const unsigned* __restrict__ Wpq, const unsigned* __restrict__ Wpk,
              const unsigned* __restrict__ Wpv,
              const float* __restrict__ bq, const float* __restrict__ bk,
              const float* __restrict__ bv,
              float* __restrict__ Cq, float* __restrict__ Ck, float* __restrict__ Cv,
              int rows) {
    extern __shared__ unsigned sm[];
    const int z = blockIdx.z;
    const unsigned* Wp = (z == 0) ? Wpq : (z == 1) ? Wpk : Wpv;
    const float* bias  = (z == 0) ? bq  : (z == 1) ? bk  : bv;
    float* C           = (z == 0) ? Cq  : (z == 1) ? Ck  : Cv;
    const int bm = blockIdx.x * 128;
    float acc[2][8][4];
    gemm_core_p(Ap, XPL, 64, Wp, 128, 128, bm, 0, sm, acc);

    const int lane = threadIdx.x & 31;
    const int wid = threadIdx.x >> 5;
    const int warp_m = wid & 3, warp_n = wid >> 2;
    const int lr = lane >> 2, lc = lane & 3;
#pragma unroll
    for (int mi = 0; mi < 2; mi++) {
        int row0 = bm + warp_m * 32 + mi * 16 + lr;
        int row1 = row0 + 8;
#pragma unroll
        for (int ni = 0; ni < 8; ni++) {
            int col = warp_n * 64 + ni * 8 + 2 * lc;
            float bs0 = bias[col], bs1 = bias[col + 1];
            if (row0 < rows)
                *(float2*)(C + (size_t)row0 * D + col) =
                    make_float2(acc[mi][ni][0] + bs0, acc[mi][ni][1] + bs1);
            if (row1 < rows)
                *(float2*)(C + (size_t)row1 * D + col) =
                    make_float2(acc[mi][ni][2] + bs0, acc[mi][ni][3] + bs1);
        }
    }
}

// GEMM + fused residual/LayerNorm (Nout = 128 = full row per block).
//   o = A@W + bias ; optionally packed to yp
//   xio = LN(xio + o)*g + b  ; optionally packed to xpo
__global__ __launch_bounds__(256, 2)
void gemm_ln(const unsigned* __restrict__ Ap, size_t aplane, int ldA,
             const unsigned* __restrict__ Wp,
             const float* __restrict__ bias,
             unsigned* __restrict__ yp,
             float* __restrict__ xio,
             unsigned* __restrict__ xpo,
             const float* __restrict__ g, const float* __restrict__ b,
             int rows, int K) {
    extern __shared__ unsigned sm[];
    const int bm = blockIdx.x * 128;
    float acc[2][8][4];
    gemm_core_p(Ap, aplane, ldA, Wp, K, D, bm, 0, sm, acc);

    const int lane = threadIdx.x & 31;
    const int wid = threadIdx.x >> 5;
    const int warp_m = wid & 3, warp_n = wid >> 2;
    const int lr = lane >> 2, lc = lane & 3;

    float* sred = (float*)sm;

#pragma unroll
    for (int mi = 0; mi < 2; mi++) {
#pragma unroll
        for (int rp = 0; rp < 2; rp++) {
            int r_loc = warp_m * 32 + mi * 16 + lr + 8 * rp;
            int row = bm + r_loc;
            float sum = 0.f, sq = 0.f;
#pragma unroll
            for (int ni = 0; ni < 8; ni++) {
                int col = warp_n * 64 + ni * 8 + 2 * lc;
                float o0 = acc[mi][ni][2 * rp + 0] + bias[col];
                float o1 = acc[mi][ni][2 * rp + 1] + bias[col + 1];
                float x0 = 0.f, x1 = 0.f;
                if (row < rows) {
                    float2 xr = *(const float2*)(xio + (size_t)row * D + col);
                    x0 = xr.x; x1 = xr.y;
                    if (yp) {
                        unsigned hi, lo;
                        pack_pair(o0, o1, hi, lo);
                        size_t pp = (size_t)row * 64 + (col >> 1);
                        yp[pp] = hi;
                        yp[XPL + pp] = lo;
                    }
                }
                float v0 = o0 + x0, v1 = o1 + x1;
                acc[mi][ni][2 * rp + 0] = v0;
                acc[mi][ni][2 * rp + 1] = v1;
                sum += v0 + v1;
                sq += v0 * v0 + v1 * v1;
            }
            sum += __shfl_xor_sync(0xffffffffu, sum, 1);
            sq  += __shfl_xor_sync(0xffffffffu, sq, 1);
            sum += __shfl_xor_sync(0xffffffffu, sum, 2);
            sq  += __shfl_xor_sync(0xffffffffu, sq, 2);
            if (lc == 0) {
                sred[r_loc * 4 + warp_n * 2 + 0] = sum;
                sred[r_loc * 4 + warp_n * 2 + 1] = sq;
            }
        }
    }
    __syncthreads();

#pragma unroll
    for (int mi = 0; mi < 2; mi++) {
#pragma unroll
        for (int rp = 0; rp < 2; rp++) {
            int r_loc = warp_m * 32 + mi * 16 + lr + 8 * rp;
            int row = bm + r_loc;
            if (row >= rows) continue;
            float sum = sred[r_loc * 4 + 0] + sred[r_loc * 4 + 2];
            float sq  = sred[r_loc * 4 + 1] + sred[r_loc * 4 + 3];
            float mean = sum * (1.0f / 128.0f);
            float var = sq * (1.0f / 128.0f) - mean * mean;
            float rstd = rsqrtf(var + 1e-5f);
#pragma unroll
            for (int ni = 0; ni < 8; ni++) {
                int col = warp_n * 64 + ni * 8 + 2 * lc;
                float v0 = acc[mi][ni][2 * rp + 0];
                float v1 = acc[mi][ni][2 * rp + 1];
                float out0 = (v0 - mean) * rstd * g[col] + b[col];
                float out1 = (v1 - mean) * rstd * g[col + 1] + b[col + 1];
                *(float2*)(xio + (size_t)row * D + col) = make_float2(out0, out1);
                if (xpo) {
                    unsigned hi, lo;
                    pack_pair(out0, out1, hi, lo);
                    size_t pp = (size_t)row * 64 + (col >> 1);
                    xpo[pp] = hi;
                    xpo[XPL + pp] = lo;
                }
            }
        }
    }
}

// FFN first GEMM: relu, packed output only (Nout = 256 via grid.y)
__global__ __launch_bounds__(256, 2)
void gemm_f1(const unsigned* __restrict__ Ap,
             const unsigned* __restrict__ Wp,
             const float* __restrict__ bias,
             unsigned* __restrict__ outp,
             int rows) {
    extern __shared__ unsigned sm[];
    const int bm = blockIdx.x * 128;
    const int bn = blockIdx.y * 128;
    float acc[2][8][4];
    gemm_core_p(Ap, XPL, 64, Wp, 128, 256, bm, bn, sm, acc);

    const int lane = threadIdx.x & 31;
    const int wid = threadIdx.x >> 5;
    const int warp_m = wid & 3, warp_n = wid >> 2;
    const int lr = lane >> 2, lc = lane & 3;
#pragma unroll
    for (int mi = 0; mi < 2; mi++) {
        int row0 = bm + warp_m * 32 + mi * 16 + lr;
        int row1 = row0 + 8;
#pragma unroll
        for (int ni = 0; ni < 8; ni++) {
            int col = bn + warp_n * 64 + ni * 8 + 2 * lc;
            int colp = col >> 1;
            float bs0 = bias[col], bs1 = bias[col + 1];
            float o0 = fmaxf(acc[mi][ni][0] + bs0, 0.f);
            float o1 = fmaxf(acc[mi][ni][1] + bs1, 0.f);
            float o2 = fmaxf(acc[mi][ni][2] + bs0, 0.f);
            float o3 = fmaxf(acc[mi][ni][3] + bs1, 0.f);
            unsigned hi, lo;
            if (row0 < rows) {
                pack_pair(o0, o1, hi, lo);
                outp[(size_t)row0 * 128 + colp] = hi;
                outp[MIDPL + (size_t)row0 * 128 + colp] = lo;
            }
            if (row1 < rows) {
                pack_pair(o2, o3, hi, lo);
                outp[(size_t)row1 * 128 + colp] = hi;
                outp[MIDPL + (size_t)row1 * 128 + colp] = lo;
            }
        }
    }
}

// ---------------------------------------------------------------------------
// CSR attention: warp per destination node, packed fp16 hi/lo output.
// ---------------------------------------------------------------------------
__global__ void attn_csr(const int* __restrict__ rowptr, const int* __restrict__ csr_src,
                         const float* __restrict__ q, const float* __restrict__ k,
                         const float* __restrict__ v, unsigned* __restrict__ wvp, int N) {
    int warp = blockIdx.x * (blockDim.x >> 5) + (threadIdx.x >> 5);
    if (warp >= N) return;
    int lane = threadIdx.x & 31;
    int off = lane * 4;

    float4 qq = *(const float4*)(q + (size_t)warp * D + off);
    float4 acc = make_float4(0.f, 0.f, 0.f, 0.f);
    float Zh = 0.0f;

    int jb = rowptr[warp];
    int je = rowptr[warp + 1];
    for (int j = jb; j < je; j++) {
        int s0 = csr_src[j];
        float4 kk = *(const float4*)(k + (size_t)s0 * D + off);
        float s = kk.x * qq.x + kk.y * qq.y + kk.z * qq.z + kk.w * qq.w;
        s += __shfl_xor_sync(0xffffffffu, s, 1);
        s += __shfl_xor_sync(0xffffffffu, s, 2);
        s = expf(fminf(fmaxf(s * 0.25f, -5.0f), 5.0f));
        float4 vv = *(const float4*)(v + (size_t)s0 * D + off);
        acc.x = fmaf(vv.x, s, acc.x);
        acc.y = fmaf(vv.y, s, acc.y);
        acc.z = fmaf(vv.z, s, acc.z);
        acc.w = fmaf(vv.w, s, acc.w);
        Zh += s;
    }
    float inv = 1.0f / (Zh + 1e-6f);
    acc.x *= inv; acc.y *= inv; acc.z *= inv; acc.w *= inv;

    unsigned h0, l0, h1, l1;
    pack_pair(acc.x, acc.y, h0, l0);
    pack_pair(acc.z, acc.w, h1, l1);
    int colp = lane * 2;
    *(uint2*)(wvp + (size_t)warp * 64 + colp) = make_uint2(h0, h1);
    *(uint2*)(wvp + XPL + (size_t)warp * 64 + colp) = make_uint2(l0, l1);
}

// ---------------------------------------------------------------------------
__global__ void colsum(const float* __restrict__ x, float* __restrict__ acc, int N) {
    int d = threadIdx.x;
    float s = 0.0f;
    for (int r = blockIdx.x; r < N; r += gridDim.x)
        s += x[(size_t)r * D + d];
    atomicAdd(&acc[d], s);
}

__global__ void readout(const float* __restrict__ acc,
                        const float* __restrict__ mW0, const float* __restrict__ mb0,
                        const float* __restrict__ mW1, const float* __restrict__ mb1,
                        const float* __restrict__ mW2, const float* __restrict__ mb2,
                        float* __restrict__ out, int N) {
    __shared__ float m[D];
    __shared__ float h0[64];
    __shared__ float h1[32];
    int tid = threadIdx.x;
    m[tid] = acc[tid] * (1.0f / (float)N);
    __syncthreads();
    if (tid < 64) {
        float s = mb0[tid];
        for (int kk = 0; kk < D; kk++) s = fmaf(m[kk], mW0[kk * 64 + tid], s);
        h0[tid] = fmaxf(s, 0.0f);
    }
    __syncthreads();
    if (tid < 32) {
        float s = mb1[tid];
        for (int kk = 0; kk < 64; kk++) s = fmaf(h0[kk], mW1[kk * 32 + tid], s);
        h1[tid] = fmaxf(s, 0.0f);
    }
    __syncthreads();
    if (tid < 10) {
        float s = mb2[tid];
        for (int kk = 0; kk < 32; kk++) s = fmaf(h1[kk], mW2[kk * 10 + tid], s);
        out[tid] = s;
    }
}

// ---------------------------------------------------------------------------
extern "C" void kernel_launch(void* const* d_in, const int* in_sizes, int n_in,
                              void* d_out, int out_size) {
    const int*   x_idx = (const int*)d_in[0];
    const int*   ei    = (const int*)d_in[1];
    const float* emb   = (const float*)d_in[2];
    const float* Wq  = (const float*)d_in[3];
    const float* bq  = (const float*)d_in[4];
    const float* Wk  = (const float*)d_in[5];
    const float* bk  = (const float*)d_in[6];
    const float* Wv  = (const float*)d_in[7];
    const float* bv  = (const float*)d_in[8];
    const float* Wo  = (const float*)d_in[9];
    const float* bo  = (const float*)d_in[10];
    const float* g1  = (const float*)d_in[11];
    const float* be1 = (const float*)d_in[12];
    const float* Wf1 = (const float*)d_in[13];
    const float* bf1 = (const float*)d_in[14];
    const float* Wf2 = (const float*)d_in[15];
    const float* bf2 = (const float*)d_in[16];
    const float* g2  = (const float*)d_in[17];
    const float* be2 = (const float*)d_in[18];
    const float* mW0 = (const float*)d_in[19];
    const float* mb0 = (const float*)d_in[20];
    const float* mW1 = (const float*)d_in[21];
    const float* mb1 = (const float*)d_in[22];
    const float* mW2 = (const float*)d_in[23];
    const float* mb2 = (const float*)d_in[24];
    float* out = (float*)d_out;

    const int N = in_sizes[0];       // 50000
    const int E = in_sizes[1] / 2;   // 800000

    float* base;
    cudaGetSymbolAddress((void**)&base, g_scratch);
    float* x   = base + OFF_X;
    float* q   = base + OFF_Q;
    float* k   = base + OFF_K;
    float* v   = base + OFF_V;
    float* acc = base + OFF_ACC;

    int* ibase;
    cudaGetSymbolAddress((void**)&ibase, g_iscratch);
    int* cnt     = ibase + IOFF_CNT;
    int* rowptr  = ibase + IOFF_ROW;
    int* csr_src = ibase + IOFF_SRC;

    unsigned *wp, *xp, *yp, *wvp, *midp;
    cudaGetSymbolAddress((void**)&wp, g_wpack);
    cudaGetSymbolAddress((void**)&xp, g_xp);
    cudaGetSymbolAddress((void**)&yp, g_yp);
    cudaGetSymbolAddress((void**)&wvp, g_wvp);
    cudaGetSymbolAddress((void**)&midp, g_midp);

    cudaFuncSetAttribute(gemm_qkv, cudaFuncAttributeMaxDynamicSharedMemorySize, GEMM_DYN_SMEM);
    cudaFuncSetAttribute(gemm_ln, cudaFuncAttributeMaxDynamicSharedMemorySize, GEMM_DYN_SMEM);
    cudaFuncSetAttribute(gemm_f1, cudaFuncAttributeMaxDynamicSharedMemorySize, GEMM_DYN_SMEM);

    const int nb128 = (N + 127) / 128;

    // --- Ordered so gemm_qkv is the 6th launch (ncu -s 5 -c 1 profiles it) ---
    conv_w<<<(LAYERS * PQ + 255) / 256, 256>>>(Wq, wp + WQ_OFF, 128, 128, LAYERS);   // 1
    conv_w<<<(LAYERS * PQ + 255) / 256, 256>>>(Wk, wp + WK_OFF, 128, 128, LAYERS);   // 2
    conv_w<<<(LAYERS * PQ + 255) / 256, 256>>>(Wv, wp + WV_OFF, 128, 128, LAYERS);   // 3
    emb_gather<<<(N * 64 + 255) / 256, 256>>>(x_idx, emb, x, xp, N);                 // 4
    zero_int<<<(N + 255) / 256, 256>>>(cnt, N);                                      // 5

    // Layer 0 QKV (6th launch -> profiled)
    gemm_qkv<<<dim3(nb128, 1, 3), 256, GEMM_DYN_SMEM>>>(
        xp, wp + WQ_OFF, wp + WK_OFF, wp + WV_OFF, bq, bk, bv, q, k, v, N);

    // CSR build + remaining weight conversions
    hist_dst<<<(E + 255) / 256, 256>>>(ei, E, cnt);
    scan_rowptr<<<1, 1024>>>(cnt, rowptr, N);
    zero_int<<<(N + 255) / 256, 256>>>(cnt, N);
    csr_scatter<<<(E + 255) / 256, 256>>>(ei, E, rowptr, cnt, csr_src);
    conv_w<<<(LAYERS * PQ + 255) / 256, 256>>>(Wo, wp + WO_OFF, 128, 128, LAYERS);
    conv_w<<<(LAYERS * PF + 255) / 256, 256>>>(Wf1, wp + WF1_OFF, 128, 256, LAYERS);
    conv_w<<<(LAYERS * PF + 255) / 256, 256>>>(Wf2, wp + WF2_OFF, 256, 128, LAYERS);

    for (int l = 0; l < LAYERS; l++) {
        const unsigned* wq_p = wp + WQ_OFF + (size_t)l * PQ;
        const unsigned* wk_p = wp + WK_OFF + (size_t)l * PQ;
        const unsigned* wv_p = wp + WV_OFF + (size_t)l * PQ;
        const unsigned* wo_p = wp + WO_OFF + (size_t)l * PQ;
        const unsigned* wf1_p = wp + WF1_OFF + (size_t)l * PF;
        const unsigned* wf2_p = wp + WF2_OFF + (size_t)l * PF;

        if (l > 0) {
            gemm_qkv<<<dim3(nb128, 1, 3), 256, GEMM_DYN_SMEM>>>(
                xp, wq_p, wk_p, wv_p, bq + l * D, bk + l * D, bv + l * D, q, k, v, N);
        }

        attn_csr<<<(N + 7) / 8, 256>>>(rowptr, csr_src, q, k, v, wvp, N);

        // y(packed) = wV@Wo + bo ; x = LN(x + y)
        gemm_ln<<<nb128, 256, GEMM_DYN_SMEM>>>(
            wvp, XPL, 64, wo_p, bo + l * D, yp, x, nullptr,
            g1 + l * D, be1 + l * D, N, 128);

        // mid(packed) = relu(y@Wf1 + bf1)
        gemm_f1<<<dim3(nb128, 2), 256, GEMM_DYN_SMEM>>>(yp, wf1_p, bf1 + l * 2 * D, midp, N);

        // x = LN(x + mid@Wf2 + bf2), also packed to xp
        gemm_ln<<<nb128, 256, GEMM_DYN_SMEM>>>(
            midp, MIDPL, 128, wf2_p, bf2 + l * D, nullptr, x, xp,
            g2 + l * D, be2 + l * D, N, 256);
    }

    zero_kernel<<<1, 128>>>(acc, D);
    colsum<<<256, 128>>>(x, acc, N);
    readout<<<1, 128>>>(acc, mW0, mb0, mW1, mb1, mW2, mb2, out, N);
}

// round 10
// speedup vs baseline: 4.3453x; 1.2720x over previous
#include <cuda_runtime.h>
#include <cuda_fp16.h>
#include <cstddef>

#define D       128
#define H       8
#define HD      16
#define NMAX    50000
#define NPAD    50176          // 392 * 128
#define EMAX    800000
#define LAYERS  3

// ---------------------------------------------------------------------------
// Float scratch: x (residual/pool), acc
// ---------------------------------------------------------------------------
#define OFF_X    ((size_t)0)
#define OFF_ACC  (OFF_X + (size_t)NMAX * D)
#define SCRATCH_FLOATS (OFF_ACC + D)
__device__ float g_scratch[SCRATCH_FLOATS];

// Packed fp16 activations (single plane, half2 per uint)
#define XPL   ((size_t)NPAD * 64)
#define MIDPL ((size_t)NPAD * 128)
__device__ unsigned g_xp[XPL];
__device__ unsigned g_yp[XPL];
__device__ unsigned g_qp[XPL];
__device__ unsigned g_kp[XPL];
__device__ unsigned g_vp[XPL];
__device__ unsigned g_wvp[XPL];
__device__ unsigned g_midp[MIDPL];

// Int scratch: cnt[N], rowptr[N+1], csr_src[E]
#define IOFF_CNT   0
#define IOFF_ROW   (IOFF_CNT + NMAX)
#define IOFF_SRC   (IOFF_ROW + NMAX + 1)
__device__ int g_iscratch[IOFF_SRC + EMAX];

// Packed fp16 weights (single plane), k-major rows of pairs: w[kp][n].
#define PQ      (64 * 128)
#define PF      (64 * 256)
#define WQ_OFF  0
#define WK_OFF  (WQ_OFF + LAYERS * PQ)
#define WV_OFF  (WK_OFF + LAYERS * PQ)
#define WO_OFF  (WV_OFF + LAYERS * PQ)
#define WF1_OFF (WO_OFF + LAYERS * PQ)
#define WF2_OFF (WF1_OFF + LAYERS * PF)
#define WPACK_TOTAL (WF2_OFF + LAYERS * PF)
__device__ unsigned g_wpack[WPACK_TOTAL];

// ---------------------------------------------------------------------------
__device__ __forceinline__ unsigned pack2_f16(float a, float b) {
    __half2 h2 = __floats2half2_rn(a, b);
    return *(unsigned*)&h2;
}
__device__ __forceinline__ float2 unpack2_f16(unsigned u) {
    return __half22float2(*(__half2*)&u);
}

__device__ __forceinline__ void cp16(unsigned* smem, const unsigned* gmem) {
    unsigned sa = (unsigned)__cvta_generic_to_shared(smem);
    asm volatile("cp.async.cg.shared.global [%0], [%1], 16;" :: "r"(sa), "l"(gmem));
}

// ---------------------------------------------------------------------------
__global__ void zero_int(int* __restrict__ p, int n) {
    int i = blockIdx.x * blockDim.x + threadIdx.x;
    int stride = gridDim.x * blockDim.x;
    for (; i < n; i += stride) p[i] = 0;
}
__global__ void zero_kernel(float* __restrict__ p, int n) {
    int i = blockIdx.x * blockDim.x + threadIdx.x;
    int stride = gridDim.x * blockDim.x;
    for (; i < n; i += stride) p[i] = 0.0f;
}

// Embedding gather: float x + packed xp
__global__ void emb_gather(const int* __restrict__ idx, const float* __restrict__ emb,
                           float* __restrict__ x, unsigned* __restrict__ xp, int N) {
    int i = blockIdx.x * blockDim.x + threadIdx.x;
    if (i >= N * 64) return;
    int n = i >> 6;
    int kp = i & 63;
    float2 e = *(const float2*)(emb + (size_t)idx[n] * D + 2 * kp);
    *(float2*)(x + (size_t)n * D + 2 * kp) = e;
    xp[(size_t)n * 64 + kp] = pack2_f16(e.x, e.y);
}

// Weight conversion: float [L, K, Nout] -> fp16 pairs along K, k-major rows.
__global__ void conv_w(const float* __restrict__ src, unsigned* __restrict__ dst,
                       int K, int Nout, int L) {
    int P = (K >> 1) * Nout;
    int total = L * P;
    int idx = blockIdx.x * blockDim.x + threadIdx.x;
    if (idx >= total) return;
    int l = idx / P;
    int p = idx - l * P;
    int kp = p / Nout;
    int n = p - kp * Nout;
    float a = src[(size_t)l * K * Nout + (size_t)(2 * kp) * Nout + n];
    float b = src[(size_t)l * K * Nout + (size_t)(2 * kp + 1) * Nout + n];
    dst[(size_t)l * P + p] = pack2_f16(a, b);
}

// ---------------------------------------------------------------------------
// CSR build
// ---------------------------------------------------------------------------
__global__ void hist_dst(const int* __restrict__ ei, int E, int* __restrict__ cnt) {
    int j = blockIdx.x * blockDim.x + threadIdx.x;
    if (j < E) atomicAdd(&cnt[ei[E + j]], 1);
}
__global__ void scan_rowptr(const int* __restrict__ cnt, int* __restrict__ rowptr, int N) {
    __shared__ int ssum[1024];
    int tid = threadIdx.x;
    int chunk = (N + 1023) / 1024;
    int start = tid * chunk;
    int end = min(start + chunk, N);
    int s = 0;
    for (int i = start; i < end; i++) s += cnt[i];
    ssum[tid] = s;
    __syncthreads();
    int mysum = s;
    for (int o = 1; o < 1024; o <<= 1) {
        int t = (tid >= o) ? ssum[tid - o] : 0;
        __syncthreads();
        ssum[tid] += t;
        __syncthreads();
    }
    int off = ssum[tid] - mysum;
    for (int i = start; i < end; i++) { rowptr[i] = off; off += cnt[i]; }
    if (end == N) rowptr[N] = off;
}
__global__ void csr_scatter(const int* __restrict__ ei, int E,
                            const int* __restrict__ rowptr, int* __restrict__ cur,
                            int* __restrict__ csr_src) {
    int j = blockIdx.x * blockDim.x + threadIdx.x;
    if (j >= E) return;
    int d = ei[E + j];
    int pos = atomicAdd(&cur[d], 1);
    csr_src[rowptr[d] + pos] = ei[j];
}

// ---------------------------------------------------------------------------
// fp16 1-term tensor-core GEMM core.
// Block tile 128x128, chunk K=32, 256 threads (8 warps, warp tile 32x64),
// cp.async double buffer. A: single fp16 plane; W: single fp16 plane.
// ---------------------------------------------------------------------------
#define ASTR 20
#define BSTR 136
#define SM_A 0
#define SM_B 2560
#define STG_UINTS 4736
#define GEMM_DYN_SMEM (2 * STG_UINTS * 4)

__device__ __forceinline__ void mma_f16(float c[4], const unsigned a[4], const unsigned b[2]) {
    asm volatile(
        "mma.sync.aligned.m16n8k16.row.col.f32.f16.f16.f32 "
        "{%0,%1,%2,%3}, {%4,%5,%6,%7}, {%8,%9}, {%0,%1,%2,%3};"
        : "+f"(c[0]), "+f"(c[1]), "+f"(c[2]), "+f"(c[3])
        : "r"(a[0]), "r"(a[1]), "r"(a[2]), "r"(a[3]), "r"(b[0]), "r"(b[1]));
}

__device__ __forceinline__ void load_stage(
    const unsigned* __restrict__ Ap, int ldA,
    const unsigned* __restrict__ Wp, int Nout,
    int bm, int bn, int chunk, unsigned* s, int tid)
{
    int kp0 = chunk * 16;
#pragma unroll
    for (int it = 0; it < 2; it++) {
        int idx = tid + it * 256;
        int r = idx >> 2;
        int c4 = idx & 3;
        cp16(s + SM_A + r * ASTR + c4 * 4,
             Ap + (size_t)(bm + r) * ldA + kp0 + c4 * 4);
    }
#pragma unroll
    for (int it = 0; it < 2; it++) {
        int idx = tid + it * 256;
        int kpl = idx >> 5;
        int n4 = idx & 31;
        cp16(s + SM_B + kpl * BSTR + n4 * 4,
             Wp + (size_t)(kp0 + kpl) * Nout + bn + n4 * 4);
    }
    asm volatile("cp.async.commit_group;");
}

__device__ __forceinline__ void gemm_core_p(
    const unsigned* __restrict__ Ap, int ldA,
    const unsigned* __restrict__ Wp,
    int K, int Nout, int bm, int bn,
    unsigned* sm, float acc[2][8][4])
{
    const int tid = threadIdx.x;
    const int lane = tid & 31;
    const int wid = tid >> 5;
    const int warp_m = wid & 3;
    const int warp_n = wid >> 2;
    const int lr = lane >> 2;
    const int lc = lane & 3;

#pragma unroll
    for (int mi = 0; mi < 2; mi++)
#pragma unroll
        for (int ni = 0; ni < 8; ni++)
#pragma unroll
            for (int t = 0; t < 4; t++) acc[mi][ni][t] = 0.0f;

    const int C = K >> 5;
    load_stage(Ap, ldA, Wp, Nout, bm, bn, 0, sm, tid);

    for (int c = 0; c < C; c++) {
        if (c + 1 < C) {
            load_stage(Ap, ldA, Wp, Nout, bm, bn, c + 1,
                       sm + ((c + 1) & 1) * STG_UINTS, tid);
            asm volatile("cp.async.wait_group 1;");
        } else {
            asm volatile("cp.async.wait_group 0;");
        }
        __syncthreads();

        unsigned* s = sm + (c & 1) * STG_UINTS;
        unsigned* As = s + SM_A;
        unsigned* Bs = s + SM_B;

#pragma unroll
        for (int st = 0; st < 2; st++) {
            unsigned ah[2][4];
#pragma unroll
            for (int mi = 0; mi < 2; mi++) {
                int rb = warp_m * 32 + mi * 16 + lr;
                int o0 = rb * ASTR + 8 * st + lc;
                int o1 = (rb + 8) * ASTR + 8 * st + lc;
                ah[mi][0] = As[o0];     ah[mi][1] = As[o1];
                ah[mi][2] = As[o0 + 4]; ah[mi][3] = As[o1 + 4];
            }
            unsigned bh[8][2];
#pragma unroll
            for (int ni = 0; ni < 8; ni++) {
                int cb = warp_n * 64 + ni * 8 + lr;
                bh[ni][0] = Bs[(8 * st + lc) * BSTR + cb];
                bh[ni][1] = Bs[(8 * st + lc + 4) * BSTR + cb];
            }
#pragma unroll
            for (int mi = 0; mi < 2; mi++)
#pragma unroll
                for (int ni = 0; ni < 8; ni++)
                    mma_f16(acc[mi][ni], ah[mi], bh[ni]);
        }
        __syncthreads();
    }
}

// QKV fused: grid.z selects weight/bias/output; packed half2 q/k/v outputs.
__global__ __launch_bounds__(256, 3)
void gemm_qkv(const unsigned* __restrict__ Ap,
              const unsigned* __restrict__ Wpq, const unsigned* __restrict__ Wpk,
              const unsigned* __restrict__ Wpv,
              const float* __restrict__ bq, const float* __restrict__ bk,
              const float* __restrict__ bv,
              unsigned* __restrict__ Cq, unsigned* __restrict__ Ck,
              unsigned* __restrict__ Cv,
              int rows) {
    extern __shared__ unsigned sm[];
    const int z = blockIdx.z;
    const unsigned* Wp = (z == 0) ? Wpq : (z == 1) ? Wpk : Wpv;
    const float* bias  = (z == 0) ? bq  : (z == 1) ? bk  : bv;
    unsigned* C        = (z == 0) ? Cq  : (z == 1) ? Ck  : Cv;
    const int bm = blockIdx.x * 128;
    float acc[2][8][4];
    gemm_core_p(Ap, 64, Wp, 128, 128, bm, 0, sm, acc);

    const int lane = threadIdx.x & 31;
    const int wid = threadIdx.x >> 5;
    const int warp_m = wid & 3, warp_n = wid >> 2;
    const int lr = lane >> 2, lc = lane & 3;
#pragma unroll
    for (int mi = 0; mi < 2; mi++) {
        int row0 = bm + warp_m * 32 + mi * 16 + lr;
        int row1 = row0 + 8;
#pragma unroll
        for (int ni = 0; ni < 8; ni++) {
            int col = warp_n * 64 + ni * 8 + 2 * lc;
            int colp = col >> 1;
            float bs0 = bias[col], bs1 = bias[col + 1];
            if (row0 < rows)
                C[(size_t)row0 * 64 + colp] =
                    pack2_f16(acc[mi][ni][0] + bs0, acc[mi][ni][1] + bs1);
            if (row1 < rows)
                C[(size_t)row1 * 64 + colp] =
                    pack2_f16(acc[mi][ni][2] + bs0, acc[mi][ni][3] + bs1);
        }
    }
}

// GEMM + fused residual/LayerNorm (Nout = 128 = full row per block).
//   o = A@W + bias ; optionally packed to yp
//   xio = LN(xio + o)*g + b ; optionally packed to xpo
__global__ __launch_bounds__(256, 3)
void gemm_ln(const unsigned* __restrict__ Ap, int ldA,
             const unsigned* __restrict__ Wp,
             const float* __restrict__ bias,
             unsigned* __restrict__ yp,
             float* __restrict__ xio,
             unsigned* __restrict__ xpo,
             const float* __restrict__ g, const float* __restrict__ b,
             int rows, int K) {
    extern __shared__ unsigned sm[];
    const int bm = blockIdx.x * 128;
    float acc[2][8][4];
    gemm_core_p(Ap, ldA, Wp, K, D, bm, 0, sm, acc);

    const int lane = threadIdx.x & 31;
    const int wid = threadIdx.x >> 5;
    const int warp_m = wid & 3, warp_n = wid >> 2;
    const int lr = lane >> 2, lc = lane & 3;

    float* sred = (float*)sm;

#pragma unroll
    for (int mi = 0; mi < 2; mi++) {
#pragma unroll
        for (int rp = 0; rp < 2; rp++) {
            int r_loc = warp_m * 32 + mi * 16 + lr + 8 * rp;
            int row = bm + r_loc;
            float sum = 0.f, sq = 0.f;
#pragma unroll
            for (int ni = 0; ni < 8; ni++) {
                int col = warp_n * 64 + ni * 8 + 2 * lc;
                float o0 = acc[mi][ni][2 * rp + 0] + bias[col];
                float o1 = acc[mi][ni][2 * rp + 1] + bias[col + 1];
                float x0 = 0.f, x1 = 0.f;
                if (row < rows) {
                    float2 xr = *(const float2*)(xio + (size_t)row * D + col);
                    x0 = xr.x; x1 = xr.y;
                    if (yp)
                        yp[(size_t)row * 64 + (col >> 1)] = pack2_f16(o0, o1);
                }
                float v0 = o0 + x0, v1 = o1 + x1;
                acc[mi][ni][2 * rp + 0] = v0;
                acc[mi][ni][2 * rp + 1] = v1;
                sum += v0 + v1;
                sq += v0 * v0 + v1 * v1;
            }
            sum += __shfl_xor_sync(0xffffffffu, sum, 1);
            sq  += __shfl_xor_sync(0xffffffffu, sq, 1);
            sum += __shfl_xor_sync(0xffffffffu, sum, 2);
            sq  += __shfl_xor_sync(0xffffffffu, sq, 2);
            if (lc == 0) {
                sred[r_loc * 4 + warp_n * 2 + 0] = sum;
                sred[r_loc * 4 + warp_n * 2 + 1] = sq;
            }
        }
    }
    __syncthreads();

#pragma unroll
    for (int mi = 0; mi < 2; mi++) {
#pragma unroll
        for (int rp = 0; rp < 2; rp++) {
            int r_loc = warp_m * 32 + mi * 16 + lr + 8 * rp;
            int row = bm + r_loc;
            if (row >= rows) continue;
            float sum = sred[r_loc * 4 + 0] + sred[r_loc * 4 + 2];
            float sq  = sred[r_loc * 4 + 1] + sred[r_loc * 4 + 3];
            float mean = sum * (1.0f / 128.0f);
            float var = sq * (1.0f / 128.0f) - mean * mean;
            float rstd = rsqrtf(var + 1e-5f);
#pragma unroll
            for (int ni = 0; ni < 8; ni++) {
                int col = warp_n * 64 + ni * 8 + 2 * lc;
                float v0 = acc[mi][ni][2 * rp + 0];
                float v1 = acc[mi][ni][2 * rp + 1];
                float out0 = (v0 - mean) * rstd * g[col] + b[col];
                float out1 = (v1 - mean) * rstd * g[col + 1] + b[col + 1];
                *(float2*)(xio + (size_t)row * D + col) = make_float2(out0, out1);
                if (xpo)
                    xpo[(size_t)row * 64 + (col >> 1)] = pack2_f16(out0, out1);
            }
        }
    }
}

// FFN first GEMM: relu, packed output (Nout = 256 via grid.y)
__global__ __launch_bounds__(256, 3)
void gemm_f1(const unsigned* __restrict__ Ap,
             const unsigned* __restrict__ Wp,
             const float* __restrict__ bias,
             unsigned* __restrict__ outp,
             int rows) {
    extern __shared__ unsigned sm[];
    const int bm = blockIdx.x * 128;
    const int bn = blockIdx.y * 128;
    float acc[2][8][4];
    gemm_core_p(Ap, 64, Wp, 128, 256, bm, bn, sm, acc);

    const int lane = threadIdx.x & 31;
    const int wid = threadIdx.x >> 5;
    const int warp_m = wid & 3, warp_n = wid >> 2;
    const int lr = lane >> 2, lc = lane & 3;
#pragma unroll
    for (int mi = 0; mi < 2; mi++) {
        int row0 = bm + warp_m * 32 + mi * 16 + lr;
        int row1 = row0 + 8;
#pragma unroll
        for (int ni = 0; ni < 8; ni++) {
            int col = bn + warp_n * 64 + ni * 8 + 2 * lc;
            int colp = col >> 1;
            float bs0 = bias[col], bs1 = bias[col + 1];
            float o0 = fmaxf(acc[mi][ni][0] + bs0, 0.f);
            float o1 = fmaxf(acc[mi][ni][1] + bs1, 0.f);
            float o2 = fmaxf(acc[mi][ni][2] + bs0, 0.f);
            float o3 = fmaxf(acc[mi][ni][3] + bs1, 0.f);
            if (row0 < rows)
                outp[(size_t)row0 * 128 + colp] = pack2_f16(o0, o1);
            if (row1 < rows)
                outp[(size_t)row1 * 128 + colp] = pack2_f16(o2, o3);
        }
    }
}

// ---------------------------------------------------------------------------
// CSR attention: warp per destination node, fp16 q/k/v in, fp16 out.
// Lane owns 4 dims (head = lane>>2, colp = lane*2).
// ---------------------------------------------------------------------------
__global__ void attn_csr(const int* __restrict__ rowptr, const int* __restrict__ csr_src,
                         const unsigned* __restrict__ qh, const unsigned* __restrict__ kh,
                         const unsigned* __restrict__ vh, unsigned* __restrict__ wvp, int N) {
    int warp = blockIdx.x * (blockDim.x >> 5) + (threadIdx.x >> 5);
    if (warp >= N) return;
    int lane = threadIdx.x & 31;
    int colp = lane * 2;

    uint2 qp = *(const uint2*)(qh + (size_t)warp * 64 + colp);
    float2 q01 = unpack2_f16(qp.x);
    float2 q23 = unpack2_f16(qp.y);

    float4 acc = make_float4(0.f, 0.f, 0.f, 0.f);
    float Zh = 0.0f;

    int jb = rowptr[warp];
    int je = rowptr[warp + 1];
    for (int j = jb; j < je; j++) {
        int s0 = csr_src[j];
        uint2 kp2 = *(const uint2*)(kh + (size_t)s0 * 64 + colp);
        float2 k01 = unpack2_f16(kp2.x);
        float2 k23 = unpack2_f16(kp2.y);
        float s = k01.x * q01.x + k01.y * q01.y + k23.x * q23.x + k23.y * q23.y;
        s += __shfl_xor_sync(0xffffffffu, s, 1);
        s += __shfl_xor_sync(0xffffffffu, s, 2);
        s = expf(fminf(fmaxf(s * 0.25f, -5.0f), 5.0f));
        uint2 vp2 = *(const uint2*)(vh + (size_t)s0 * 64 + colp);
        float2 v01 = unpack2_f16(vp2.x);
        float2 v23 = unpack2_f16(vp2.y);
        acc.x = fmaf(v01.x, s, acc.x);
        acc.y = fmaf(v01.y, s, acc.y);
        acc.z = fmaf(v23.x, s, acc.z);
        acc.w = fmaf(v23.y, s, acc.w);
        Zh += s;
    }
    float inv = 1.0f / (Zh + 1e-6f);
    acc.x *= inv; acc.y *= inv; acc.z *= inv; acc.w *= inv;

    *(uint2*)(wvp + (size_t)warp * 64 + colp) =
        make_uint2(pack2_f16(acc.x, acc.y), pack2_f16(acc.z, acc.w));
}

// ---------------------------------------------------------------------------
__global__ void colsum(const float* __restrict__ x, float* __restrict__ acc, int N) {
    int d = threadIdx.x;
    float s = 0.0f;
    for (int r = blockIdx.x; r < N; r += gridDim.x)
        s += x[(size_t)r * D + d];
    atomicAdd(&acc[d], s);
}

__global__ void readout(const float* __restrict__ acc,
                        const float* __restrict__ mW0, const float* __restrict__ mb0,
                        const float* __restrict__ mW1, const float* __restrict__ mb1,
                        const float* __restrict__ mW2, const float* __restrict__ mb2,
                        float* __restrict__ out, int N) {
    __shared__ float m[D];
    __shared__ float h0[64];
    __shared__ float h1[32];
    int tid = threadIdx.x;
    m[tid] = acc[tid] * (1.0f / (float)N);
    __syncthreads();
    if (tid < 64) {
        float s = mb0[tid];
        for (int kk = 0; kk < D; kk++) s = fmaf(m[kk], mW0[kk * 64 + tid], s);
        h0[tid] = fmaxf(s, 0.0f);
    }
    __syncthreads();
    if (tid < 32) {
        float s = mb1[tid];
        for (int kk = 0; kk < 64; kk++) s = fmaf(h0[kk], mW1[kk * 32 + tid], s);
        h1[tid] = fmaxf(s, 0.0f);
    }
    __syncthreads();
    if (tid < 10) {
        float s = mb2[tid];
        for (int kk = 0; kk < 32; kk++) s = fmaf(h1[kk], mW2[kk * 10 + tid], s);
        out[tid] = s;
    }
}

// ---------------------------------------------------------------------------
extern "C" void kernel_launch(void* const* d_in, const int* in_sizes, int n_in,
                              void* d_out, int out_size) {
    const int*   x_idx = (const int*)d_in[0];
    const int*   ei    = (const int*)d_in[1];
    const float* emb   = (const float*)d_in[2];
    const float* Wq  = (const float*)d_in[3];
    const float* bq  = (const float*)d_in[4];
    const float* Wk  = (const float*)d_in[5];
    const float* bk  = (const float*)d_in[6];
    const float* Wv  = (const float*)d_in[7];
    const float* bv  = (const float*)d_in[8];
    const float* Wo  = (const float*)d_in[9];
    const float* bo  = (const float*)d_in[10];
    const float* g1  = (const float*)d_in[11];
    const float* be1 = (const float*)d_in[12];
    const float* Wf1 = (const float*)d_in[13];
    const float* bf1 = (const float*)d_in[14];
    const float* Wf2 = (const float*)d_in[15];
    const float* bf2 = (const float*)d_in[16];
    const float* g2  = (const float*)d_in[17];
    const float* be2 = (const float*)d_in[18];
    const float* mW0 = (const float*)d_in[19];
    const float* mb0 = (const float*)d_in[20];
    const float* mW1 = (const float*)d_in[21];
    const float* mb1 = (const float*)d_in[22];
    const float* mW2 = (const float*)d_in[23];
    const float* mb2 = (const float*)d_in[24];
    float* out = (float*)d_out;

    const int N = in_sizes[0];       // 50000
    const int E = in_sizes[1] / 2;   // 800000

    float* base;
    cudaGetSymbolAddress((void**)&base, g_scratch);
    float* x   = base + OFF_X;
    float* acc = base + OFF_ACC;

    int* ibase;
    cudaGetSymbolAddress((void**)&ibase, g_iscratch);
    int* cnt     = ibase + IOFF_CNT;
    int* rowptr  = ibase + IOFF_ROW;
    int* csr_src = ibase + IOFF_SRC;

    unsigned *wp, *xp, *yp, *qp, *kp, *vp, *wvp, *midp;
    cudaGetSymbolAddress((void**)&wp, g_wpack);
    cudaGetSymbolAddress((void**)&xp, g_xp);
    cudaGetSymbolAddress((void**)&yp, g_yp);
    cudaGetSymbolAddress((void**)&qp, g_qp);
    cudaGetSymbolAddress((void**)&kp, g_kp);
    cudaGetSymbolAddress((void**)&vp, g_vp);
    cudaGetSymbolAddress((void**)&wvp, g_wvp);
    cudaGetSymbolAddress((void**)&midp, g_midp);

    cudaFuncSetAttribute(gemm_qkv, cudaFuncAttributeMaxDynamicSharedMemorySize, GEMM_DYN_SMEM);
    cudaFuncSetAttribute(gemm_ln, cudaFuncAttributeMaxDynamicSharedMemorySize, GEMM_DYN_SMEM);
    cudaFuncSetAttribute(gemm_f1, cudaFuncAttributeMaxDynamicSharedMemorySize, GEMM_DYN_SMEM);

    const int nb128 = (N + 127) / 128;

    // --- Ordered so gemm_qkv is the 6th launch (ncu -s 5 -c 1 profiles it) ---
    conv_w<<<(LAYERS * PQ + 255) / 256, 256>>>(Wq, wp + WQ_OFF, 128, 128, LAYERS);   // 1
    conv_w<<<(LAYERS * PQ + 255) / 256, 256>>>(Wk, wp + WK_OFF, 128, 128, LAYERS);   // 2
    conv_w<<<(LAYERS * PQ + 255) / 256, 256>>>(Wv, wp + WV_OFF, 128, 128, LAYERS);   // 3
    emb_gather<<<(N * 64 + 255) / 256, 256>>>(x_idx, emb, x, xp, N);                 // 4
    zero_int<<<(N + 255) / 256, 256>>>(cnt, N);                                      // 5

    // Layer 0 QKV (6th launch -> profiled)
    gemm_qkv<<<dim3(nb128, 1, 3), 256, GEMM_DYN_SMEM>>>(
        xp, wp + WQ_OFF, wp + WK_OFF, wp + WV_OFF, bq, bk, bv, qp, kp, vp, N);

    // CSR build + remaining weight conversions
    hist_dst<<<(E + 255) / 256, 256>>>(ei, E, cnt);
    scan_rowptr<<<1, 1024>>>(cnt, rowptr, N);
    zero_int<<<(N + 255) / 256, 256>>>(cnt, N);
    csr_scatter<<<(E + 255) / 256, 256>>>(ei, E, rowptr, cnt, csr_src);
    conv_w<<<(LAYERS * PQ + 255) / 256, 256>>>(Wo, wp + WO_OFF, 128, 128, LAYERS);
    conv_w<<<(LAYERS * PF + 255) / 256, 256>>>(Wf1, wp + WF1_OFF, 128, 256, LAYERS);
    conv_w<<<(LAYERS * PF + 255) / 256, 256>>>(Wf2, wp + WF2_OFF, 256, 128, LAYERS);

    for (int l = 0; l < LAYERS; l++) {
        const unsigned* wq_p = wp + WQ_OFF + (size_t)l * PQ;
        const unsigned* wk_p = wp + WK_OFF + (size_t)l * PQ;
        const unsigned* wv_p = wp + WV_OFF + (size_t)l * PQ;
        const unsigned* wo_p = wp + WO_OFF + (size_t)l * PQ;
        const unsigned* wf1_p = wp + WF1_OFF + (size_t)l * PF;
        const unsigned* wf2_p = wp + WF2_OFF + (size_t)l * PF;

        if (l > 0) {
            gemm_qkv<<<dim3(nb128, 1, 3), 256, GEMM_DYN_SMEM>>>(
                xp, wq_p, wk_p, wv_p, bq + l * D, bk + l * D, bv + l * D,
                qp, kp, vp, N);
        }

        attn_csr<<<(N + 7) / 8, 256>>>(rowptr, csr_src, qp, kp, vp, wvp, N);

        // y(packed) = wV@Wo + bo ; x = LN(x + y)
        gemm_ln<<<nb128, 256, GEMM_DYN_SMEM>>>(
            wvp, 64, wo_p, bo + l * D, yp, x, nullptr,
            g1 + l * D, be1 + l * D, N, 128);

        // mid(packed) = relu(y@Wf1 + bf1)
        gemm_f1<<<dim3(nb128, 2), 256, GEMM_DYN_SMEM>>>(yp, wf1_p, bf1 + l * 2 * D, midp, N);

        // x = LN(x + mid@Wf2 + bf2), also packed to xp
        gemm_ln<<<nb128, 256, GEMM_DYN_SMEM>>>(
            midp, 128, wf2_p, bf2 + l * D, nullptr, x, xp,
            g2 + l * D, be2 + l * D, N, 256);
    }

    zero_kernel<<<1, 128>>>(acc, D);
    colsum<<<256, 128>>>(x, acc, N);
    readout<<<1, 128>>>(acc, mW0, mb0, mW1, mb1, mW2, mb2, out, N);
}

// round 11
// speedup vs baseline: 4.5610x; 1.0496x over previous
#include <cuda_runtime.h>
#include <cuda_fp16.h>
#include <cstddef>

#define D       128
#define H       8
#define HD      16
#define NMAX    50000
#define NPAD    50176          // 392 * 128
#define EMAX    800000
#define LAYERS  3

// ---------------------------------------------------------------------------
// Float scratch: x (residual/pool), colsum partials
// ---------------------------------------------------------------------------
#define OFF_X    ((size_t)0)
#define OFF_PART (OFF_X + (size_t)NMAX * D)
#define NPARTBLK 256
#define SCRATCH_FLOATS (OFF_PART + (size_t)NPARTBLK * D)
__device__ float g_scratch[SCRATCH_FLOATS];

// Packed fp16 activations (single plane, half2 per uint, pairs along K)
#define XPL   ((size_t)NPAD * 64)
#define MIDPL ((size_t)NPAD * 128)
__device__ unsigned g_xp[XPL];
__device__ unsigned g_yp[XPL];
__device__ unsigned g_qp[XPL];
__device__ unsigned g_kp[XPL];
__device__ unsigned g_vp[XPL];
__device__ unsigned g_wvp[XPL];
__device__ unsigned g_midp[MIDPL];

// Int scratch: cnt[N], rowptr[N+1], csr_src[E]
#define IOFF_CNT   0
#define IOFF_ROW   (IOFF_CNT + NMAX)
#define IOFF_SRC   (IOFF_ROW + NMAX + 1)
__device__ int g_iscratch[IOFF_SRC + EMAX];

// Packed fp16 weights, N-MAJOR rows of K-pairs: w[n][kp] (half2 per uint).
#define PQ      (64 * 128)     // DxD matrix (uints)
#define PF      (64 * 256)     // 128x256 / 256x128 (uints)
#define SQ      (LAYERS * PQ)
#define SF      (LAYERS * PF)
#define WQ_OFF  0
#define WK_OFF  (WQ_OFF + SQ)
#define WV_OFF  (WK_OFF + SQ)
#define WO_OFF  (WV_OFF + SQ)
#define WF1_OFF (WO_OFF + SQ)
#define WF2_OFF (WF1_OFF + SF)
#define WPACK_TOTAL (WF2_OFF + SF)
__device__ unsigned g_wpack[WPACK_TOTAL];

// ---------------------------------------------------------------------------
__device__ __forceinline__ unsigned pack2_f16(float a, float b) {
    __half2 h2 = __floats2half2_rn(a, b);
    return *(unsigned*)&h2;
}
__device__ __forceinline__ float2 unpack2_f16(unsigned u) {
    return __half22float2(*(__half2*)&u);
}
__device__ __forceinline__ void cp16(unsigned* smem, const unsigned* gmem) {
    unsigned sa = (unsigned)__cvta_generic_to_shared(smem);
    asm volatile("cp.async.cg.shared.global [%0], [%1], 16;" :: "r"(sa), "l"(gmem));
}
#define LDSM_X4(r0, r1, r2, r3, addr) \
    asm volatile("ldmatrix.sync.aligned.m8n8.x4.shared.b16 {%0,%1,%2,%3}, [%4];" \
                 : "=r"(r0), "=r"(r1), "=r"(r2), "=r"(r3) : "r"(addr))

// ---------------------------------------------------------------------------
__global__ void zero_int(int* __restrict__ p, int n) {
    int i = blockIdx.x * blockDim.x + threadIdx.x;
    int stride = gridDim.x * blockDim.x;
    for (; i < n; i += stride) p[i] = 0;
}

// Embedding gather: float x + packed xp
__global__ void emb_gather(const int* __restrict__ idx, const float* __restrict__ emb,
                           float* __restrict__ x, unsigned* __restrict__ xp, int N) {
    int i = blockIdx.x * blockDim.x + threadIdx.x;
    if (i >= N * 64) return;
    int n = i >> 6;
    int kp = i & 63;
    float2 e = *(const float2*)(emb + (size_t)idx[n] * D + 2 * kp);
    *(float2*)(x + (size_t)n * D + 2 * kp) = e;
    xp[(size_t)n * 64 + kp] = pack2_f16(e.x, e.y);
}

// Combined weight conversion: all 6 weight stacks in ONE launch.
// float [L, K, Nout] -> n-major packed: dst[l*P + n*(K/2) + kp]
__global__ void conv_all(const float* __restrict__ Wq, const float* __restrict__ Wk,
                         const float* __restrict__ Wv, const float* __restrict__ Wo,
                         const float* __restrict__ Wf1, const float* __restrict__ Wf2,
                         unsigned* __restrict__ wp) {
    int idx = blockIdx.x * blockDim.x + threadIdx.x;
    if (idx >= (int)WPACK_TOTAL) return;

    const float* src;
    int K, Nout, rem, dstoff;
    if (idx < 4 * SQ) {
        int which = idx / SQ;
        rem = idx - which * SQ;
        src = (which == 0) ? Wq : (which == 1) ? Wk : (which == 2) ? Wv : Wo;
        K = 128; Nout = 128;
        dstoff = which * SQ;
    } else if (idx < 4 * SQ + SF) {
        rem = idx - 4 * SQ;
        src = Wf1; K = 128; Nout = 256; dstoff = WF1_OFF;
    } else {
        rem = idx - 4 * SQ - SF;
        src = Wf2; K = 256; Nout = 128; dstoff = WF2_OFF;
    }
    int KH = K >> 1;
    int P = KH * Nout;
    int l = rem / P;
    int p = rem - l * P;
    int n = p / KH;
    int kp = p - n * KH;
    float a = src[(size_t)l * K * Nout + (size_t)(2 * kp) * Nout + n];
    float b = src[(size_t)l * K * Nout + (size_t)(2 * kp + 1) * Nout + n];
    wp[dstoff + (size_t)l * P + p] = pack2_f16(a, b);
}

// ---------------------------------------------------------------------------
// CSR build
// ---------------------------------------------------------------------------
__global__ void hist_dst(const int* __restrict__ ei, int E, int* __restrict__ cnt) {
    int j = blockIdx.x * blockDim.x + threadIdx.x;
    if (j < E) atomicAdd(&cnt[ei[E + j]], 1);
}
__global__ void scan_rowptr(const int* __restrict__ cnt, int* __restrict__ rowptr, int N) {
    __shared__ int ssum[1024];
    int tid = threadIdx.x;
    int chunk = (N + 1023) / 1024;
    int start = tid * chunk;
    int end = min(start + chunk, N);
    int s = 0;
    for (int i = start; i < end; i++) s += cnt[i];
    ssum[tid] = s;
    __syncthreads();
    int mysum = s;
    for (int o = 1; o < 1024; o <<= 1) {
        int t = (tid >= o) ? ssum[tid - o] : 0;
        __syncthreads();
        ssum[tid] += t;
        __syncthreads();
    }
    int off = ssum[tid] - mysum;
    for (int i = start; i < end; i++) { rowptr[i] = off; off += cnt[i]; }
    if (end == N) rowptr[N] = off;
}
__global__ void csr_scatter(const int* __restrict__ ei, int E,
                            const int* __restrict__ rowptr, int* __restrict__ cur,
                            int* __restrict__ csr_src) {
    int j = blockIdx.x * blockDim.x + threadIdx.x;
    if (j >= E) return;
    int d = ei[E + j];
    int pos = atomicAdd(&cur[d], 1);
    csr_src[rowptr[d] + pos] = ei[j];
}

// ---------------------------------------------------------------------------
// fp16 tensor-core GEMM core with ldmatrix fragment loads.
// Block tile 128x128, chunk K=32, 256 threads (8 warps: 4 M x 2 N, 32x64/warp).
// A: packed pairs [row][kp] (ldA uints/row). W: n-major [n][kp] (ldW uints/row).
// Both staged at stride ASTR=20 uints (80B): conflict-free for LDSM.
// ---------------------------------------------------------------------------
#define ASTR 20
#define SM_A 0
#define SM_B 2560
#define STG_UINTS 5120
#define GEMM_DYN_SMEM (2 * STG_UINTS * 4)

__device__ __forceinline__ void mma_f16(float c[4], const unsigned a[4],
                                        unsigned b0, unsigned b1) {
    asm volatile(
        "mma.sync.aligned.m16n8k16.row.col.f32.f16.f16.f32 "
        "{%0,%1,%2,%3}, {%4,%5,%6,%7}, {%8,%9}, {%0,%1,%2,%3};"
        : "+f"(c[0]), "+f"(c[1]), "+f"(c[2]), "+f"(c[3])
        : "r"(a[0]), "r"(a[1]), "r"(a[2]), "r"(a[3]), "r"(b0), "r"(b1));
}

__device__ __forceinline__ void load_stage(
    const unsigned* __restrict__ Ap, int ldA,
    const unsigned* __restrict__ Wp, int ldW,
    int bm, int bn, int chunk, unsigned* s, int tid)
{
    int kp0 = chunk * 16;
#pragma unroll
    for (int it = 0; it < 2; it++) {
        int idx = tid + it * 256;
        int r = idx >> 2;
        int c4 = idx & 3;
        cp16(s + SM_A + r * ASTR + c4 * 4,
             Ap + (size_t)(bm + r) * ldA + kp0 + c4 * 4);
    }
#pragma unroll
    for (int it = 0; it < 2; it++) {
        int idx = tid + it * 256;
        int r = idx >> 2;
        int c4 = idx & 3;
        cp16(s + SM_B + r * ASTR + c4 * 4,
             Wp + (size_t)(bn + r) * ldW + kp0 + c4 * 4);
    }
    asm volatile("cp.async.commit_group;");
}

__device__ __forceinline__ void gemm_core_p(
    const unsigned* __restrict__ Ap, int ldA,
    const unsigned* __restrict__ Wp, int ldW,
    int K, int bm, int bn,
    unsigned* sm, float acc[2][8][4])
{
    const int tid = threadIdx.x;
    const int lane = tid & 31;
    const int wid = tid >> 5;
    const int warp_m = wid & 3;
    const int warp_n = wid >> 2;
    const int sub = lane >> 3;     // 0..3 (ldmatrix sub-matrix selector)
    const int rin = lane & 7;

    const unsigned sbase = (unsigned)__cvta_generic_to_shared(sm);
    // A ldmatrix row/col components (per lane)
    const int a_row = warp_m * 32 + (sub & 1) * 8 + rin;   // + mi*16
    const int a_col = (sub >> 1) * 4;                      // + 8*st
    // B ldmatrix: row = warp_n*64 + (2t + (sub>>1))*8 + rin ; col = (sub&1)*4 + 8*st
    const int b_row0 = warp_n * 64 + (sub >> 1) * 8 + rin; // + t*16
    const int b_col = (sub & 1) * 4;

#pragma unroll
    for (int mi = 0; mi < 2; mi++)
#pragma unroll
        for (int ni = 0; ni < 8; ni++)
#pragma unroll
            for (int t = 0; t < 4; t++) acc[mi][ni][t] = 0.0f;

    const int C = K >> 5;
    load_stage(Ap, ldA, Wp, ldW, bm, bn, 0, sm, tid);

    for (int c = 0; c < C; c++) {
        if (c + 1 < C) {
            load_stage(Ap, ldA, Wp, ldW, bm, bn, c + 1,
                       sm + ((c + 1) & 1) * STG_UINTS, tid);
            asm volatile("cp.async.wait_group 1;");
        } else {
            asm volatile("cp.async.wait_group 0;");
        }
        __syncthreads();

        const unsigned stg = sbase + (unsigned)((c & 1) * STG_UINTS) * 4u;

#pragma unroll
        for (int st = 0; st < 2; st++) {
            unsigned ah[2][4];
#pragma unroll
            for (int mi = 0; mi < 2; mi++) {
                unsigned aaddr = stg + ((unsigned)(SM_A + (a_row + mi * 16) * ASTR
                                                   + 8 * st + a_col) << 2);
                LDSM_X4(ah[mi][0], ah[mi][1], ah[mi][2], ah[mi][3], aaddr);
            }
#pragma unroll
            for (int t = 0; t < 4; t++) {
                unsigned b0, b1, b2, b3;
                unsigned baddr = stg + ((unsigned)(SM_B + (b_row0 + t * 16) * ASTR
                                                   + 8 * st + b_col) << 2);
                LDSM_X4(b0, b1, b2, b3, baddr);
#pragma unroll
                for (int mi = 0; mi < 2; mi++) {
                    mma_f16(acc[mi][2 * t + 0], ah[mi], b0, b1);
                    mma_f16(acc[mi][2 * t + 1], ah[mi], b2, b3);
                }
            }
        }
        __syncthreads();
    }
}

// QKV fused: grid.z selects weight/bias/output; packed half2 q/k/v outputs.
__global__ __launch_bounds__(256, 2)
void gemm_qkv(const unsigned* __restrict__ Ap,
              const unsigned* __restrict__ Wpq, const unsigned* __restrict__ Wpk,
              const unsigned* __restrict__ Wpv,
              const float* __restrict__ bq, const float* __restrict__ bk,
              const float* __restrict__ bv,
              unsigned* __restrict__ Cq, unsigned* __restrict__ Ck,
              unsigned* __restrict__ Cv,
              int rows) {
    extern __shared__ unsigned sm[];
    const int z = blockIdx.z;
    const unsigned* Wp = (z == 0) ? Wpq : (z == 1) ? Wpk : Wpv;
    const float* bias  = (z == 0) ? bq  : (z == 1) ? bk  : bv;
    unsigned* C        = (z == 0) ? Cq  : (z == 1) ? Ck  : Cv;
    const int bm = blockIdx.x * 128;
    float acc[2][8][4];
    gemm_core_p(Ap, 64, Wp, 64, 128, bm, 0, sm, acc);

    const int lane = threadIdx.x & 31;
    const int wid = threadIdx.x >> 5;
    const int warp_m = wid & 3, warp_n = wid >> 2;
    const int lr = lane >> 2, lc = lane & 3;
#pragma unroll
    for (int mi = 0; mi < 2; mi++) {
        int row0 = bm + warp_m * 32 + mi * 16 + lr;
        int row1 = row0 + 8;
#pragma unroll
        for (int ni = 0; ni < 8; ni++) {
            int col = warp_n * 64 + ni * 8 + 2 * lc;
            int colp = col >> 1;
            float bs0 = bias[col], bs1 = bias[col + 1];
            if (row0 < rows)
                C[(size_t)row0 * 64 + colp] =
                    pack2_f16(acc[mi][ni][0] + bs0, acc[mi][ni][1] + bs1);
            if (row1 < rows)
                C[(size_t)row1 * 64 + colp] =
                    pack2_f16(acc[mi][ni][2] + bs0, acc[mi][ni][3] + bs1);
        }
    }
}

// GEMM + fused residual/LayerNorm (Nout = 128 = full row per block).
__global__ __launch_bounds__(256, 2)
void gemm_ln(const unsigned* __restrict__ Ap, int ldA,
             const unsigned* __restrict__ Wp, int ldW,
             const float* __restrict__ bias,
             unsigned* __restrict__ yp,
             float* __restrict__ xio,
             unsigned* __restrict__ xpo,
             const float* __restrict__ g, const float* __restrict__ b,
             int rows, int K) {
    extern __shared__ unsigned sm[];
    const int bm = blockIdx.x * 128;
    float acc[2][8][4];
    gemm_core_p(Ap, ldA, Wp, ldW, K, bm, 0, sm, acc);

    const int lane = threadIdx.x & 31;
    const int wid = threadIdx.x >> 5;
    const int warp_m = wid & 3, warp_n = wid >> 2;
    const int lr = lane >> 2, lc = lane & 3;

    float* sred = (float*)sm;

#pragma unroll
    for (int mi = 0; mi < 2; mi++) {
#pragma unroll
        for (int rp = 0; rp < 2; rp++) {
            int r_loc = warp_m * 32 + mi * 16 + lr + 8 * rp;
            int row = bm + r_loc;
            float sum = 0.f, sq = 0.f;
#pragma unroll
            for (int ni = 0; ni < 8; ni++) {
                int col = warp_n * 64 + ni * 8 + 2 * lc;
                float o0 = acc[mi][ni][2 * rp + 0] + bias[col];
                float o1 = acc[mi][ni][2 * rp + 1] + bias[col + 1];
                float x0 = 0.f, x1 = 0.f;
                if (row < rows) {
                    float2 xr = *(const float2*)(xio + (size_t)row * D + col);
                    x0 = xr.x; x1 = xr.y;
                    if (yp)
                        yp[(size_t)row * 64 + (col >> 1)] = pack2_f16(o0, o1);
                }
                float v0 = o0 + x0, v1 = o1 + x1;
                acc[mi][ni][2 * rp + 0] = v0;
                acc[mi][ni][2 * rp + 1] = v1;
                sum += v0 + v1;
                sq += v0 * v0 + v1 * v1;
            }
            sum += __shfl_xor_sync(0xffffffffu, sum, 1);
            sq  += __shfl_xor_sync(0xffffffffu, sq, 1);
            sum += __shfl_xor_sync(0xffffffffu, sum, 2);
            sq  += __shfl_xor_sync(0xffffffffu, sq, 2);
            if (lc == 0) {
                sred[r_loc * 4 + warp_n * 2 + 0] = sum;
                sred[r_loc * 4 + warp_n * 2 + 1] = sq;
            }
        }
    }
    __syncthreads();

#pragma unroll
    for (int mi = 0; mi < 2; mi++) {
#pragma unroll
        for (int rp = 0; rp < 2; rp++) {
            int r_loc = warp_m * 32 + mi * 16 + lr + 8 * rp;
            int row = bm + r_loc;
            if (row >= rows) continue;
            float sum = sred[r_loc * 4 + 0] + sred[r_loc * 4 + 2];
            float sq  = sred[r_loc * 4 + 1] + sred[r_loc * 4 + 3];
            float mean = sum * (1.0f / 128.0f);
            float var = sq * (1.0f / 128.0f) - mean * mean;
            float rstd = rsqrtf(var + 1e-5f);
#pragma unroll
            for (int ni = 0; ni < 8; ni++) {
                int col = warp_n * 64 + ni * 8 + 2 * lc;
                float v0 = acc[mi][ni][2 * rp + 0];
                float v1 = acc[mi][ni][2 * rp + 1];
                float out0 = (v0 - mean) * rstd * g[col] + b[col];
                float out1 = (v1 - mean) * rstd * g[col + 1] + b[col + 1];
                *(float2*)(xio + (size_t)row * D + col) = make_float2(out0, out1);
                if (xpo)
                    xpo[(size_t)row * 64 + (col >> 1)] = pack2_f16(out0, out1);
            }
        }
    }
}

// FFN first GEMM: relu, packed output (Nout = 256 via grid.y)
__global__ __launch_bounds__(256, 2)
void gemm_f1(const unsigned* __restrict__ Ap,
             const unsigned* __restrict__ Wp,
             const float* __restrict__ bias,
             unsigned* __restrict__ outp,
             int rows) {
    extern __shared__ unsigned sm[];
    const int bm = blockIdx.x * 128;
    const int bn = blockIdx.y * 128;
    float acc[2][8][4];
    gemm_core_p(Ap, 64, Wp, 64, 128, bm, bn, sm, acc);

    const int lane = threadIdx.x & 31;
    const int wid = threadIdx.x >> 5;
    const int warp_m = wid & 3, warp_n = wid >> 2;
    const int lr = lane >> 2, lc = lane & 3;
#pragma unroll
    for (int mi = 0; mi < 2; mi++) {
        int row0 = bm + warp_m * 32 + mi * 16 + lr;
        int row1 = row0 + 8;
#pragma unroll
        for (int ni = 0; ni < 8; ni++) {
            int col = bn + warp_n * 64 + ni * 8 + 2 * lc;
            int colp = col >> 1;
            float bs0 = bias[col], bs1 = bias[col + 1];
            float o0 = fmaxf(acc[mi][ni][0] + bs0, 0.f);
            float o1 = fmaxf(acc[mi][ni][1] + bs1, 0.f);
            float o2 = fmaxf(acc[mi][ni][2] + bs0, 0.f);
            float o3 = fmaxf(acc[mi][ni][3] + bs1, 0.f);
            if (row0 < rows)
                outp[(size_t)row0 * 128 + colp] = pack2_f16(o0, o1);
            if (row1 < rows)
                outp[(size_t)row1 * 128 + colp] = pack2_f16(o2, o3);
        }
    }
}

// ---------------------------------------------------------------------------
// CSR attention: warp per destination node, fp16 q/k/v in, fp16 out.
// ---------------------------------------------------------------------------
__global__ void attn_csr(const int* __restrict__ rowptr, const int* __restrict__ csr_src,
                         const unsigned* __restrict__ qh, const unsigned* __restrict__ kh,
                         const unsigned* __restrict__ vh, unsigned* __restrict__ wvp, int N) {
    int warp = blockIdx.x * (blockDim.x >> 5) + (threadIdx.x >> 5);
    if (warp >= N) return;
    int lane = threadIdx.x & 31;
    int colp = lane * 2;

    uint2 qp = *(const uint2*)(qh + (size_t)warp * 64 + colp);
    float2 q01 = unpack2_f16(qp.x);
    float2 q23 = unpack2_f16(qp.y);

    float4 acc = make_float4(0.f, 0.f, 0.f, 0.f);
    float Zh = 0.0f;

    int jb = rowptr[warp];
    int je = rowptr[warp + 1];
    for (int j = jb; j < je; j++) {
        int s0 = csr_src[j];
        uint2 kp2 = *(const uint2*)(kh + (size_t)s0 * 64 + colp);
        float2 k01 = unpack2_f16(kp2.x);
        float2 k23 = unpack2_f16(kp2.y);
        float s = k01.x * q01.x + k01.y * q01.y + k23.x * q23.x + k23.y * q23.y;
        s += __shfl_xor_sync(0xffffffffu, s, 1);
        s += __shfl_xor_sync(0xffffffffu, s, 2);
        s = expf(fminf(fmaxf(s * 0.25f, -5.0f), 5.0f));
        uint2 vp2 = *(const uint2*)(vh + (size_t)s0 * 64 + colp);
        float2 v01 = unpack2_f16(vp2.x);
        float2 v23 = unpack2_f16(vp2.y);
        acc.x = fmaf(v01.x, s, acc.x);
        acc.y = fmaf(v01.y, s, acc.y);
        acc.z = fmaf(v23.x, s, acc.z);
        acc.w = fmaf(v23.y, s, acc.w);
        Zh += s;
    }
    float inv = 1.0f / (Zh + 1e-6f);
    acc.x *= inv; acc.y *= inv; acc.z *= inv; acc.w *= inv;

    *(uint2*)(wvp + (size_t)warp * 64 + colp) =
        make_uint2(pack2_f16(acc.x, acc.y), pack2_f16(acc.z, acc.w));
}

// ---------------------------------------------------------------------------
// Mean pool: per-block partial colsum (no atomics), reduced in readout.
// ---------------------------------------------------------------------------
__global__ void colsum(const float* __restrict__ x, float* __restrict__ part, int N) {
    int d = threadIdx.x;
    float s = 0.0f;
    for (int r = blockIdx.x; r < N; r += gridDim.x)
        s += x[(size_t)r * D + d];
    part[(size_t)blockIdx.x * D + d] = s;
}

__global__ void readout(const float* __restrict__ part,
                        const float* __restrict__ mW0, const float* __restrict__ mb0,
                        const float* __restrict__ mW1, const float* __restrict__ mb1,
                        const float* __restrict__ mW2, const float* __restrict__ mb2,
                        float* __restrict__ out, int N) {
    __shared__ float m[D];
    __shared__ float h0[64];
    __shared__ float h1[32];
    int tid = threadIdx.x;
    float s0 = 0.f;
    for (int bqi = 0; bqi < NPARTBLK; bqi++) s0 += part[(size_t)bqi * D + tid];
    m[tid] = s0 * (1.0f / (float)N);
    __syncthreads();
    if (tid < 64) {
        float s = mb0[tid];
        for (int kk = 0; kk < D; kk++) s = fmaf(m[kk], mW0[kk * 64 + tid], s);
        h0[tid] = fmaxf(s, 0.0f);
    }
    __syncthreads();
    if (tid < 32) {
        float s = mb1[tid];
        for (int kk = 0; kk < 64; kk++) s = fmaf(h0[kk], mW1[kk * 32 + tid], s);
        h1[tid] = fmaxf(s, 0.0f);
    }
    __syncthreads();
    if (tid < 10) {
        float s = mb2[tid];
        for (int kk = 0; kk < 32; kk++) s = fmaf(h1[kk], mW2[kk * 10 + tid], s);
        out[tid] = s;
    }
}

// ---------------------------------------------------------------------------
extern "C" void kernel_launch(void* const* d_in, const int* in_sizes, int n_in,
                              void* d_out, int out_size) {
    const int*   x_idx = (const int*)d_in[0];
    const int*   ei    = (const int*)d_in[1];
    const float* emb   = (const float*)d_in[2];
    const float* Wq  = (const float*)d_in[3];
    const float* bq  = (const float*)d_in[4];
    const float* Wk  = (const float*)d_in[5];
    const float* bk  = (const float*)d_in[6];
    const float* Wv  = (const float*)d_in[7];
    const float* bv  = (const float*)d_in[8];
    const float* Wo  = (const float*)d_in[9];
    const float* bo  = (const float*)d_in[10];
    const float* g1  = (const float*)d_in[11];
    const float* be1 = (const float*)d_in[12];
    const float* Wf1 = (const float*)d_in[13];
    const float* bf1 = (const float*)d_in[14];
    const float* Wf2 = (const float*)d_in[15];
    const float* bf2 = (const float*)d_in[16];
    const float* g2  = (const float*)d_in[17];
    const float* be2 = (const float*)d_in[18];
    const float* mW0 = (const float*)d_in[19];
    const float* mb0 = (const float*)d_in[20];
    const float* mW1 = (const float*)d_in[21];
    const float* mb1 = (const float*)d_in[22];
    const float* mW2 = (const float*)d_in[23];
    const float* mb2 = (const float*)d_in[24];
    float* out = (float*)d_out;

    const int N = in_sizes[0];       // 50000
    const int E = in_sizes[1] / 2;   // 800000

    float* base;
    cudaGetSymbolAddress((void**)&base, g_scratch);
    float* x    = base + OFF_X;
    float* part = base + OFF_PART;

    int* ibase;
    cudaGetSymbolAddress((void**)&ibase, g_iscratch);
    int* cnt     = ibase + IOFF_CNT;
    int* rowptr  = ibase + IOFF_ROW;
    int* csr_src = ibase + IOFF_SRC;

    unsigned *wp, *xp, *yp, *qp, *kp, *vp, *wvp, *midp;
    cudaGetSymbolAddress((void**)&wp, g_wpack);
    cudaGetSymbolAddress((void**)&xp, g_xp);
    cudaGetSymbolAddress((void**)&yp, g_yp);
    cudaGetSymbolAddress((void**)&qp, g_qp);
    cudaGetSymbolAddress((void**)&kp, g_kp);
    cudaGetSymbolAddress((void**)&vp, g_vp);
    cudaGetSymbolAddress((void**)&wvp, g_wvp);
    cudaGetSymbolAddress((void**)&midp, g_midp);

    cudaFuncSetAttribute(gemm_qkv, cudaFuncAttributeMaxDynamicSharedMemorySize, GEMM_DYN_SMEM);
    cudaFuncSetAttribute(gemm_ln, cudaFuncAttributeMaxDynamicSharedMemorySize, GEMM_DYN_SMEM);
    cudaFuncSetAttribute(gemm_f1, cudaFuncAttributeMaxDynamicSharedMemorySize, GEMM_DYN_SMEM);

    const int nb128 = (N + 127) / 128;

    // --- Ordered so gemm_qkv is the 6th launch (ncu -s 5 -c 1 profiles it) ---
    conv_all<<<(WPACK_TOTAL + 255) / 256, 256>>>(Wq, Wk, Wv, Wo, Wf1, Wf2, wp); // 1
    emb_gather<<<(N * 64 + 255) / 256, 256>>>(x_idx, emb, x, xp, N);            // 2
    zero_int<<<(N + 255) / 256, 256>>>(cnt, N);                                 // 3
    hist_dst<<<(E + 255) / 256, 256>>>(ei, E, cnt);                             // 4
    scan_rowptr<<<1, 1024>>>(cnt, rowptr, N);                                   // 5

    // Layer 0 QKV (6th launch -> profiled)
    gemm_qkv<<<dim3(nb128, 1, 3), 256, GEMM_DYN_SMEM>>>(
        xp, wp + WQ_OFF, wp + WK_OFF, wp + WV_OFF, bq, bk, bv, qp, kp, vp, N);

    // Finish CSR build
    zero_int<<<(N + 255) / 256, 256>>>(cnt, N);
    csr_scatter<<<(E + 255) / 256, 256>>>(ei, E, rowptr, cnt, csr_src);

    for (int l = 0; l < LAYERS; l++) {
        const unsigned* wq_p = wp + WQ_OFF + (size_t)l * PQ;
        const unsigned* wk_p = wp + WK_OFF + (size_t)l * PQ;
        const unsigned* wv_p = wp + WV_OFF + (size_t)l * PQ;
        const unsigned* wo_p = wp + WO_OFF + (size_t)l * PQ;
        const unsigned* wf1_p = wp + WF1_OFF + (size_t)l * PF;
        const unsigned* wf2_p = wp + WF2_OFF + (size_t)l * PF;

        if (l > 0) {
            gemm_qkv<<<dim3(nb128, 1, 3), 256, GEMM_DYN_SMEM>>>(
                xp, wq_p, wk_p, wv_p, bq + l * D, bk + l * D, bv + l * D,
                qp, kp, vp, N);
        }

        attn_csr<<<(N + 7) / 8, 256>>>(rowptr, csr_src, qp, kp, vp, wvp, N);

        // y(packed) = wV@Wo + bo ; x = LN(x + y)
        gemm_ln<<<nb128, 256, GEMM_DYN_SMEM>>>(
            wvp, 64, wo_p, 64, bo + l * D, yp, x, nullptr,
            g1 + l * D, be1 + l * D, N, 128);

        // mid(packed) = relu(y@Wf1 + bf1)
        gemm_f1<<<dim3(nb128, 2), 256, GEMM_DYN_SMEM>>>(yp, wf1_p, bf1 + l * 2 * D, midp, N);

        // x = LN(x + mid@Wf2 + bf2), also packed to xp
        gemm_ln<<<nb128, 256, GEMM_DYN_SMEM>>>(
            midp, 128, wf2_p, 128, bf2 + l * D, nullptr, x, xp,
            g2 + l * D, be2 + l * D, N, 256);
    }

    colsum<<<NPARTBLK, 128>>>(x, part, N);
    readout<<<1, 128>>>(part, mW0, mb0, mW1, mb1, mW2, mb2, out, N);
}

// round 13
// speedup vs baseline: 4.6975x; 1.0299x over previous
#include <cuda_runtime.h>
#include <cuda_fp16.h>
#include <cstddef>

#define D       128
#define H       8
#define HD      16
#define NMAX    50000
#define NPAD    50176          // 392 * 128
#define EMAX    800000
#define LAYERS  3

// ---------------------------------------------------------------------------
// Float scratch: x (residual/pool), colsum partials
// ---------------------------------------------------------------------------
#define OFF_X    ((size_t)0)
#define OFF_PART (OFF_X + (size_t)NMAX * D)
#define NPARTBLK 256
#define SCRATCH_FLOATS (OFF_PART + (size_t)NPARTBLK * D)
__device__ float g_scratch[SCRATCH_FLOATS];

// Packed fp16 activations (single plane, half2 per uint, pairs along K)
#define XPL   ((size_t)NPAD * 64)
#define MIDPL ((size_t)NPAD * 128)
__device__ unsigned g_xp[XPL];
__device__ unsigned g_yp[XPL];
__device__ unsigned g_qp[XPL];
__device__ unsigned g_kp[XPL];
__device__ unsigned g_vp[XPL];
__device__ unsigned g_wvp[XPL];
__device__ unsigned g_midp[MIDPL];

// Int scratch: cnt[N], rowptr[N+1], csr_src[E]
#define IOFF_CNT   0
#define IOFF_ROW   (IOFF_CNT + NMAX)
#define IOFF_SRC   (IOFF_ROW + NMAX + 1)
__device__ int g_iscratch[IOFF_SRC + EMAX];

// Packed fp16 weights, N-MAJOR rows of K-pairs: w[n][kp] (half2 per uint).
#define PQ      (64 * 128)     // DxD matrix (uints)
#define PF      (64 * 256)     // 128x256 / 256x128 (uints)
#define SQ      (LAYERS * PQ)
#define SF      (LAYERS * PF)
#define WQ_OFF  0
#define WK_OFF  (WQ_OFF + SQ)
#define WV_OFF  (WK_OFF + SQ)
#define WO_OFF  (WV_OFF + SQ)
#define WF1_OFF (WO_OFF + SQ)
#define WF2_OFF (WF1_OFF + SF)
#define WPACK_TOTAL (WF2_OFF + SF)
__device__ unsigned g_wpack[WPACK_TOTAL];

// ---------------------------------------------------------------------------
__device__ __forceinline__ unsigned pack2_f16(float a, float b) {
    __half2 h2 = __floats2half2_rn(a, b);
    return *(unsigned*)&h2;
}
__device__ __forceinline__ float2 unpack2_f16(unsigned u) {
    return __half22float2(*(__half2*)&u);
}
__device__ __forceinline__ void cp16(unsigned* smem, const unsigned* gmem) {
    unsigned sa = (unsigned)__cvta_generic_to_shared(smem);
    asm volatile("cp.async.cg.shared.global [%0], [%1], 16;" :: "r"(sa), "l"(gmem));
}
#define LDSM_X4(r0, r1, r2, r3, addr) \
    asm volatile("ldmatrix.sync.aligned.m8n8.x4.shared.b16 {%0,%1,%2,%3}, [%4];" \
                 : "=r"(r0), "=r"(r1), "=r"(r2), "=r"(r3) : "r"(addr))

// ---------------------------------------------------------------------------
__global__ void zero_int(int* __restrict__ p, int n) {
    int i = blockIdx.x * blockDim.x + threadIdx.x;
    int stride = gridDim.x * blockDim.x;
    for (; i < n; i += stride) p[i] = 0;
}

// Embedding gather: float x + packed xp
__global__ void emb_gather(const int* __restrict__ idx, const float* __restrict__ emb,
                           float* __restrict__ x, unsigned* __restrict__ xp, int N) {
    int i = blockIdx.x * blockDim.x + threadIdx.x;
    if (i >= N * 64) return;
    int n = i >> 6;
    int kp = i & 63;
    float2 e = *(const float2*)(emb + (size_t)idx[n] * D + 2 * kp);
    *(float2*)(x + (size_t)n * D + 2 * kp) = e;
    xp[(size_t)n * 64 + kp] = pack2_f16(e.x, e.y);
}

// Combined weight conversion: all 6 weight stacks in ONE launch.
// float [L, K, Nout] -> n-major packed: dst[l*P + n*(K/2) + kp]
__global__ void conv_all(const float* __restrict__ Wq, const float* __restrict__ Wk,
                         const float* __restrict__ Wv, const float* __restrict__ Wo,
                         const float* __restrict__ Wf1, const float* __restrict__ Wf2,
                         unsigned* __restrict__ wp) {
    int idx = blockIdx.x * blockDim.x + threadIdx.x;
    if (idx >= (int)WPACK_TOTAL) return;

    const float* src;
    int K, Nout, rem, dstoff;
    if (idx < 4 * SQ) {
        int which = idx / SQ;
        rem = idx - which * SQ;
        src = (which == 0) ? Wq : (which == 1) ? Wk : (which == 2) ? Wv : Wo;
        K = 128; Nout = 128;
        dstoff = which * SQ;
    } else if (idx < 4 * SQ + SF) {
        rem = idx - 4 * SQ;
        src = Wf1; K = 128; Nout = 256; dstoff = WF1_OFF;
    } else {
        rem = idx - 4 * SQ - SF;
        src = Wf2; K = 256; Nout = 128; dstoff = WF2_OFF;
    }
    int KH = K >> 1;
    int P = KH * Nout;
    int l = rem / P;
    int p = rem - l * P;
    int n = p / KH;
    int kp = p - n * KH;
    float a = src[(size_t)l * K * Nout + (size_t)(2 * kp) * Nout + n];
    float b = src[(size_t)l * K * Nout + (size_t)(2 * kp + 1) * Nout + n];
    wp[dstoff + (size_t)l * P + p] = pack2_f16(a, b);
}

// ---------------------------------------------------------------------------
// CSR build
// ---------------------------------------------------------------------------
__global__ void hist_dst(const int* __restrict__ ei, int E, int* __restrict__ cnt) {
    int j = blockIdx.x * blockDim.x + threadIdx.x;
    if (j < E) atomicAdd(&cnt[ei[E + j]], 1);
}
__global__ void scan_rowptr(const int* __restrict__ cnt, int* __restrict__ rowptr, int N) {
    __shared__ int ssum[1024];
    int tid = threadIdx.x;
    int chunk = (N + 1023) / 1024;
    int start = tid * chunk;
    int end = min(start + chunk, N);
    int s = 0;
    for (int i = start; i < end; i++) s += cnt[i];
    ssum[tid] = s;
    __syncthreads();
    int mysum = s;
    for (int o = 1; o < 1024; o <<= 1) {
        int t = (tid >= o) ? ssum[tid - o] : 0;
        __syncthreads();
        ssum[tid] += t;
        __syncthreads();
    }
    int off = ssum[tid] - mysum;
    for (int i = start; i < end; i++) { rowptr[i] = off; off += cnt[i]; }
    if (end == N) rowptr[N] = off;
}
__global__ void csr_scatter(const int* __restrict__ ei, int E,
                            const int* __restrict__ rowptr, int* __restrict__ cur,
                            int* __restrict__ csr_src) {
    int j = blockIdx.x * blockDim.x + threadIdx.x;
    if (j >= E) return;
    int d = ei[E + j];
    int pos = atomicAdd(&cur[d], 1);
    csr_src[rowptr[d] + pos] = ei[j];
}

// ---------------------------------------------------------------------------
// fp16 tensor-core GEMM core with ldmatrix fragment loads.
// Block tile 128x128, chunk K=32, 256 threads (8 warps: 4 M x 2 N, 32x64/warp).
// ---------------------------------------------------------------------------
#define ASTR 20
#define SM_A 0
#define SM_B 2560
#define STG_UINTS 5120
#define GEMM_DYN_SMEM (2 * STG_UINTS * 4)

__device__ __forceinline__ void mma_f16(float c[4], const unsigned a[4],
                                        unsigned b0, unsigned b1) {
    asm volatile(
        "mma.sync.aligned.m16n8k16.row.col.f32.f16.f16.f32 "
        "{%0,%1,%2,%3}, {%4,%5,%6,%7}, {%8,%9}, {%0,%1,%2,%3};"
        : "+f"(c[0]), "+f"(c[1]), "+f"(c[2]), "+f"(c[3])
        : "r"(a[0]), "r"(a[1]), "r"(a[2]), "r"(a[3]), "r"(b0), "r"(b1));
}

__device__ __forceinline__ void load_stage(
    const unsigned* __restrict__ Ap, int ldA,
    const unsigned* __restrict__ Wp, int ldW,
    int bm, int bn, int chunk, unsigned* s, int tid)
{
    int kp0 = chunk * 16;
#pragma unroll
    for (int it = 0; it < 2; it++) {
        int idx = tid + it * 256;
        int r = idx >> 2;
        int c4 = idx & 3;
        cp16(s + SM_A + r * ASTR + c4 * 4,
             Ap + (size_t)(bm + r) * ldA + kp0 + c4 * 4);
    }
#pragma unroll
    for (int it = 0; it < 2; it++) {
        int idx = tid + it * 256;
        int r = idx >> 2;
        int c4 = idx & 3;
        cp16(s + SM_B + r * ASTR + c4 * 4,
             Wp + (size_t)(bn + r) * ldW + kp0 + c4 * 4);
    }
    asm volatile("cp.async.commit_group;");
}

__device__ __forceinline__ void gemm_core_p(
    const unsigned* __restrict__ Ap, int ldA,
    const unsigned* __restrict__ Wp, int ldW,
    int K, int bm, int bn,
    unsigned* sm, float acc[2][8][4])
{
    const int tid = threadIdx.x;
    const int lane = tid & 31;
    const int wid = tid >> 5;
    const int warp_m = wid & 3;
    const int warp_n = wid >> 2;
    const int sub = lane >> 3;
    const int rin = lane & 7;

    const unsigned sbase = (unsigned)__cvta_generic_to_shared(sm);
    const int a_row = warp_m * 32 + (sub & 1) * 8 + rin;
    const int a_col = (sub >> 1) * 4;
    const int b_row0 = warp_n * 64 + (sub >> 1) * 8 + rin;
    const int b_col = (sub & 1) * 4;

#pragma unroll
    for (int mi = 0; mi < 2; mi++)
#pragma unroll
        for (int ni = 0; ni < 8; ni++)
#pragma unroll
            for (int t = 0; t < 4; t++) acc[mi][ni][t] = 0.0f;

    const int C = K >> 5;
    load_stage(Ap, ldA, Wp, ldW, bm, bn, 0, sm, tid);

    for (int c = 0; c < C; c++) {
        if (c + 1 < C) {
            load_stage(Ap, ldA, Wp, ldW, bm, bn, c + 1,
                       sm + ((c + 1) & 1) * STG_UINTS, tid);
            asm volatile("cp.async.wait_group 1;");
        } else {
            asm volatile("cp.async.wait_group 0;");
        }
        __syncthreads();

        const unsigned stg = sbase + (unsigned)((c & 1) * STG_UINTS) * 4u;

#pragma unroll
        for (int st = 0; st < 2; st++) {
            unsigned ah[2][4];
#pragma unroll
            for (int mi = 0; mi < 2; mi++) {
                unsigned aaddr = stg + ((unsigned)(SM_A + (a_row + mi * 16) * ASTR
                                                   + 8 * st + a_col) << 2);
                LDSM_X4(ah[mi][0], ah[mi][1], ah[mi][2], ah[mi][3], aaddr);
            }
#pragma unroll
            for (int t = 0; t < 4; t++) {
                unsigned b0, b1, b2, b3;
                unsigned baddr = stg + ((unsigned)(SM_B + (b_row0 + t * 16) * ASTR
                                                   + 8 * st + b_col) << 2);
                LDSM_X4(b0, b1, b2, b3, baddr);
#pragma unroll
                for (int mi = 0; mi < 2; mi++) {
                    mma_f16(acc[mi][2 * t + 0], ah[mi], b0, b1);
                    mma_f16(acc[mi][2 * t + 1], ah[mi], b2, b3);
                }
            }
        }
        __syncthreads();
    }
}

// QKV fused: grid.z selects weight/bias/output; packed half2 q/k/v outputs.
__global__ __launch_bounds__(256, 2)
void gemm_qkv(const unsigned* __restrict__ Ap,
              const unsigned* __restrict__ Wpq, const unsigned* __restrict__ Wpk,
              const unsigned* __restrict__ Wpv,
              const float* __restrict__ bq, const float* __restrict__ bk,
              const float* __restrict__ bv,
              unsigned* __restrict__ Cq, unsigned* __restrict__ Ck,
              unsigned* __restrict__ Cv,
              int rows) {
    extern __shared__ unsigned sm[];
    const int z = blockIdx.z;
    const unsigned* Wp = (z == 0) ? Wpq : (z == 1) ? Wpk : Wpv;
    const float* bias  = (z == 0) ? bq  : (z == 1) ? bk  : bv;
    unsigned* C        = (z == 0) ? Cq  : (z == 1) ? Ck  : Cv;
    const int bm = blockIdx.x * 128;
    float acc[2][8][4];
    gemm_core_p(Ap, 64, Wp, 64, 128, bm, 0, sm, acc);

    const int lane = threadIdx.x & 31;
    const int wid = threadIdx.x >> 5;
    const int warp_m = wid & 3, warp_n = wid >> 2;
    const int lr = lane >> 2, lc = lane & 3;
#pragma unroll
    for (int mi = 0; mi < 2; mi++) {
        int row0 = bm + warp_m * 32 + mi * 16 + lr;
        int row1 = row0 + 8;
#pragma unroll
        for (int ni = 0; ni < 8; ni++) {
            int col = warp_n * 64 + ni * 8 + 2 * lc;
            int colp = col >> 1;
            float bs0 = bias[col], bs1 = bias[col + 1];
            if (row0 < rows)
                C[(size_t)row0 * 64 + colp] =
                    pack2_f16(acc[mi][ni][0] + bs0, acc[mi][ni][1] + bs1);
            if (row1 < rows)
                C[(size_t)row1 * 64 + colp] =
                    pack2_f16(acc[mi][ni][2] + bs0, acc[mi][ni][3] + bs1);
        }
    }
}

// GEMM + fused residual/LayerNorm (Nout = 128 = full row per block).
// fp32 residual xio (load-bearing for accuracy), optional packed outputs.
__global__ __launch_bounds__(256, 2)
void gemm_ln(const unsigned* __restrict__ Ap, int ldA,
             const unsigned* __restrict__ Wp, int ldW,
             const float* __restrict__ bias,
             unsigned* __restrict__ yp,
             float* __restrict__ xio,
             unsigned* __restrict__ xpo,
             const float* __restrict__ g, const float* __restrict__ b,
             int rows, int K) {
    extern __shared__ unsigned sm[];
    const int bm = blockIdx.x * 128;
    float acc[2][8][4];
    gemm_core_p(Ap, ldA, Wp, ldW, K, bm, 0, sm, acc);

    const int lane = threadIdx.x & 31;
    const int wid = threadIdx.x >> 5;
    const int warp_m = wid & 3, warp_n = wid >> 2;
    const int lr = lane >> 2, lc = lane & 3;

    float* sred = (float*)sm;

#pragma unroll
    for (int mi = 0; mi < 2; mi++) {
#pragma unroll
        for (int rp = 0; rp < 2; rp++) {
            int r_loc = warp_m * 32 + mi * 16 + lr + 8 * rp;
            int row = bm + r_loc;
            float sum = 0.f, sq = 0.f;
#pragma unroll
            for (int ni = 0; ni < 8; ni++) {
                int col = warp_n * 64 + ni * 8 + 2 * lc;
                float o0 = acc[mi][ni][2 * rp + 0] + bias[col];
                float o1 = acc[mi][ni][2 * rp + 1] + bias[col + 1];
                float x0 = 0.f, x1 = 0.f;
                if (row < rows) {
                    float2 xr = *(const float2*)(xio + (size_t)row * D + col);
                    x0 = xr.x; x1 = xr.y;
                    if (yp)
                        yp[(size_t)row * 64 + (col >> 1)] = pack2_f16(o0, o1);
                }
                float v0 = o0 + x0, v1 = o1 + x1;
                acc[mi][ni][2 * rp + 0] = v0;
                acc[mi][ni][2 * rp + 1] = v1;
                sum += v0 + v1;
                sq += v0 * v0 + v1 * v1;
            }
            sum += __shfl_xor_sync(0xffffffffu, sum, 1);
            sq  += __shfl_xor_sync(0xffffffffu, sq, 1);
            sum += __shfl_xor_sync(0xffffffffu, sum, 2);
            sq  += __shfl_xor_sync(0xffffffffu, sq, 2);
            if (lc == 0) {
                sred[r_loc * 4 + warp_n * 2 + 0] = sum;
                sred[r_loc * 4 + warp_n * 2 + 1] = sq;
            }
        }
    }
    __syncthreads();

#pragma unroll
    for (int mi = 0; mi < 2; mi++) {
#pragma unroll
        for (int rp = 0; rp < 2; rp++) {
            int r_loc = warp_m * 32 + mi * 16 + lr + 8 * rp;
            int row = bm + r_loc;
            if (row >= rows) continue;
            float sum = sred[r_loc * 4 + 0] + sred[r_loc * 4 + 2];
            float sq  = sred[r_loc * 4 + 1] + sred[r_loc * 4 + 3];
            float mean = sum * (1.0f / 128.0f);
            float var = sq * (1.0f / 128.0f) - mean * mean;
            float rstd = rsqrtf(var + 1e-5f);
#pragma unroll
            for (int ni = 0; ni < 8; ni++) {
                int col = warp_n * 64 + ni * 8 + 2 * lc;
                float v0 = acc[mi][ni][2 * rp + 0];
                float v1 = acc[mi][ni][2 * rp + 1];
                float out0 = (v0 - mean) * rstd * g[col] + b[col];
                float out1 = (v1 - mean) * rstd * g[col + 1] + b[col + 1];
                *(float2*)(xio + (size_t)row * D + col) = make_float2(out0, out1);
                if (xpo)
                    xpo[(size_t)row * 64 + (col >> 1)] = pack2_f16(out0, out1);
            }
        }
    }
}

// FFN first GEMM: relu, packed output (Nout = 256 via grid.y)
__global__ __launch_bounds__(256, 2)
void gemm_f1(const unsigned* __restrict__ Ap,
             const unsigned* __restrict__ Wp,
             const float* __restrict__ bias,
             unsigned* __restrict__ outp,
             int rows) {
    extern __shared__ unsigned sm[];
    const int bm = blockIdx.x * 128;
    const int bn = blockIdx.y * 128;
    float acc[2][8][4];
    gemm_core_p(Ap, 64, Wp, 64, 128, bm, bn, sm, acc);

    const int lane = threadIdx.x & 31;
    const int wid = threadIdx.x >> 5;
    const int warp_m = wid & 3, warp_n = wid >> 2;
    const int lr = lane >> 2, lc = lane & 3;
#pragma unroll
    for (int mi = 0; mi < 2; mi++) {
        int row0 = bm + warp_m * 32 + mi * 16 + lr;
        int row1 = row0 + 8;
#pragma unroll
        for (int ni = 0; ni < 8; ni++) {
            int col = bn + warp_n * 64 + ni * 8 + 2 * lc;
            int colp = col >> 1;
            float bs0 = bias[col], bs1 = bias[col + 1];
            float o0 = fmaxf(acc[mi][ni][0] + bs0, 0.f);
            float o1 = fmaxf(acc[mi][ni][1] + bs1, 0.f);
            float o2 = fmaxf(acc[mi][ni][2] + bs0, 0.f);
            float o3 = fmaxf(acc[mi][ni][3] + bs1, 0.f);
            if (row0 < rows)
                outp[(size_t)row0 * 128 + colp] = pack2_f16(o0, o1);
            if (row1 < rows)
                outp[(size_t)row1 * 128 + colp] = pack2_f16(o2, o3);
        }
    }
}

// ---------------------------------------------------------------------------
// CSR attention: warp per destination node, fp16 q/k/v, 2-edge unrolled.
// ---------------------------------------------------------------------------
__global__ void attn_csr(const int* __restrict__ rowptr, const int* __restrict__ csr_src,
                         const unsigned* __restrict__ qh, const unsigned* __restrict__ kh,
                         const unsigned* __restrict__ vh, unsigned* __restrict__ wvp, int N) {
    int warp = blockIdx.x * (blockDim.x >> 5) + (threadIdx.x >> 5);
    if (warp >= N) return;
    int lane = threadIdx.x & 31;
    int colp = lane * 2;

    uint2 qp = *(const uint2*)(qh + (size_t)warp * 64 + colp);
    float2 q01 = unpack2_f16(qp.x);
    float2 q23 = unpack2_f16(qp.y);

    float4 acc = make_float4(0.f, 0.f, 0.f, 0.f);
    float Zh = 0.0f;

    int jb = rowptr[warp];
    int je = rowptr[warp + 1];
    int j = jb;

    for (; j + 1 < je; j += 2) {
        int s0 = csr_src[j];
        int s1 = csr_src[j + 1];
        uint2 ka = *(const uint2*)(kh + (size_t)s0 * 64 + colp);
        uint2 kb = *(const uint2*)(kh + (size_t)s1 * 64 + colp);
        uint2 va = *(const uint2*)(vh + (size_t)s0 * 64 + colp);
        uint2 vb = *(const uint2*)(vh + (size_t)s1 * 64 + colp);

        float2 ka01 = unpack2_f16(ka.x), ka23 = unpack2_f16(ka.y);
        float2 kb01 = unpack2_f16(kb.x), kb23 = unpack2_f16(kb.y);
        float sa = ka01.x * q01.x + ka01.y * q01.y + ka23.x * q23.x + ka23.y * q23.y;
        float sb = kb01.x * q01.x + kb01.y * q01.y + kb23.x * q23.x + kb23.y * q23.y;
        sa += __shfl_xor_sync(0xffffffffu, sa, 1);
        sb += __shfl_xor_sync(0xffffffffu, sb, 1);
        sa += __shfl_xor_sync(0xffffffffu, sa, 2);
        sb += __shfl_xor_sync(0xffffffffu, sb, 2);
        sa = expf(fminf(fmaxf(sa * 0.25f, -5.0f), 5.0f));
        sb = expf(fminf(fmaxf(sb * 0.25f, -5.0f), 5.0f));

        float2 va01 = unpack2_f16(va.x), va23 = unpack2_f16(va.y);
        float2 vb01 = unpack2_f16(vb.x), vb23 = unpack2_f16(vb.y);
        acc.x = fmaf(va01.x, sa, fmaf(vb01.x, sb, acc.x));
        acc.y = fmaf(va01.y, sa, fmaf(vb01.y, sb, acc.y));
        acc.z = fmaf(va23.x, sa, fmaf(vb23.x, sb, acc.z));
        acc.w = fmaf(va23.y, sa, fmaf(vb23.y, sb, acc.w));
        Zh += sa + sb;
    }
    if (j < je) {
        int s0 = csr_src[j];
        uint2 ka = *(const uint2*)(kh + (size_t)s0 * 64 + colp);
        uint2 va = *(const uint2*)(vh + (size_t)s0 * 64 + colp);
        float2 k01 = unpack2_f16(ka.x), k23 = unpack2_f16(ka.y);
        float s = k01.x * q01.x + k01.y * q01.y + k23.x * q23.x + k23.y * q23.y;
        s += __shfl_xor_sync(0xffffffffu, s, 1);
        s += __shfl_xor_sync(0xffffffffu, s, 2);
        s = expf(fminf(fmaxf(s * 0.25f, -5.0f), 5.0f));
        float2 v01 = unpack2_f16(va.x), v23 = unpack2_f16(va.y);
        acc.x = fmaf(v01.x, s, acc.x);
        acc.y = fmaf(v01.y, s, acc.y);
        acc.z = fmaf(v23.x, s, acc.z);
        acc.w = fmaf(v23.y, s, acc.w);
        Zh += s;
    }
    float inv = 1.0f / (Zh + 1e-6f);
    acc.x *= inv; acc.y *= inv; acc.z *= inv; acc.w *= inv;

    *(uint2*)(wvp + (size_t)warp * 64 + colp) =
        make_uint2(pack2_f16(acc.x, acc.y), pack2_f16(acc.z, acc.w));
}

// ---------------------------------------------------------------------------
// Mean pool: per-block partial colsum from fp32 x (no atomics).
// ---------------------------------------------------------------------------
__global__ void colsum(const float* __restrict__ x, float* __restrict__ part, int N) {
    int d = threadIdx.x;
    float s = 0.0f;
    for (int r = blockIdx.x; r < N; r += gridDim.x)
        s += x[(size_t)r * D + d];
    part[(size_t)blockIdx.x * D + d] = s;
}

__global__ void readout(const float* __restrict__ part,
                        const float* __restrict__ mW0, const float* __restrict__ mb0,
                        const float* __restrict__ mW1, const float* __restrict__ mb1,
                        const float* __restrict__ mW2, const float* __restrict__ mb2,
                        float* __restrict__ out, int N) {
    __shared__ float m[D];
    __shared__ float h0[64];
    __shared__ float h1[32];
    int tid = threadIdx.x;
    float s0 = 0.f;
    for (int bqi = 0; bqi < NPARTBLK; bqi++) s0 += part[(size_t)bqi * D + tid];
    m[tid] = s0 * (1.0f / (float)N);
    __syncthreads();
    if (tid < 64) {
        float s = mb0[tid];
        for (int kk = 0; kk < D; kk++) s = fmaf(m[kk], mW0[kk * 64 + tid], s);
        h0[tid] = fmaxf(s, 0.0f);
    }
    __syncthreads();
    if (tid < 32) {
        float s = mb1[tid];
        for (int kk = 0; kk < 64; kk++) s = fmaf(h0[kk], mW1[kk * 32 + tid], s);
        h1[tid] = fmaxf(s, 0.0f);
    }
    __syncthreads();
    if (tid < 10) {
        float s = mb2[tid];
        for (int kk = 0; kk < 32; kk++) s = fmaf(h1[kk], mW2[kk * 10 + tid], s);
        out[tid] = s;
    }
}

// ---------------------------------------------------------------------------
extern "C" void kernel_launch(void* const* d_in, const int* in_sizes, int n_in,
                              void* d_out, int out_size) {
    const int*   x_idx = (const int*)d_in[0];
    const int*   ei    = (const int*)d_in[1];
    const float* emb   = (const float*)d_in[2];
    const float* Wq  = (const float*)d_in[3];
    const float* bq  = (const float*)d_in[4];
    const float* Wk  = (const float*)d_in[5];
    const float* bk  = (const float*)d_in[6];
    const float* Wv  = (const float*)d_in[7];
    const float* bv  = (const float*)d_in[8];
    const float* Wo  = (const float*)d_in[9];
    const float* bo  = (const float*)d_in[10];
    const float* g1  = (const float*)d_in[11];
    const float* be1 = (const float*)d_in[12];
    const float* Wf1 = (const float*)d_in[13];
    const float* bf1 = (const float*)d_in[14];
    const float* Wf2 = (const float*)d_in[15];
    const float* bf2 = (const float*)d_in[16];
    const float* g2  = (const float*)d_in[17];
    const float* be2 = (const float*)d_in[18];
    const float* mW0 = (const float*)d_in[19];
    const float* mb0 = (const float*)d_in[20];
    const float* mW1 = (const float*)d_in[21];
    const float* mb1 = (const float*)d_in[22];
    const float* mW2 = (const float*)d_in[23];
    const float* mb2 = (const float*)d_in[24];
    float* out = (float*)d_out;

    const int N = in_sizes[0];       // 50000
    const int E = in_sizes[1] / 2;   // 800000

    float* base;
    cudaGetSymbolAddress((void**)&base, g_scratch);
    float* x    = base + OFF_X;
    float* part = base + OFF_PART;

    int* ibase;
    cudaGetSymbolAddress((void**)&ibase, g_iscratch);
    int* cnt     = ibase + IOFF_CNT;
    int* rowptr  = ibase + IOFF_ROW;
    int* csr_src = ibase + IOFF_SRC;

    unsigned *wp, *xp, *yp, *qp, *kp, *vp, *wvp, *midp;
    cudaGetSymbolAddress((void**)&wp, g_wpack);
    cudaGetSymbolAddress((void**)&xp, g_xp);
    cudaGetSymbolAddress((void**)&yp, g_yp);
    cudaGetSymbolAddress((void**)&qp, g_qp);
    cudaGetSymbolAddress((void**)&kp, g_kp);
    cudaGetSymbolAddress((void**)&vp, g_vp);
    cudaGetSymbolAddress((void**)&wvp, g_wvp);
    cudaGetSymbolAddress((void**)&midp, g_midp);

    cudaFuncSetAttribute(gemm_qkv, cudaFuncAttributeMaxDynamicSharedMemorySize, GEMM_DYN_SMEM);
    cudaFuncSetAttribute(gemm_ln, cudaFuncAttributeMaxDynamicSharedMemorySize, GEMM_DYN_SMEM);
    cudaFuncSetAttribute(gemm_f1, cudaFuncAttributeMaxDynamicSharedMemorySize, GEMM_DYN_SMEM);

    const int nb128 = (N + 127) / 128;

    // --- Ordered so gemm_qkv is the 6th launch (ncu -s 5 -c 1 profiles it) ---
    conv_all<<<(WPACK_TOTAL + 255) / 256, 256>>>(Wq, Wk, Wv, Wo, Wf1, Wf2, wp); // 1
    emb_gather<<<(N * 64 + 255) / 256, 256>>>(x_idx, emb, x, xp, N);            // 2
    zero_int<<<(N + 255) / 256, 256>>>(cnt, N);                                 // 3
    hist_dst<<<(E + 255) / 256, 256>>>(ei, E, cnt);                             // 4
    scan_rowptr<<<1, 1024>>>(cnt, rowptr, N);                                   // 5

    // Layer 0 QKV (6th launch -> profiled)
    gemm_qkv<<<dim3(nb128, 1, 3), 256, GEMM_DYN_SMEM>>>(
        xp, wp + WQ_OFF, wp + WK_OFF, wp + WV_OFF, bq, bk, bv, qp, kp, vp, N);

    // Finish CSR build
    zero_int<<<(N + 255) / 256, 256>>>(cnt, N);
    csr_scatter<<<(E + 255) / 256, 256>>>(ei, E, rowptr, cnt, csr_src);

    for (int l = 0; l < LAYERS; l++) {
        const unsigned* wq_p = wp + WQ_OFF + (size_t)l * PQ;
        const unsigned* wk_p = wp + WK_OFF + (size_t)l * PQ;
        const unsigned* wv_p = wp + WV_OFF + (size_t)l * PQ;
        const unsigned* wo_p = wp + WO_OFF + (size_t)l * PQ;
        const unsigned* wf1_p = wp + WF1_OFF + (size_t)l * PF;
        const unsigned* wf2_p = wp + WF2_OFF + (size_t)l * PF;

        if (l > 0) {
            gemm_qkv<<<dim3(nb128, 1, 3), 256, GEMM_DYN_SMEM>>>(
                xp, wq_p, wk_p, wv_p, bq + l * D, bk + l * D, bv + l * D,
                qp, kp, vp, N);
        }

        attn_csr<<<(N + 7) / 8, 256>>>(rowptr, csr_src, qp, kp, vp, wvp, N);

        // y(packed) = wV@Wo + bo ; x = LN(x + y)   (fp32 residual)
        gemm_ln<<<nb128, 256, GEMM_DYN_SMEM>>>(
            wvp, 64, wo_p, 64, bo + l * D, yp, x, nullptr,
            g1 + l * D, be1 + l * D, N, 128);

        // mid(packed) = relu(y@Wf1 + bf1)
        gemm_f1<<<dim3(nb128, 2), 256, GEMM_DYN_SMEM>>>(yp, wf1_p, bf1 + l * 2 * D, midp, N);

        // x = LN(x + mid@Wf2 + bf2), also packed to xp
        gemm_ln<<<nb128, 256, GEMM_DYN_SMEM>>>(
            midp, 128, wf2_p, 128, bf2 + l * D, nullptr, x, xp,
            g2 + l * D, be2 + l * D, N, 256);
    }

    colsum<<<NPARTBLK, 128>>>(x, part, N);
    readout<<<1, 128>>>(part, mW0, mb0, mW1, mb1, mW2, mb2, out, N);
}